// round 3
// baseline (speedup 1.0000x reference)
#include <cuda_runtime.h>
#include <cuda_bf16.h>
#include <math.h>

// ---------------------------------------------------------------------------
// Problem constants
// ---------------------------------------------------------------------------
#define BB 32      // batch
#define SS 128     // seq len
#define DD 300     // emb dim
#define DPAD 304   // padded emb dim (19*16)
#define HH 1024    // hidden
#define G4 4096    // 4*H
#define NT 9       // tags
#define NBLK 128   // persistent LSTM blocks (single wave, < 148 SMs)

// ---------------------------------------------------------------------------
// Scratch (static device allocations - allowed)
// ---------------------------------------------------------------------------
__device__ float g_E[4096 * DPAD];          // gathered+padded embeddings (S*B, 304)
__device__ float g_W1p[512 * DPAD];         // padded lin1 weight
__device__ float g_X0[4096 * 2048];         // ping
__device__ float g_X1[4096 * 2048];         // pong
__device__ float g_pre[2ull * 4096 * 4096]; // input projections, both dirs
__device__ float g_h[2 * 2 * BB * HH];      // [buf][dir][b][j] double-buffered h
__device__ float g_emis[BB * SS * NT];

__device__ unsigned g_bar_cnt;
__device__ unsigned g_bar_gen;

// ---------------------------------------------------------------------------
// Gather embeddings into (s*B+b, 304) rows, zero-padded cols 300..303
// ---------------------------------------------------------------------------
__global__ void gather_kernel(float* __restrict__ E, const int* __restrict__ x,
                              const float* __restrict__ emb) {
    int i = blockIdx.x * blockDim.x + threadIdx.x;
    if (i >= 4096 * DPAD) return;
    int m = i / DPAD, col = i % DPAD;
    int s = m / BB, b = m % BB;
    int tok = x[b * SS + s];
    E[i] = (col < DD) ? emb[(size_t)tok * DD + col] : 0.f;
}

__global__ void padw_kernel(float* __restrict__ Wp, const float* __restrict__ W) {
    int i = blockIdx.x * blockDim.x + threadIdx.x;
    if (i >= 512 * DPAD) return;
    int r = i / DPAD, col = i % DPAD;
    Wp[i] = (col < DD) ? W[r * DD + col] : 0.f;
}

// ---------------------------------------------------------------------------
// Generic tiled GEMM:  C[M,N] = A[M,K] * B[N,K]^T + bias[N]
// BM=128, BN=64, BK=16, 256 threads, 8x4 per-thread tile.
// ---------------------------------------------------------------------------
__global__ void gemm_bias(const float* __restrict__ A, const float* __restrict__ Bm,
                          const float* __restrict__ bias, float* __restrict__ C,
                          int N, int K) {
    __shared__ float As[16][132];
    __shared__ float Bs[16][68];
    int tid = threadIdx.x;
    int m0 = blockIdx.y * 128;
    int n0 = blockIdx.x * 64;
    int tx = tid & 15;   // n-group
    int ty = tid >> 4;   // m-group
    int lr = tid >> 2;   // 0..63 loader row
    int lc = (tid & 3) * 4;

    const float* Ap  = A  + (size_t)(m0 + lr) * K + lc;
    const float* Ap2 = Ap + (size_t)64 * K;
    const float* Bp  = Bm + (size_t)(n0 + lr) * K + lc;

    float acc[8][4];
#pragma unroll
    for (int i = 0; i < 8; i++)
#pragma unroll
        for (int j = 0; j < 4; j++) acc[i][j] = 0.f;

    for (int k0 = 0; k0 < K; k0 += 16) {
        float4 a0 = *(const float4*)(Ap + k0);
        float4 a1 = *(const float4*)(Ap2 + k0);
        float4 b0 = *(const float4*)(Bp + k0);
        __syncthreads();
        As[lc + 0][lr] = a0.x; As[lc + 1][lr] = a0.y;
        As[lc + 2][lr] = a0.z; As[lc + 3][lr] = a0.w;
        As[lc + 0][lr + 64] = a1.x; As[lc + 1][lr + 64] = a1.y;
        As[lc + 2][lr + 64] = a1.z; As[lc + 3][lr + 64] = a1.w;
        Bs[lc + 0][lr] = b0.x; Bs[lc + 1][lr] = b0.y;
        Bs[lc + 2][lr] = b0.z; Bs[lc + 3][lr] = b0.w;
        __syncthreads();
#pragma unroll
        for (int k = 0; k < 16; k++) {
            float4 av0 = *(const float4*)&As[k][ty * 8];
            float4 av1 = *(const float4*)&As[k][ty * 8 + 4];
            float4 bv  = *(const float4*)&Bs[k][tx * 4];
            float am[8] = {av0.x, av0.y, av0.z, av0.w, av1.x, av1.y, av1.z, av1.w};
            float bb[4] = {bv.x, bv.y, bv.z, bv.w};
#pragma unroll
            for (int i = 0; i < 8; i++)
#pragma unroll
                for (int j = 0; j < 4; j++) acc[i][j] += am[i] * bb[j];
        }
    }
    float bs0 = bias[n0 + tx * 4 + 0];
    float bs1 = bias[n0 + tx * 4 + 1];
    float bs2 = bias[n0 + tx * 4 + 2];
    float bs3 = bias[n0 + tx * 4 + 3];
#pragma unroll
    for (int i = 0; i < 8; i++) {
        int m = m0 + ty * 8 + i;
        float4 ov;
        ov.x = acc[i][0] + bs0;
        ov.y = acc[i][1] + bs1;
        ov.z = acc[i][2] + bs2;
        ov.w = acc[i][3] + bs3;
        *(float4*)&C[(size_t)m * N + n0 + tx * 4] = ov;
    }
}

// ---------------------------------------------------------------------------
// Grid barrier (single-wave persistent kernel; 128 co-resident blocks)
// ---------------------------------------------------------------------------
__device__ __forceinline__ void grid_bar() {
    __threadfence();
    __syncthreads();
    if (threadIdx.x == 0) {
        volatile unsigned* vgen = &g_bar_gen;
        unsigned gen = *vgen;
        unsigned rank = atomicAdd(&g_bar_cnt, 1);
        if (rank == NBLK - 1) {
            atomicExch(&g_bar_cnt, 0);
            __threadfence();
            atomicExch(&g_bar_gen, gen + 1);
        } else {
            while (*vgen == gen) { __nanosleep(64); }
        }
        __threadfence();
    }
    __syncthreads();
}

// ---------------------------------------------------------------------------
// Persistent BiLSTM layer kernel. 128 blocks x 256 threads.
// Block bid: dir = bid>>6, j-slice = (bid&63)*16 (16 hidden units, 4 gates).
// Per step: stage h (32x1024) in smem, GEMM vs streamed Whh rows, cell update
// with c in registers, write h to double-buffered global + layer output.
// ---------------------------------------------------------------------------
__global__ void __launch_bounds__(256, 1)
lstm_layer(const float* __restrict__ whh, const float* __restrict__ pre,
           float* __restrict__ hbuf, float* __restrict__ Xout) {
    extern __shared__ float sm[];
    float* hs  = sm;                 // [32][1028]
    float* gsm = sm + 32 * 1028;     // [64][33]

    const int bid = blockIdx.x;
    const int dir = bid >> 6;
    const int js  = (bid & 63) * 16;
    const int tid = threadIdx.x;

    // GEMM thread tile: 2 gate-rows x 4 batches (stride 8)
    const int ng = tid >> 3;         // 0..31
    const int bg = tid & 7;
    const int r0 = 2 * ng, r1 = 2 * ng + 1;
    const int row0 = ((r0 >> 4) << 10) + js + (r0 & 15);
    const int row1 = ((r1 >> 4) << 10) + js + (r1 & 15);
    const float* W0 = whh + (size_t)dir * G4 * HH + (size_t)row0 * HH;
    const float* W1 = whh + (size_t)dir * G4 * HH + (size_t)row1 * HH;
    const float* preD = pre + (size_t)dir * 4096 * 4096;

    // cell ownership: (jj, cb) and (jj, cb+16)
    const int jj = tid >> 4;         // 0..15
    const int cb = tid & 15;
    float c0 = 0.f, c1 = 0.f;

    for (int t = 0; t < SS; t++) {
        const int sdir = dir ? (SS - 1 - t) : t;

        if (t > 0) {
            // stage h[prev] into smem (L2 path; L1 may be stale across barrier)
            const float* hsrc = hbuf + (size_t)((t & 1) * 2 + dir) * (BB * HH);
            for (int f = tid; f < 32 * 256; f += 256) {
                int b = f >> 8, j4 = (f & 255) << 2;
                float4 v;
                v.x = __ldcg(hsrc + b * 1024 + j4 + 0);
                v.y = __ldcg(hsrc + b * 1024 + j4 + 1);
                v.z = __ldcg(hsrc + b * 1024 + j4 + 2);
                v.w = __ldcg(hsrc + b * 1024 + j4 + 3);
                *(float4*)(hs + b * 1028 + j4) = v;
            }
        }
        __syncthreads();

        float acc[4][2] = {{0.f,0.f},{0.f,0.f},{0.f,0.f},{0.f,0.f}};
        if (t > 0) {
            for (int k = 0; k < HH; k += 4) {
                float4 w0 = *(const float4*)(W0 + k);
                float4 w1 = *(const float4*)(W1 + k);
#pragma unroll
                for (int kk = 0; kk < 4; kk++) {
                    float wa = (&w0.x)[kk], wb = (&w1.x)[kk];
#pragma unroll
                    for (int i = 0; i < 4; i++) {
                        float hv = hs[(bg + 8 * i) * 1028 + k + kk];
                        acc[i][0] += hv * wa;
                        acc[i][1] += hv * wb;
                    }
                }
            }
        }
        const float* prep = preD + (size_t)sdir * BB * G4;
#pragma unroll
        for (int i = 0; i < 4; i++) {
            int b = bg + 8 * i;
            gsm[r0 * 33 + b] = acc[i][0] + prep[(size_t)b * G4 + row0];
            gsm[r1 * 33 + b] = acc[i][1] + prep[(size_t)b * G4 + row1];
        }
        __syncthreads();

        // cell update for (jj, cb) and (jj, cb+16)
        float* hdst = hbuf + (size_t)(((t + 1) & 1) * 2 + dir) * (BB * HH);
        {
            float gi = gsm[(jj)      * 33 + cb];
            float gf = gsm[(16 + jj) * 33 + cb];
            float gg = gsm[(32 + jj) * 33 + cb];
            float go = gsm[(48 + jj) * 33 + cb];
            float i_ = 1.f / (1.f + expf(-gi));
            float f_ = 1.f / (1.f + expf(-gf));
            c0 = f_ * c0 + i_ * tanhf(gg);
            float hv = (1.f / (1.f + expf(-go))) * tanhf(c0);
            hdst[cb * HH + js + jj] = hv;
            Xout[(size_t)(sdir * BB + cb) * 2048 + dir * HH + js + jj] = hv;
        }
        {
            int b2 = cb + 16;
            float gi = gsm[(jj)      * 33 + b2];
            float gf = gsm[(16 + jj) * 33 + b2];
            float gg = gsm[(32 + jj) * 33 + b2];
            float go = gsm[(48 + jj) * 33 + b2];
            float i_ = 1.f / (1.f + expf(-gi));
            float f_ = 1.f / (1.f + expf(-gf));
            c1 = f_ * c1 + i_ * tanhf(gg);
            float hv = (1.f / (1.f + expf(-go))) * tanhf(c1);
            hdst[b2 * HH + js + jj] = hv;
            Xout[(size_t)(sdir * BB + b2) * 2048 + dir * HH + js + jj] = hv;
        }

        grid_bar();
    }
}

// ---------------------------------------------------------------------------
// BN(affine, fixed var=1) + ReLU + lin2 -> emissions (B,S,9)
// ---------------------------------------------------------------------------
__global__ void bn_lin2(const float* __restrict__ X, const float* __restrict__ gamma,
                        const float* __restrict__ beta, const float* __restrict__ w2,
                        const float* __restrict__ b2, float* __restrict__ emis) {
    int m = blockIdx.x;     // s*B+b
    int s = m / BB, b = m % BB;
    int tid = threadIdx.x;
    const float inv = rsqrtf(1.f + 1e-5f);
    float acc[NT];
#pragma unroll
    for (int j = 0; j < NT; j++) acc[j] = 0.f;
    for (int k = tid; k < 2048; k += 128) {
        float hv = X[(size_t)m * 2048 + k];
        hv = fmaxf(gamma[k] * inv * hv + beta[k], 0.f);
#pragma unroll
        for (int j = 0; j < NT; j++) acc[j] += hv * w2[j * 2048 + k];
    }
    __shared__ float red[NT][128];
#pragma unroll
    for (int j = 0; j < NT; j++) red[j][tid] = acc[j];
    __syncthreads();
    for (int off = 64; off > 0; off >>= 1) {
        if (tid < off) {
#pragma unroll
            for (int j = 0; j < NT; j++) red[j][tid] += red[j][tid + off];
        }
        __syncthreads();
    }
    if (tid < NT) emis[(size_t)(b * SS + s) * NT + tid] = red[tid][0] + b2[tid];
}

// ---------------------------------------------------------------------------
// CRF log-likelihood -> scalar. One block, 288 threads.
// ---------------------------------------------------------------------------
__global__ void crf_kernel(const float* __restrict__ emis, const int* __restrict__ y,
                           const unsigned char* __restrict__ maskb,
                           const float* __restrict__ start, const float* __restrict__ end_,
                           const float* __restrict__ trans, float* __restrict__ out) {
    __shared__ float alpha[BB][12];
    __shared__ float tmp[BB][12];
    __shared__ float tr[NT * NT];
    __shared__ float numv[BB];
    __shared__ float denv[BB];
    __shared__ int mask_mode;   // 1 = int32, 0 = bytes

    int tid = threadIdx.x;
    if (tid == 0) {
        int mm = 1;
        for (int i = 0; i < 16; i++) {
            if (maskb[4 * i + 1] | maskb[4 * i + 2] | maskb[4 * i + 3]) { mm = 0; break; }
        }
        mask_mode = mm;
    }
    if (tid < NT * NT) tr[tid] = trans[tid];
    __syncthreads();

    int b = tid / NT;
    int j = tid % NT;
    const int mm = mask_mode;
    const int* mi = (const int*)maskb;

    alpha[b][j] = start[j] + emis[(size_t)(b * SS) * NT + j];
    __syncthreads();

    for (int t = 1; t < SS; t++) {
        float mx = -1e30f;
#pragma unroll
        for (int i = 0; i < NT; i++) {
            float v = alpha[b][i] + tr[i * NT + j];
            mx = fmaxf(mx, v);
        }
        float ssum = 0.f;
#pragma unroll
        for (int i = 0; i < NT; i++)
            ssum += expf(alpha[b][i] + tr[i * NT + j] - mx);
        float nxt = mx + logf(ssum) + emis[(size_t)(b * SS + t) * NT + j];
        bool mk = mm ? (mi[b * SS + t] != 0) : (maskb[b * SS + t] != 0);
        __syncthreads();
        if (mk) alpha[b][j] = nxt;
        __syncthreads();
    }

    tmp[b][j] = alpha[b][j] + end_[j];
    __syncthreads();
    if (j == 0) {
        float mx = tmp[b][0];
#pragma unroll
        for (int i = 1; i < NT; i++) mx = fmaxf(mx, tmp[b][i]);
        float ssum = 0.f;
#pragma unroll
        for (int i = 0; i < NT; i++) ssum += expf(tmp[b][i] - mx);
        denv[b] = mx + logf(ssum);

        const int* yb = y + b * SS;
        float num = start[yb[0]] + emis[(size_t)(b * SS) * NT + yb[0]];
        int len = (mm ? (mi[b * SS] != 0) : (maskb[b * SS] != 0)) ? 1 : 0;
        for (int t = 1; t < SS; t++) {
            bool mk = mm ? (mi[b * SS + t] != 0) : (maskb[b * SS + t] != 0);
            if (mk) {
                num += tr[yb[t - 1] * NT + yb[t]] + emis[(size_t)(b * SS + t) * NT + yb[t]];
                len++;
            }
        }
        int last = yb[(len > 0 ? len : 1) - 1];
        num += end_[last];
        numv[b] = num;
    }
    __syncthreads();
    if (tid == 0) {
        float acc = 0.f;
        for (int bb2 = 0; bb2 < BB; bb2++) acc += numv[bb2] - denv[bb2];
        out[0] = acc;
    }
}

// ---------------------------------------------------------------------------
// Host launcher  (17 graph nodes total)
// ---------------------------------------------------------------------------
extern "C" void kernel_launch(void* const* d_in, const int* in_sizes, int n_in,
                              void* d_out, int out_size) {
    const int*   x       = (const int*)d_in[0];
    const int*   y       = (const int*)d_in[1];
    const unsigned char* mask = (const unsigned char*)d_in[2];
    const float* emb     = (const float*)d_in[3];
    const float* lin1_w  = (const float*)d_in[4];
    const float* lin1_b  = (const float*)d_in[5];
    const float* wih[4]  = {(const float*)d_in[6],  (const float*)d_in[9],
                            (const float*)d_in[12], (const float*)d_in[15]};
    const float* whh[4]  = {(const float*)d_in[7],  (const float*)d_in[10],
                            (const float*)d_in[13], (const float*)d_in[16]};
    const float* bias[4] = {(const float*)d_in[8],  (const float*)d_in[11],
                            (const float*)d_in[14], (const float*)d_in[17]};
    const float* bn_gamma = (const float*)d_in[18];
    const float* bn_beta  = (const float*)d_in[19];
    const float* lin2_w   = (const float*)d_in[20];
    const float* lin2_b   = (const float*)d_in[21];
    const float* crf_start = (const float*)d_in[22];
    const float* crf_end   = (const float*)d_in[23];
    const float* crf_trans = (const float*)d_in[24];

    float *E, *W1p, *X0, *X1, *pre, *h, *emis;
    cudaGetSymbolAddress((void**)&E, g_E);
    cudaGetSymbolAddress((void**)&W1p, g_W1p);
    cudaGetSymbolAddress((void**)&X0, g_X0);
    cudaGetSymbolAddress((void**)&X1, g_X1);
    cudaGetSymbolAddress((void**)&pre, g_pre);
    cudaGetSymbolAddress((void**)&h, g_h);
    cudaGetSymbolAddress((void**)&emis, g_emis);

    static bool attr_set = false;
    if (!attr_set) {
        cudaFuncSetAttribute(lstm_layer, cudaFuncAttributeMaxDynamicSharedMemorySize,
                             (32 * 1028 + 64 * 33) * sizeof(float));
        attr_set = true;
    }
    const int lstm_smem = (32 * 1028 + 64 * 33) * sizeof(float);

    gather_kernel<<<(4096 * DPAD + 255) / 256, 256>>>(E, x, emb);
    padw_kernel<<<(512 * DPAD + 255) / 256, 256>>>(W1p, lin1_w);
    gemm_bias<<<dim3(512 / 64, 4096 / 128), 256>>>(E, W1p, lin1_b, X0, 512, DPAD);

    float* Xin = X0;
    float* Xout = X1;
    const int Kin[4] = {512, 2048, 2048, 2048};

    for (int l = 0; l < 4; l++) {
        for (int dir = 0; dir < 2; dir++) {
            gemm_bias<<<dim3(G4 / 64, 4096 / 128), 256>>>(
                Xin, wih[l] + (size_t)dir * G4 * Kin[l], bias[l] + dir * G4,
                pre + (size_t)dir * 4096 * 4096, G4, Kin[l]);
        }
        lstm_layer<<<NBLK, 256, lstm_smem>>>(whh[l], pre, h, Xout);
        float* tmpp = Xin; Xin = Xout; Xout = tmpp;
    }

    bn_lin2<<<4096, 128>>>(Xin, bn_gamma, bn_beta, lin2_w, lin2_b, emis);
    crf_kernel<<<1, BB * NT>>>(emis, y, mask, crf_start, crf_end, crf_trans,
                               (float*)d_out);
}

// round 5
// speedup vs baseline: 1.4904x; 1.4904x over previous
#include <cuda_runtime.h>
#include <cuda_bf16.h>
#include <math.h>
#include <stdint.h>

// ---------------------------------------------------------------------------
// Problem constants
// ---------------------------------------------------------------------------
#define BB 32      // batch
#define SS 128     // seq len
#define DD 300     // emb dim
#define DPAD 304   // padded emb dim
#define HH 1024    // hidden
#define G4 4096    // 4*H
#define NT 9       // tags
#define LBLK 128   // persistent LSTM CTAs (single wave, <148 SMs)

// ---------------------------------------------------------------------------
// Scratch (static device allocations - allowed)
// ---------------------------------------------------------------------------
__device__ float g_E[4096 * DPAD];
__device__ float g_W1p[512 * DPAD];
__device__ float g_X0[4096 * 2048];
__device__ float g_X1[4096 * 2048];
__device__ float g_pre[2ull * 4096 * 4096];
__device__ float g_h[2 * 2 * BB * HH];      // [buf][dir][b][j]
__device__ float g_emis[BB * SS * NT];
// Whh bf16 hi/lo, A-fragment order: [cta 128][kstep 64][mtile 4][lane 32][4 u32]
__device__ uint4 g_Ahi[128 * 8192];
__device__ uint4 g_Alo[128 * 8192];

__device__ unsigned g_bar_cnt;
__device__ unsigned g_bar_gen;

// mma.sync m16n8k16 bf16 (baseline PTX, compiles for plain sm_103 -> HMMA)
#define MMA_BF16(d, a, b) \
    asm volatile("mma.sync.aligned.m16n8k16.row.col.f32.bf16.bf16.f32 " \
        "{%0,%1,%2,%3}, {%4,%5,%6,%7}, {%8,%9}, {%0,%1,%2,%3};" \
        : "+f"((d)[0]), "+f"((d)[1]), "+f"((d)[2]), "+f"((d)[3]) \
        : "r"((a).x), "r"((a).y), "r"((a).z), "r"((a).w), \
          "r"((b).x), "r"((b).y))

// ---------------------------------------------------------------------------
// Small prep kernels
// ---------------------------------------------------------------------------
__global__ void gather_kernel(float* __restrict__ E, const int* __restrict__ x,
                              const float* __restrict__ emb) {
    int i = blockIdx.x * blockDim.x + threadIdx.x;
    if (i >= 4096 * DPAD) return;
    int m = i / DPAD, col = i % DPAD;
    int s = m / BB, b = m % BB;
    int tok = x[b * SS + s];
    E[i] = (col < DD) ? emb[(size_t)tok * DD + col] : 0.f;
}

__global__ void padw_kernel(float* __restrict__ Wp, const float* __restrict__ W) {
    int i = blockIdx.x * blockDim.x + threadIdx.x;
    if (i >= 512 * DPAD) return;
    int r = i / DPAD, col = i % DPAD;
    Wp[i] = (col < DD) ? W[r * DD + col] : 0.f;
}

// Whh fp32 -> bf16 hi/lo, reordered into per-lane mma A-fragments.
// CTA c (of 128): dir=c>>6, j0=(c&63)*16; local row r(0..63): gate=r>>4, jj=r&15.
__global__ void convw_kernel(const float* __restrict__ whh,
                             __nv_bfloat16* __restrict__ Ahi,
                             __nv_bfloat16* __restrict__ Alo) {
    int i = blockIdx.x * blockDim.x + threadIdx.x;   // 128*64*1024
    if (i >= 128 * 64 * 1024) return;
    int c = i >> 16;
    int r = (i >> 10) & 63;
    int k = i & 1023;
    int dir = c >> 6, j0 = (c & 63) * 16;
    int gate = r >> 4, jj = r & 15;
    int grow = gate * 1024 + j0 + jj;
    float w = whh[(size_t)dir * G4 * HH + (size_t)grow * HH + k];
    __nv_bfloat16 hi = __float2bfloat16(w);
    __nv_bfloat16 lo = __float2bfloat16(w - __bfloat162float(hi));
    int mtile = gate, m = jj;
    int kstep = k >> 4, kin = k & 15;
    int lane = (m & 7) * 4 + ((kin >> 1) & 3);
    int reg = ((m >> 3) & 1) + ((kin >> 3) << 1);
    size_t idx = (size_t)c * 32768 + kstep * 512 + mtile * 128 + lane * 4 + reg;
    Ahi[idx * 2 + (kin & 1)] = hi;
    Alo[idx * 2 + (kin & 1)] = lo;
}

// ---------------------------------------------------------------------------
// Input-projection GEMM (SIMT fp32): C[M,N] = A[M,K]*B[N,K]^T + bias
// ---------------------------------------------------------------------------
__global__ void gemm_bias(const float* __restrict__ A, const float* __restrict__ Bm,
                          const float* __restrict__ bias, float* __restrict__ C,
                          int N, int K) {
    __shared__ float As[16][132];
    __shared__ float Bs[16][68];
    int tid = threadIdx.x;
    int m0 = blockIdx.y * 128;
    int n0 = blockIdx.x * 64;
    int tx = tid & 15, ty = tid >> 4;
    int lr = tid >> 2, lc = (tid & 3) * 4;

    const float* Ap  = A  + (size_t)(m0 + lr) * K + lc;
    const float* Ap2 = Ap + (size_t)64 * K;
    const float* Bp  = Bm + (size_t)(n0 + lr) * K + lc;

    float acc[8][4];
#pragma unroll
    for (int i = 0; i < 8; i++)
#pragma unroll
        for (int j = 0; j < 4; j++) acc[i][j] = 0.f;

    for (int k0 = 0; k0 < K; k0 += 16) {
        float4 a0 = *(const float4*)(Ap + k0);
        float4 a1 = *(const float4*)(Ap2 + k0);
        float4 b0 = *(const float4*)(Bp + k0);
        __syncthreads();
        As[lc + 0][lr] = a0.x; As[lc + 1][lr] = a0.y;
        As[lc + 2][lr] = a0.z; As[lc + 3][lr] = a0.w;
        As[lc + 0][lr + 64] = a1.x; As[lc + 1][lr + 64] = a1.y;
        As[lc + 2][lr + 64] = a1.z; As[lc + 3][lr + 64] = a1.w;
        Bs[lc + 0][lr] = b0.x; Bs[lc + 1][lr] = b0.y;
        Bs[lc + 2][lr] = b0.z; Bs[lc + 3][lr] = b0.w;
        __syncthreads();
#pragma unroll
        for (int k = 0; k < 16; k++) {
            float4 av0 = *(const float4*)&As[k][ty * 8];
            float4 av1 = *(const float4*)&As[k][ty * 8 + 4];
            float4 bv  = *(const float4*)&Bs[k][tx * 4];
            float am[8] = {av0.x, av0.y, av0.z, av0.w, av1.x, av1.y, av1.z, av1.w};
            float bb[4] = {bv.x, bv.y, bv.z, bv.w};
#pragma unroll
            for (int i = 0; i < 8; i++)
#pragma unroll
                for (int j = 0; j < 4; j++) acc[i][j] += am[i] * bb[j];
        }
    }
    float bs0 = bias[n0 + tx * 4 + 0];
    float bs1 = bias[n0 + tx * 4 + 1];
    float bs2 = bias[n0 + tx * 4 + 2];
    float bs3 = bias[n0 + tx * 4 + 3];
#pragma unroll
    for (int i = 0; i < 8; i++) {
        int m = m0 + ty * 8 + i;
        float4 ov;
        ov.x = acc[i][0] + bs0; ov.y = acc[i][1] + bs1;
        ov.z = acc[i][2] + bs2; ov.w = acc[i][3] + bs3;
        *(float4*)&C[(size_t)m * N + n0 + tx * 4] = ov;
    }
}

// ---------------------------------------------------------------------------
// Grid barrier (128 co-resident blocks)
// ---------------------------------------------------------------------------
__device__ __forceinline__ void grid_bar() {
    __threadfence();
    __syncthreads();
    if (threadIdx.x == 0) {
        volatile unsigned* vgen = &g_bar_gen;
        unsigned gen = *vgen;
        unsigned rank = atomicAdd(&g_bar_cnt, 1);
        if (rank == LBLK - 1) {
            atomicExch(&g_bar_cnt, 0);
            __threadfence();
            atomicExch(&g_bar_gen, gen + 1);
        } else {
            while (*vgen == gen) { __nanosleep(64); }
        }
        __threadfence();
    }
    __syncthreads();
}

// ---------------------------------------------------------------------------
// Persistent HMMA BiLSTM layer. 128 CTAs x 256 threads.
// CTA c: dir=c>>6, j0=(c&63)*16, owns 64 gate-rows {i,f,g,o}x16.
// Per step: h -> bf16 hi/lo B-fragments in smem, K-loop of mma.sync with
// A hi/lo streamed from L2 (prefetch d=2), raw gates to smem, cell update
// (CTA-local, c in regs), one grid barrier.
// ---------------------------------------------------------------------------
#define OFF_BLO 16384u            /* u32 index: sBhi[0..16383], sBlo[...] */
#define OFF_GSM 32768u            /* float idx in same u32 space */
#define SMEM_REQ (131072u + 8448u)

__global__ void __launch_bounds__(256, 1)
lstm_mma(const uint4* __restrict__ Ahi, const uint4* __restrict__ Alo,
         const float* __restrict__ pre, float* __restrict__ hbuf,
         float* __restrict__ Xout) {
    extern __shared__ __align__(16) uint32_t sm32[];
    uint32_t* sBhi = sm32;
    uint32_t* sBlo = sm32 + OFF_BLO;
    float*    gsm  = (float*)(sm32 + OFF_GSM);   // [64 rows][33]

    const int tid = threadIdx.x;
    const int wid = tid >> 5;
    const int lid = tid & 31;
    const int cta = blockIdx.x;
    const int dir = cta >> 6;
    const int j0  = (cta & 63) * 16;

    const int mtile  = wid >> 1;          // gate 0..3
    const int ntbase = (wid & 1) * 2;     // batch ntile pair

    const uint4* Ap  = Ahi + (size_t)cta * 8192 + mtile * 32 + lid;
    const uint4* Alp = Alo + (size_t)cta * 8192 + mtile * 32 + lid;
    const float* preD = pre + (size_t)dir * 4096 * 4096;

    float creg[2] = {0.f, 0.f};

    for (int t = 0; t < SS; t++) {
        const int sdir = dir ? (SS - 1 - t) : t;

        if (t > 0) {
            // --- h -> bf16 hi/lo B-fragments (float4 per iter) ---
            const float* hsrc = hbuf + (size_t)((t & 1) * 2 + dir) * (BB * HH);
            for (int i = tid; i < 8192; i += 256) {
                int b = i >> 8;
                int k4 = (i & 255) * 4;
                float4 v = __ldcg((const float4*)(hsrc + b * 1024 + k4));
                __nv_bfloat16 h0 = __float2bfloat16(v.x);
                __nv_bfloat16 h1 = __float2bfloat16(v.y);
                __nv_bfloat16 h2 = __float2bfloat16(v.z);
                __nv_bfloat16 h3 = __float2bfloat16(v.w);
                __nv_bfloat16 l0 = __float2bfloat16(v.x - __bfloat162float(h0));
                __nv_bfloat16 l1 = __float2bfloat16(v.y - __bfloat162float(h1));
                __nv_bfloat16 l2 = __float2bfloat16(v.z - __bfloat162float(h2));
                __nv_bfloat16 l3 = __float2bfloat16(v.w - __bfloat162float(h3));
                int kstep = k4 >> 4, kin = k4 & 15;         // kin in {0,4,8,12}
                int tig = (kin >> 1) & 3;
                int reg = kin >> 3;
                int nt = b >> 3, gid = b & 7;
                int idx = ((kstep * 4 + nt) * 32 + gid * 4 + tig) * 2 + reg;
                sBhi[idx] = (uint32_t)__bfloat16_as_ushort(h0) |
                            ((uint32_t)__bfloat16_as_ushort(h1) << 16);
                sBhi[idx + 2] = (uint32_t)__bfloat16_as_ushort(h2) |
                                ((uint32_t)__bfloat16_as_ushort(h3) << 16);
                sBlo[idx] = (uint32_t)__bfloat16_as_ushort(l0) |
                            ((uint32_t)__bfloat16_as_ushort(l1) << 16);
                sBlo[idx + 2] = (uint32_t)__bfloat16_as_ushort(l2) |
                                ((uint32_t)__bfloat16_as_ushort(l3) << 16);
            }
            __syncthreads();

            // --- K loop: 64 ksteps, 3-term hi/lo mma, prefetch distance 2 ---
            float d0[4] = {0.f, 0.f, 0.f, 0.f};
            float d1[4] = {0.f, 0.f, 0.f, 0.f};
            uint4 bufh[2], bufl[2];
            bufh[0] = __ldcg(Ap);          bufl[0] = __ldcg(Alp);
            bufh[1] = __ldcg(Ap + 128);    bufl[1] = __ldcg(Alp + 128);
#pragma unroll 2
            for (int ks = 0; ks < 64; ks++) {
                int s = ks & 1;
                uint4 ah = bufh[s], al = bufl[s];
                if (ks < 62) {
                    bufh[s] = __ldcg(Ap + (ks + 2) * 128);
                    bufl[s] = __ldcg(Alp + (ks + 2) * 128);
                }
                int bb0 = ((ks * 4 + ntbase) * 32 + lid) * 2;
                uint2 bh0 = *(const uint2*)(sBhi + bb0);
                uint2 bl0 = *(const uint2*)(sBlo + bb0);
                MMA_BF16(d0, ah, bh0);
                MMA_BF16(d0, ah, bl0);
                MMA_BF16(d0, al, bh0);
                int bb1 = bb0 + 64;
                uint2 bh1 = *(const uint2*)(sBhi + bb1);
                uint2 bl1 = *(const uint2*)(sBlo + bb1);
                MMA_BF16(d1, ah, bh1);
                MMA_BF16(d1, ah, bl1);
                MMA_BF16(d1, al, bh1);
            }
            // write raw gates to gsm
            int row0 = mtile * 16 + (lid >> 2);
            int n0 = ntbase * 8 + (lid & 3) * 2;
            gsm[row0 * 33 + n0]           = d0[0];
            gsm[row0 * 33 + n0 + 1]       = d0[1];
            gsm[(row0 + 8) * 33 + n0]     = d0[2];
            gsm[(row0 + 8) * 33 + n0 + 1] = d0[3];
            gsm[row0 * 33 + n0 + 8]           = d1[0];
            gsm[row0 * 33 + n0 + 9]           = d1[1];
            gsm[(row0 + 8) * 33 + n0 + 8]     = d1[2];
            gsm[(row0 + 8) * 33 + n0 + 9]     = d1[3];
        }
        __syncthreads();

        // --- cell update: 512 cells (16 j x 32 b), 2 per thread ---
        const float* prep = preD + (size_t)sdir * BB * G4;
        float* hdst = hbuf + (size_t)(((t + 1) & 1) * 2 + dir) * (BB * HH);
#pragma unroll
        for (int q = 0; q < 2; q++) {
            int idx = q * 256 + tid;
            int b = idx >> 4;
            int jj = idx & 15;
            const float* pp = prep + (size_t)b * G4 + j0 + jj;
            float gi = pp[0],    gf = pp[1024];
            float gg = pp[2048], go = pp[3072];
            if (t > 0) {
                gi += gsm[(0 * 16 + jj) * 33 + b];
                gf += gsm[(1 * 16 + jj) * 33 + b];
                gg += gsm[(2 * 16 + jj) * 33 + b];
                go += gsm[(3 * 16 + jj) * 33 + b];
            }
            float i_ = 1.f / (1.f + expf(-gi));
            float f_ = 1.f / (1.f + expf(-gf));
            creg[q] = f_ * creg[q] + i_ * tanhf(gg);
            float hv = (1.f / (1.f + expf(-go))) * tanhf(creg[q]);
            hdst[b * HH + j0 + jj] = hv;
            Xout[(size_t)(sdir * BB + b) * 2048 + dir * HH + j0 + jj] = hv;
        }

        grid_bar();
    }
}

// ---------------------------------------------------------------------------
// BN + ReLU + lin2 -> emissions
// ---------------------------------------------------------------------------
__global__ void bn_lin2(const float* __restrict__ X, const float* __restrict__ gamma,
                        const float* __restrict__ beta, const float* __restrict__ w2,
                        const float* __restrict__ b2, float* __restrict__ emis) {
    int m = blockIdx.x;
    int s = m / BB, b = m % BB;
    int tid = threadIdx.x;
    const float inv = rsqrtf(1.f + 1e-5f);
    float acc[NT];
#pragma unroll
    for (int j = 0; j < NT; j++) acc[j] = 0.f;
    for (int k = tid; k < 2048; k += 128) {
        float hv = X[(size_t)m * 2048 + k];
        hv = fmaxf(gamma[k] * inv * hv + beta[k], 0.f);
#pragma unroll
        for (int j = 0; j < NT; j++) acc[j] += hv * w2[j * 2048 + k];
    }
    __shared__ float red[NT][128];
#pragma unroll
    for (int j = 0; j < NT; j++) red[j][tid] = acc[j];
    __syncthreads();
    for (int off = 64; off > 0; off >>= 1) {
        if (tid < off) {
#pragma unroll
            for (int j = 0; j < NT; j++) red[j][tid] += red[j][tid + off];
        }
        __syncthreads();
    }
    if (tid < NT) emis[(size_t)(b * SS + s) * NT + tid] = red[tid][0] + b2[tid];
}

// ---------------------------------------------------------------------------
// CRF log-likelihood -> scalar
// ---------------------------------------------------------------------------
__global__ void crf_kernel(const float* __restrict__ emis, const int* __restrict__ y,
                           const unsigned char* __restrict__ maskb,
                           const float* __restrict__ start, const float* __restrict__ end_,
                           const float* __restrict__ trans, float* __restrict__ out) {
    __shared__ float alpha[BB][12];
    __shared__ float tmp[BB][12];
    __shared__ float tr[NT * NT];
    __shared__ float numv[BB];
    __shared__ float denv[BB];
    __shared__ int mask_mode;

    int tid = threadIdx.x;
    if (tid == 0) {
        int mm = 1;
        for (int i = 0; i < 16; i++) {
            if (maskb[4 * i + 1] | maskb[4 * i + 2] | maskb[4 * i + 3]) { mm = 0; break; }
        }
        mask_mode = mm;
    }
    if (tid < NT * NT) tr[tid] = trans[tid];
    __syncthreads();

    int b = tid / NT;
    int j = tid % NT;
    const int mm = mask_mode;
    const int* mi = (const int*)maskb;

    alpha[b][j] = start[j] + emis[(size_t)(b * SS) * NT + j];
    __syncthreads();

    for (int t = 1; t < SS; t++) {
        float mx = -1e30f;
#pragma unroll
        for (int i = 0; i < NT; i++) {
            float v = alpha[b][i] + tr[i * NT + j];
            mx = fmaxf(mx, v);
        }
        float ssum = 0.f;
#pragma unroll
        for (int i = 0; i < NT; i++)
            ssum += expf(alpha[b][i] + tr[i * NT + j] - mx);
        float nxt = mx + logf(ssum) + emis[(size_t)(b * SS + t) * NT + j];
        bool mk = mm ? (mi[b * SS + t] != 0) : (maskb[b * SS + t] != 0);
        __syncthreads();
        if (mk) alpha[b][j] = nxt;
        __syncthreads();
    }

    tmp[b][j] = alpha[b][j] + end_[j];
    __syncthreads();
    if (j == 0) {
        float mx = tmp[b][0];
#pragma unroll
        for (int i = 1; i < NT; i++) mx = fmaxf(mx, tmp[b][i]);
        float ssum = 0.f;
#pragma unroll
        for (int i = 0; i < NT; i++) ssum += expf(tmp[b][i] - mx);
        denv[b] = mx + logf(ssum);

        const int* yb = y + b * SS;
        float num = start[yb[0]] + emis[(size_t)(b * SS) * NT + yb[0]];
        int len = (mm ? (mi[b * SS] != 0) : (maskb[b * SS] != 0)) ? 1 : 0;
        for (int t = 1; t < SS; t++) {
            bool mk = mm ? (mi[b * SS + t] != 0) : (maskb[b * SS + t] != 0);
            if (mk) {
                num += tr[yb[t - 1] * NT + yb[t]] + emis[(size_t)(b * SS + t) * NT + yb[t]];
                len++;
            }
        }
        int last = yb[(len > 0 ? len : 1) - 1];
        num += end_[last];
        numv[b] = num;
    }
    __syncthreads();
    if (tid == 0) {
        float acc = 0.f;
        for (int bb2 = 0; bb2 < BB; bb2++) acc += numv[bb2] - denv[bb2];
        out[0] = acc;
    }
}

// ---------------------------------------------------------------------------
// Host launcher
// ---------------------------------------------------------------------------
extern "C" void kernel_launch(void* const* d_in, const int* in_sizes, int n_in,
                              void* d_out, int out_size) {
    const int*   x       = (const int*)d_in[0];
    const int*   y       = (const int*)d_in[1];
    const unsigned char* mask = (const unsigned char*)d_in[2];
    const float* emb     = (const float*)d_in[3];
    const float* lin1_w  = (const float*)d_in[4];
    const float* lin1_b  = (const float*)d_in[5];
    const float* wih[4]  = {(const float*)d_in[6],  (const float*)d_in[9],
                            (const float*)d_in[12], (const float*)d_in[15]};
    const float* whh[4]  = {(const float*)d_in[7],  (const float*)d_in[10],
                            (const float*)d_in[13], (const float*)d_in[16]};
    const float* bias[4] = {(const float*)d_in[8],  (const float*)d_in[11],
                            (const float*)d_in[14], (const float*)d_in[17]};
    const float* bn_gamma = (const float*)d_in[18];
    const float* bn_beta  = (const float*)d_in[19];
    const float* lin2_w   = (const float*)d_in[20];
    const float* lin2_b   = (const float*)d_in[21];
    const float* crf_start = (const float*)d_in[22];
    const float* crf_end   = (const float*)d_in[23];
    const float* crf_trans = (const float*)d_in[24];

    float *E, *W1p, *X0, *X1, *pre, *h, *emis;
    uint4 *Ahi, *Alo;
    cudaGetSymbolAddress((void**)&E, g_E);
    cudaGetSymbolAddress((void**)&W1p, g_W1p);
    cudaGetSymbolAddress((void**)&X0, g_X0);
    cudaGetSymbolAddress((void**)&X1, g_X1);
    cudaGetSymbolAddress((void**)&pre, g_pre);
    cudaGetSymbolAddress((void**)&h, g_h);
    cudaGetSymbolAddress((void**)&emis, g_emis);
    cudaGetSymbolAddress((void**)&Ahi, g_Ahi);
    cudaGetSymbolAddress((void**)&Alo, g_Alo);

    static bool attr_set = false;
    if (!attr_set) {
        cudaFuncSetAttribute(lstm_mma, cudaFuncAttributeMaxDynamicSharedMemorySize,
                             SMEM_REQ);
        attr_set = true;
    }

    gather_kernel<<<(4096 * DPAD + 255) / 256, 256>>>(E, x, emb);
    padw_kernel<<<(512 * DPAD + 255) / 256, 256>>>(W1p, lin1_w);
    gemm_bias<<<dim3(512 / 64, 4096 / 128), 256>>>(E, W1p, lin1_b, X0, 512, DPAD);

    float* Xin = X0;
    float* Xout = X1;
    const int Kin[4] = {512, 2048, 2048, 2048};

    for (int l = 0; l < 4; l++) {
        convw_kernel<<<(128 * 64 * 1024) / 256, 256>>>(
            whh[l], (__nv_bfloat16*)Ahi, (__nv_bfloat16*)Alo);
        for (int dir2 = 0; dir2 < 2; dir2++) {
            gemm_bias<<<dim3(G4 / 64, 4096 / 128), 256>>>(
                Xin, wih[l] + (size_t)dir2 * G4 * Kin[l], bias[l] + dir2 * G4,
                pre + (size_t)dir2 * 4096 * 4096, G4, Kin[l]);
        }
        lstm_mma<<<LBLK, 256, SMEM_REQ>>>(Ahi, Alo, pre, h, Xout);
        float* tmpp = Xin; Xin = Xout; Xout = tmpp;
    }

    bn_lin2<<<4096, 128>>>(Xin, bn_gamma, bn_beta, lin2_w, lin2_b, emis);
    crf_kernel<<<1, BB * NT>>>(emis, y, mask, crf_start, crf_end, crf_trans,
                               (float*)d_out);
}

// round 6
// speedup vs baseline: 1.5739x; 1.0560x over previous
#include <cuda_runtime.h>
#include <cuda_bf16.h>
#include <math.h>
#include <stdint.h>

// ---------------------------------------------------------------------------
// Problem constants
// ---------------------------------------------------------------------------
#define BB 32      // batch
#define SS 128     // seq len
#define DD 300     // emb dim
#define DPAD 304   // padded emb dim
#define HH 1024    // hidden
#define G4 4096    // 4*H
#define NT 9       // tags
#define LBLK 128   // persistent LSTM CTAs (single wave, <148 SMs)

// ---------------------------------------------------------------------------
// Scratch (static device allocations - allowed)
// ---------------------------------------------------------------------------
__device__ float g_E[4096 * DPAD];
__device__ float g_W1p[512 * DPAD];
__device__ float g_X0[4096 * 2048];
__device__ float g_X1[4096 * 2048];
__device__ float g_pre[2ull * 4096 * 4096];
__device__ float g_h[2 * 2 * BB * HH];      // [buf][dir][b][j]
__device__ float g_emis[BB * SS * NT];
// Whh bf16 hi/lo, A-fragment order: [cta 128][kstep 64][mtile 4][lane 32][4 u32]
__device__ uint4 g_Ahi[128 * 8192];
__device__ uint4 g_Alo[128 * 8192];

__device__ unsigned g_bar_cnt;
__device__ unsigned g_bar_gen;

// mma.sync m16n8k16 bf16 (baseline PTX, compiles for plain sm_103 -> HMMA)
#define MMA_BF16(d, a, b) \
    asm volatile("mma.sync.aligned.m16n8k16.row.col.f32.bf16.bf16.f32 " \
        "{%0,%1,%2,%3}, {%4,%5,%6,%7}, {%8,%9}, {%0,%1,%2,%3};" \
        : "+f"((d)[0]), "+f"((d)[1]), "+f"((d)[2]), "+f"((d)[3]) \
        : "r"((a).x), "r"((a).y), "r"((a).z), "r"((a).w), \
          "r"((b).x), "r"((b).y))

// ---------------------------------------------------------------------------
// Small prep kernels
// ---------------------------------------------------------------------------
__global__ void gather_kernel(float* __restrict__ E, const int* __restrict__ x,
                              const float* __restrict__ emb) {
    int i = blockIdx.x * blockDim.x + threadIdx.x;
    if (i >= 4096 * DPAD) return;
    int m = i / DPAD, col = i % DPAD;
    int s = m / BB, b = m % BB;
    int tok = x[b * SS + s];
    E[i] = (col < DD) ? emb[(size_t)tok * DD + col] : 0.f;
}

__global__ void padw_kernel(float* __restrict__ Wp, const float* __restrict__ W) {
    int i = blockIdx.x * blockDim.x + threadIdx.x;
    if (i >= 512 * DPAD) return;
    int r = i / DPAD, col = i % DPAD;
    Wp[i] = (col < DD) ? W[r * DD + col] : 0.f;
}

// Whh fp32 -> bf16 hi/lo, reordered into per-lane mma A-fragments.
// CTA c (of 128): dir=c>>6, j0=(c&63)*16; local row r(0..63): gate=r>>4, jj=r&15.
__global__ void convw_kernel(const float* __restrict__ whh,
                             __nv_bfloat16* __restrict__ Ahi,
                             __nv_bfloat16* __restrict__ Alo) {
    int i = blockIdx.x * blockDim.x + threadIdx.x;   // 128*64*1024
    if (i >= 128 * 64 * 1024) return;
    int c = i >> 16;
    int r = (i >> 10) & 63;
    int k = i & 1023;
    int dir = c >> 6, j0 = (c & 63) * 16;
    int gate = r >> 4, jj = r & 15;
    int grow = gate * 1024 + j0 + jj;
    float w = whh[(size_t)dir * G4 * HH + (size_t)grow * HH + k];
    __nv_bfloat16 hi = __float2bfloat16(w);
    __nv_bfloat16 lo = __float2bfloat16(w - __bfloat162float(hi));
    int mtile = gate, m = jj;
    int kstep = k >> 4, kin = k & 15;
    int lane = (m & 7) * 4 + ((kin >> 1) & 3);
    int reg = ((m >> 3) & 1) + ((kin >> 3) << 1);
    size_t idx = (size_t)c * 32768 + kstep * 512 + mtile * 128 + lane * 4 + reg;
    Ahi[idx * 2 + (kin & 1)] = hi;
    Alo[idx * 2 + (kin & 1)] = lo;
}

// ---------------------------------------------------------------------------
// Input-projection GEMM (SIMT fp32): C[M,N] = A[M,K]*B[N,K]^T + bias
// ---------------------------------------------------------------------------
__global__ void gemm_bias(const float* __restrict__ A, const float* __restrict__ Bm,
                          const float* __restrict__ bias, float* __restrict__ C,
                          int N, int K) {
    __shared__ float As[16][132];
    __shared__ float Bs[16][68];
    int tid = threadIdx.x;
    int m0 = blockIdx.y * 128;
    int n0 = blockIdx.x * 64;
    int tx = tid & 15, ty = tid >> 4;
    int lr = tid >> 2, lc = (tid & 3) * 4;

    const float* Ap  = A  + (size_t)(m0 + lr) * K + lc;
    const float* Ap2 = Ap + (size_t)64 * K;
    const float* Bp  = Bm + (size_t)(n0 + lr) * K + lc;

    float acc[8][4];
#pragma unroll
    for (int i = 0; i < 8; i++)
#pragma unroll
        for (int j = 0; j < 4; j++) acc[i][j] = 0.f;

    for (int k0 = 0; k0 < K; k0 += 16) {
        float4 a0 = *(const float4*)(Ap + k0);
        float4 a1 = *(const float4*)(Ap2 + k0);
        float4 b0 = *(const float4*)(Bp + k0);
        __syncthreads();
        As[lc + 0][lr] = a0.x; As[lc + 1][lr] = a0.y;
        As[lc + 2][lr] = a0.z; As[lc + 3][lr] = a0.w;
        As[lc + 0][lr + 64] = a1.x; As[lc + 1][lr + 64] = a1.y;
        As[lc + 2][lr + 64] = a1.z; As[lc + 3][lr + 64] = a1.w;
        Bs[lc + 0][lr] = b0.x; Bs[lc + 1][lr] = b0.y;
        Bs[lc + 2][lr] = b0.z; Bs[lc + 3][lr] = b0.w;
        __syncthreads();
#pragma unroll
        for (int k = 0; k < 16; k++) {
            float4 av0 = *(const float4*)&As[k][ty * 8];
            float4 av1 = *(const float4*)&As[k][ty * 8 + 4];
            float4 bv  = *(const float4*)&Bs[k][tx * 4];
            float am[8] = {av0.x, av0.y, av0.z, av0.w, av1.x, av1.y, av1.z, av1.w};
            float bb[4] = {bv.x, bv.y, bv.z, bv.w};
#pragma unroll
            for (int i = 0; i < 8; i++)
#pragma unroll
                for (int j = 0; j < 4; j++) acc[i][j] += am[i] * bb[j];
        }
    }
    float bs0 = bias[n0 + tx * 4 + 0];
    float bs1 = bias[n0 + tx * 4 + 1];
    float bs2 = bias[n0 + tx * 4 + 2];
    float bs3 = bias[n0 + tx * 4 + 3];
#pragma unroll
    for (int i = 0; i < 8; i++) {
        int m = m0 + ty * 8 + i;
        float4 ov;
        ov.x = acc[i][0] + bs0; ov.y = acc[i][1] + bs1;
        ov.z = acc[i][2] + bs2; ov.w = acc[i][3] + bs3;
        *(float4*)&C[(size_t)m * N + n0 + tx * 4] = ov;
    }
}

// ---------------------------------------------------------------------------
// Grid barrier (128 co-resident blocks)
// ---------------------------------------------------------------------------
__device__ __forceinline__ void grid_bar() {
    __threadfence();
    __syncthreads();
    if (threadIdx.x == 0) {
        volatile unsigned* vgen = &g_bar_gen;
        unsigned gen = *vgen;
        unsigned rank = atomicAdd(&g_bar_cnt, 1);
        if (rank == LBLK - 1) {
            atomicExch(&g_bar_cnt, 0);
            __threadfence();
            atomicExch(&g_bar_gen, gen + 1);
        } else {
            while (*vgen == gen) { __nanosleep(64); }
        }
        __threadfence();
    }
    __syncthreads();
}

// ---------------------------------------------------------------------------
// Persistent HMMA BiLSTM layer. 128 CTAs x 256 threads.
// CTA c: dir=c>>6, j0=(c&63)*16, owns 64 gate-rows {i,f,g,o}x16.
// K-loop: 2 ksteps/iter, 4 independent accumulator chains (dep distance 4),
// A hi/lo streamed from L2 with a 4-deep prefetch ring.
// ---------------------------------------------------------------------------
#define OFF_BLO 16384u            /* u32 index: sBhi[0..16383], sBlo[...] */
#define OFF_GSM 32768u            /* float idx in same u32 space */
#define SMEM_REQ (131072u + 8448u)

__global__ void __launch_bounds__(256, 1)
lstm_mma(const uint4* __restrict__ Ahi, const uint4* __restrict__ Alo,
         const float* __restrict__ pre, float* __restrict__ hbuf,
         float* __restrict__ Xout) {
    extern __shared__ __align__(16) uint32_t sm32[];
    uint32_t* sBhi = sm32;
    uint32_t* sBlo = sm32 + OFF_BLO;
    float*    gsm  = (float*)(sm32 + OFF_GSM);   // [64 rows][33]

    const int tid = threadIdx.x;
    const int wid = tid >> 5;
    const int lid = tid & 31;
    const int cta = blockIdx.x;
    const int dir = cta >> 6;
    const int j0  = (cta & 63) * 16;

    const int mtile  = wid >> 1;          // gate 0..3
    const int ntbase = (wid & 1) * 2;     // batch ntile pair

    const uint4* Ap  = Ahi + (size_t)cta * 8192 + mtile * 32 + lid;
    const uint4* Alp = Alo + (size_t)cta * 8192 + mtile * 32 + lid;
    const float* preD = pre + (size_t)dir * 4096 * 4096;

    float creg[2] = {0.f, 0.f};

    for (int t = 0; t < SS; t++) {
        const int sdir = dir ? (SS - 1 - t) : t;

        if (t > 0) {
            // --- h -> bf16 hi/lo B-fragments (float4 per iter) ---
            const float* hsrc = hbuf + (size_t)((t & 1) * 2 + dir) * (BB * HH);
            for (int i = tid; i < 8192; i += 256) {
                int b = i >> 8;
                int k4 = (i & 255) * 4;
                float4 v = __ldcg((const float4*)(hsrc + b * 1024 + k4));
                __nv_bfloat16 h0 = __float2bfloat16(v.x);
                __nv_bfloat16 h1 = __float2bfloat16(v.y);
                __nv_bfloat16 h2 = __float2bfloat16(v.z);
                __nv_bfloat16 h3 = __float2bfloat16(v.w);
                __nv_bfloat16 l0 = __float2bfloat16(v.x - __bfloat162float(h0));
                __nv_bfloat16 l1 = __float2bfloat16(v.y - __bfloat162float(h1));
                __nv_bfloat16 l2 = __float2bfloat16(v.z - __bfloat162float(h2));
                __nv_bfloat16 l3 = __float2bfloat16(v.w - __bfloat162float(h3));
                int kstep = k4 >> 4, kin = k4 & 15;         // kin in {0,4,8,12}
                int tig = (kin >> 1) & 3;
                int reg = kin >> 3;
                int nt = b >> 3, gid = b & 7;
                int idx = ((kstep * 4 + nt) * 32 + gid * 4 + tig) * 2 + reg;
                sBhi[idx] = (uint32_t)__bfloat16_as_ushort(h0) |
                            ((uint32_t)__bfloat16_as_ushort(h1) << 16);
                sBhi[idx + 2] = (uint32_t)__bfloat16_as_ushort(h2) |
                                ((uint32_t)__bfloat16_as_ushort(h3) << 16);
                sBlo[idx] = (uint32_t)__bfloat16_as_ushort(l0) |
                            ((uint32_t)__bfloat16_as_ushort(l1) << 16);
                sBlo[idx + 2] = (uint32_t)__bfloat16_as_ushort(l2) |
                                ((uint32_t)__bfloat16_as_ushort(l3) << 16);
            }
            __syncthreads();

            // --- K loop: 2 ksteps/iter, 4 accumulator chains, prefetch ring 4 ---
            float d0a[4] = {0.f,0.f,0.f,0.f}, d0b[4] = {0.f,0.f,0.f,0.f};
            float d1a[4] = {0.f,0.f,0.f,0.f}, d1b[4] = {0.f,0.f,0.f,0.f};
            uint4 bh[4], bl[4];
#pragma unroll
            for (int i = 0; i < 4; i++) {
                bh[i] = __ldcg(Ap + i * 128);
                bl[i] = __ldcg(Alp + i * 128);
            }
#pragma unroll 2
            for (int ks = 0; ks < 64; ks += 2) {
                int s0 = ks & 3, s1 = (ks + 1) & 3;
                uint4 ahE = bh[s0], alE = bl[s0];
                uint4 ahO = bh[s1], alO = bl[s1];
                if (ks < 60) {
                    bh[s0] = __ldcg(Ap + (ks + 4) * 128);
                    bl[s0] = __ldcg(Alp + (ks + 4) * 128);
                    bh[s1] = __ldcg(Ap + (ks + 5) * 128);
                    bl[s1] = __ldcg(Alp + (ks + 5) * 128);
                }
                int bbE = ((ks * 4 + ntbase) * 32 + lid) * 2;
                int bbO = (((ks + 1) * 4 + ntbase) * 32 + lid) * 2;
                uint2 bh0E = *(const uint2*)(sBhi + bbE);
                uint2 bl0E = *(const uint2*)(sBlo + bbE);
                uint2 bh1E = *(const uint2*)(sBhi + bbE + 64);
                uint2 bl1E = *(const uint2*)(sBlo + bbE + 64);
                uint2 bh0O = *(const uint2*)(sBhi + bbO);
                uint2 bl0O = *(const uint2*)(sBlo + bbO);
                uint2 bh1O = *(const uint2*)(sBhi + bbO + 64);
                uint2 bl1O = *(const uint2*)(sBlo + bbO + 64);
                // fully interleaved: each chain has dep distance 4
                MMA_BF16(d0a, ahE, bh0E); MMA_BF16(d0b, ahO, bh0O);
                MMA_BF16(d1a, ahE, bh1E); MMA_BF16(d1b, ahO, bh1O);
                MMA_BF16(d0a, ahE, bl0E); MMA_BF16(d0b, ahO, bl0O);
                MMA_BF16(d1a, ahE, bl1E); MMA_BF16(d1b, ahO, bl1O);
                MMA_BF16(d0a, alE, bh0E); MMA_BF16(d0b, alO, bh0O);
                MMA_BF16(d1a, alE, bh1E); MMA_BF16(d1b, alO, bh1O);
            }
            float d0[4], d1[4];
#pragma unroll
            for (int i = 0; i < 4; i++) {
                d0[i] = d0a[i] + d0b[i];
                d1[i] = d1a[i] + d1b[i];
            }
            // write raw gates to gsm
            int row0 = mtile * 16 + (lid >> 2);
            int n0 = ntbase * 8 + (lid & 3) * 2;
            gsm[row0 * 33 + n0]           = d0[0];
            gsm[row0 * 33 + n0 + 1]       = d0[1];
            gsm[(row0 + 8) * 33 + n0]     = d0[2];
            gsm[(row0 + 8) * 33 + n0 + 1] = d0[3];
            gsm[row0 * 33 + n0 + 8]           = d1[0];
            gsm[row0 * 33 + n0 + 9]           = d1[1];
            gsm[(row0 + 8) * 33 + n0 + 8]     = d1[2];
            gsm[(row0 + 8) * 33 + n0 + 9]     = d1[3];
        }
        __syncthreads();

        // --- cell update: 512 cells (16 j x 32 b), 2 per thread ---
        const float* prep = preD + (size_t)sdir * BB * G4;
        float* hdst = hbuf + (size_t)(((t + 1) & 1) * 2 + dir) * (BB * HH);
#pragma unroll
        for (int q = 0; q < 2; q++) {
            int idx = q * 256 + tid;
            int b = idx >> 4;
            int jj = idx & 15;
            const float* pp = prep + (size_t)b * G4 + j0 + jj;
            float gi = pp[0],    gf = pp[1024];
            float gg = pp[2048], go = pp[3072];
            if (t > 0) {
                gi += gsm[(0 * 16 + jj) * 33 + b];
                gf += gsm[(1 * 16 + jj) * 33 + b];
                gg += gsm[(2 * 16 + jj) * 33 + b];
                go += gsm[(3 * 16 + jj) * 33 + b];
            }
            float i_ = 1.f / (1.f + expf(-gi));
            float f_ = 1.f / (1.f + expf(-gf));
            creg[q] = f_ * creg[q] + i_ * tanhf(gg);
            float hv = (1.f / (1.f + expf(-go))) * tanhf(creg[q]);
            hdst[b * HH + j0 + jj] = hv;
            Xout[(size_t)(sdir * BB + b) * 2048 + dir * HH + j0 + jj] = hv;
        }

        grid_bar();
    }
}

// ---------------------------------------------------------------------------
// BN + ReLU + lin2 -> emissions
// ---------------------------------------------------------------------------
__global__ void bn_lin2(const float* __restrict__ X, const float* __restrict__ gamma,
                        const float* __restrict__ beta, const float* __restrict__ w2,
                        const float* __restrict__ b2, float* __restrict__ emis) {
    int m = blockIdx.x;
    int s = m / BB, b = m % BB;
    int tid = threadIdx.x;
    const float inv = rsqrtf(1.f + 1e-5f);
    float acc[NT];
#pragma unroll
    for (int j = 0; j < NT; j++) acc[j] = 0.f;
    for (int k = tid; k < 2048; k += 128) {
        float hv = X[(size_t)m * 2048 + k];
        hv = fmaxf(gamma[k] * inv * hv + beta[k], 0.f);
#pragma unroll
        for (int j = 0; j < NT; j++) acc[j] += hv * w2[j * 2048 + k];
    }
    __shared__ float red[NT][128];
#pragma unroll
    for (int j = 0; j < NT; j++) red[j][tid] = acc[j];
    __syncthreads();
    for (int off = 64; off > 0; off >>= 1) {
        if (tid < off) {
#pragma unroll
            for (int j = 0; j < NT; j++) red[j][tid] += red[j][tid + off];
        }
        __syncthreads();
    }
    if (tid < NT) emis[(size_t)(b * SS + s) * NT + tid] = red[tid][0] + b2[tid];
}

// ---------------------------------------------------------------------------
// CRF log-likelihood -> scalar
// ---------------------------------------------------------------------------
__global__ void crf_kernel(const float* __restrict__ emis, const int* __restrict__ y,
                           const unsigned char* __restrict__ maskb,
                           const float* __restrict__ start, const float* __restrict__ end_,
                           const float* __restrict__ trans, float* __restrict__ out) {
    __shared__ float alpha[BB][12];
    __shared__ float tmp[BB][12];
    __shared__ float tr[NT * NT];
    __shared__ float numv[BB];
    __shared__ float denv[BB];
    __shared__ int mask_mode;

    int tid = threadIdx.x;
    if (tid == 0) {
        int mm = 1;
        for (int i = 0; i < 16; i++) {
            if (maskb[4 * i + 1] | maskb[4 * i + 2] | maskb[4 * i + 3]) { mm = 0; break; }
        }
        mask_mode = mm;
    }
    if (tid < NT * NT) tr[tid] = trans[tid];
    __syncthreads();

    int b = tid / NT;
    int j = tid % NT;
    const int mm = mask_mode;
    const int* mi = (const int*)maskb;

    alpha[b][j] = start[j] + emis[(size_t)(b * SS) * NT + j];
    __syncthreads();

    for (int t = 1; t < SS; t++) {
        float mx = -1e30f;
#pragma unroll
        for (int i = 0; i < NT; i++) {
            float v = alpha[b][i] + tr[i * NT + j];
            mx = fmaxf(mx, v);
        }
        float ssum = 0.f;
#pragma unroll
        for (int i = 0; i < NT; i++)
            ssum += expf(alpha[b][i] + tr[i * NT + j] - mx);
        float nxt = mx + logf(ssum) + emis[(size_t)(b * SS + t) * NT + j];
        bool mk = mm ? (mi[b * SS + t] != 0) : (maskb[b * SS + t] != 0);
        __syncthreads();
        if (mk) alpha[b][j] = nxt;
        __syncthreads();
    }

    tmp[b][j] = alpha[b][j] + end_[j];
    __syncthreads();
    if (j == 0) {
        float mx = tmp[b][0];
#pragma unroll
        for (int i = 1; i < NT; i++) mx = fmaxf(mx, tmp[b][i]);
        float ssum = 0.f;
#pragma unroll
        for (int i = 0; i < NT; i++) ssum += expf(tmp[b][i] - mx);
        denv[b] = mx + logf(ssum);

        const int* yb = y + b * SS;
        float num = start[yb[0]] + emis[(size_t)(b * SS) * NT + yb[0]];
        int len = (mm ? (mi[b * SS] != 0) : (maskb[b * SS] != 0)) ? 1 : 0;
        for (int t = 1; t < SS; t++) {
            bool mk = mm ? (mi[b * SS + t] != 0) : (maskb[b * SS + t] != 0);
            if (mk) {
                num += tr[yb[t - 1] * NT + yb[t]] + emis[(size_t)(b * SS + t) * NT + yb[t]];
                len++;
            }
        }
        int last = yb[(len > 0 ? len : 1) - 1];
        num += end_[last];
        numv[b] = num;
    }
    __syncthreads();
    if (tid == 0) {
        float acc = 0.f;
        for (int bb2 = 0; bb2 < BB; bb2++) acc += numv[bb2] - denv[bb2];
        out[0] = acc;
    }
}

// ---------------------------------------------------------------------------
// Host launcher
// ---------------------------------------------------------------------------
extern "C" void kernel_launch(void* const* d_in, const int* in_sizes, int n_in,
                              void* d_out, int out_size) {
    const int*   x       = (const int*)d_in[0];
    const int*   y       = (const int*)d_in[1];
    const unsigned char* mask = (const unsigned char*)d_in[2];
    const float* emb     = (const float*)d_in[3];
    const float* lin1_w  = (const float*)d_in[4];
    const float* lin1_b  = (const float*)d_in[5];
    const float* wih[4]  = {(const float*)d_in[6],  (const float*)d_in[9],
                            (const float*)d_in[12], (const float*)d_in[15]};
    const float* whh[4]  = {(const float*)d_in[7],  (const float*)d_in[10],
                            (const float*)d_in[13], (const float*)d_in[16]};
    const float* bias[4] = {(const float*)d_in[8],  (const float*)d_in[11],
                            (const float*)d_in[14], (const float*)d_in[17]};
    const float* bn_gamma = (const float*)d_in[18];
    const float* bn_beta  = (const float*)d_in[19];
    const float* lin2_w   = (const float*)d_in[20];
    const float* lin2_b   = (const float*)d_in[21];
    const float* crf_start = (const float*)d_in[22];
    const float* crf_end   = (const float*)d_in[23];
    const float* crf_trans = (const float*)d_in[24];

    float *E, *W1p, *X0, *X1, *pre, *h, *emis;
    uint4 *Ahi, *Alo;
    cudaGetSymbolAddress((void**)&E, g_E);
    cudaGetSymbolAddress((void**)&W1p, g_W1p);
    cudaGetSymbolAddress((void**)&X0, g_X0);
    cudaGetSymbolAddress((void**)&X1, g_X1);
    cudaGetSymbolAddress((void**)&pre, g_pre);
    cudaGetSymbolAddress((void**)&h, g_h);
    cudaGetSymbolAddress((void**)&emis, g_emis);
    cudaGetSymbolAddress((void**)&Ahi, g_Ahi);
    cudaGetSymbolAddress((void**)&Alo, g_Alo);

    static bool attr_set = false;
    if (!attr_set) {
        cudaFuncSetAttribute(lstm_mma, cudaFuncAttributeMaxDynamicSharedMemorySize,
                             SMEM_REQ);
        attr_set = true;
    }

    gather_kernel<<<(4096 * DPAD + 255) / 256, 256>>>(E, x, emb);
    padw_kernel<<<(512 * DPAD + 255) / 256, 256>>>(W1p, lin1_w);
    gemm_bias<<<dim3(512 / 64, 4096 / 128), 256>>>(E, W1p, lin1_b, X0, 512, DPAD);

    float* Xin = X0;
    float* Xout = X1;
    const int Kin[4] = {512, 2048, 2048, 2048};

    for (int l = 0; l < 4; l++) {
        convw_kernel<<<(128 * 64 * 1024) / 256, 256>>>(
            whh[l], (__nv_bfloat16*)Ahi, (__nv_bfloat16*)Alo);
        for (int dir2 = 0; dir2 < 2; dir2++) {
            gemm_bias<<<dim3(G4 / 64, 4096 / 128), 256>>>(
                Xin, wih[l] + (size_t)dir2 * G4 * Kin[l], bias[l] + dir2 * G4,
                pre + (size_t)dir2 * 4096 * 4096, G4, Kin[l]);
        }
        lstm_mma<<<LBLK, 256, SMEM_REQ>>>(Ahi, Alo, pre, h, Xout);
        float* tmpp = Xin; Xin = Xout; Xout = tmpp;
    }

    bn_lin2<<<4096, 128>>>(Xin, bn_gamma, bn_beta, lin2_w, lin2_b, emis);
    crf_kernel<<<1, BB * NT>>>(emis, y, mask, crf_start, crf_end, crf_trans,
                               (float*)d_out);
}

// round 7
// speedup vs baseline: 1.7295x; 1.0989x over previous
#include <cuda_runtime.h>
#include <cuda_fp16.h>
#include <cuda_bf16.h>
#include <math.h>
#include <stdint.h>

// ---------------------------------------------------------------------------
// Problem constants
// ---------------------------------------------------------------------------
#define BB 32      // batch
#define SS 128     // seq len
#define DD 300     // emb dim
#define DPAD 304   // padded emb dim
#define HH 1024    // hidden
#define G4 4096    // 4*H
#define NT 9       // tags
#define LBLK 128   // persistent LSTM CTAs (single wave, <148 SMs)

// ---------------------------------------------------------------------------
// Scratch (static device allocations - allowed)
// ---------------------------------------------------------------------------
__device__ float g_E[4096 * DPAD];
__device__ float g_W1p[512 * DPAD];
__device__ float g_X0[4096 * 2048];
__device__ float g_X1[4096 * 2048];
__device__ float g_pre[2ull * 4096 * 4096];
__device__ float g_emis[BB * SS * NT];
// Whh fp16 hi/lo, A-fragment order: [cta 128][kstep 64][mtile 4][lane 32][4 u32]
__device__ uint4 g_Ahi[128 * 8192];
__device__ uint4 g_Alo[128 * 8192];
// h as fp16 B-fragments, parity double-buffered: [parity][dir][16384 u32]
__device__ uint32_t g_hfrag[2][2][16384];

__device__ unsigned g_bar_cnt;
__device__ unsigned g_bar_gen;

// mma.sync m16n8k16 fp16 -> f32 (baseline PTX, compiles for plain sm_103)
#define MMA_F16(d, a, b) \
    asm volatile("mma.sync.aligned.m16n8k16.row.col.f32.f16.f16.f32 " \
        "{%0,%1,%2,%3}, {%4,%5,%6,%7}, {%8,%9}, {%0,%1,%2,%3};" \
        : "+f"((d)[0]), "+f"((d)[1]), "+f"((d)[2]), "+f"((d)[3]) \
        : "r"((a).x), "r"((a).y), "r"((a).z), "r"((a).w), \
          "r"((b).x), "r"((b).y))

// ---------------------------------------------------------------------------
// Small prep kernels
// ---------------------------------------------------------------------------
__global__ void gather_kernel(float* __restrict__ E, const int* __restrict__ x,
                              const float* __restrict__ emb) {
    int i = blockIdx.x * blockDim.x + threadIdx.x;
    if (i >= 4096 * DPAD) return;
    int m = i / DPAD, col = i % DPAD;
    int s = m / BB, b = m % BB;
    int tok = x[b * SS + s];
    E[i] = (col < DD) ? emb[(size_t)tok * DD + col] : 0.f;
}

__global__ void padw_kernel(float* __restrict__ Wp, const float* __restrict__ W) {
    int i = blockIdx.x * blockDim.x + threadIdx.x;
    if (i >= 512 * DPAD) return;
    int r = i / DPAD, col = i % DPAD;
    Wp[i] = (col < DD) ? W[r * DD + col] : 0.f;
}

// Whh fp32 -> fp16 hi + fp16 residual, reordered into per-lane mma A-fragments.
// CTA c (of 128): dir=c>>6, j0=(c&63)*16; local row r(0..63): gate=r>>4, jj=r&15.
__global__ void convw_kernel(const float* __restrict__ whh,
                             __half* __restrict__ Ahi,
                             __half* __restrict__ Alo) {
    int i = blockIdx.x * blockDim.x + threadIdx.x;   // 128*64*1024
    if (i >= 128 * 64 * 1024) return;
    int c = i >> 16;
    int r = (i >> 10) & 63;
    int k = i & 1023;
    int dir = c >> 6, j0 = (c & 63) * 16;
    int gate = r >> 4, jj = r & 15;
    int grow = gate * 1024 + j0 + jj;
    float w = whh[(size_t)dir * G4 * HH + (size_t)grow * HH + k];
    __half hi = __float2half_rn(w);
    __half lo = __float2half_rn(w - __half2float(hi));
    int mtile = gate, m = jj;
    int kstep = k >> 4, kin = k & 15;
    int lane = (m & 7) * 4 + ((kin >> 1) & 3);
    int reg = ((m >> 3) & 1) + ((kin >> 3) << 1);
    size_t idx = (size_t)c * 32768 + kstep * 512 + mtile * 128 + lane * 4 + reg;
    Ahi[idx * 2 + (kin & 1)] = hi;
    Alo[idx * 2 + (kin & 1)] = lo;
}

// ---------------------------------------------------------------------------
// Input-projection GEMM (SIMT fp32): C[M,N] = A[M,K]*B[N,K]^T + bias
// ---------------------------------------------------------------------------
__global__ void gemm_bias(const float* __restrict__ A, const float* __restrict__ Bm,
                          const float* __restrict__ bias, float* __restrict__ C,
                          int N, int K) {
    __shared__ float As[16][132];
    __shared__ float Bs[16][68];
    int tid = threadIdx.x;
    int m0 = blockIdx.y * 128;
    int n0 = blockIdx.x * 64;
    int tx = tid & 15, ty = tid >> 4;
    int lr = tid >> 2, lc = (tid & 3) * 4;

    const float* Ap  = A  + (size_t)(m0 + lr) * K + lc;
    const float* Ap2 = Ap + (size_t)64 * K;
    const float* Bp  = Bm + (size_t)(n0 + lr) * K + lc;

    float acc[8][4];
#pragma unroll
    for (int i = 0; i < 8; i++)
#pragma unroll
        for (int j = 0; j < 4; j++) acc[i][j] = 0.f;

    for (int k0 = 0; k0 < K; k0 += 16) {
        float4 a0 = *(const float4*)(Ap + k0);
        float4 a1 = *(const float4*)(Ap2 + k0);
        float4 b0 = *(const float4*)(Bp + k0);
        __syncthreads();
        As[lc + 0][lr] = a0.x; As[lc + 1][lr] = a0.y;
        As[lc + 2][lr] = a0.z; As[lc + 3][lr] = a0.w;
        As[lc + 0][lr + 64] = a1.x; As[lc + 1][lr + 64] = a1.y;
        As[lc + 2][lr + 64] = a1.z; As[lc + 3][lr + 64] = a1.w;
        Bs[lc + 0][lr] = b0.x; Bs[lc + 1][lr] = b0.y;
        Bs[lc + 2][lr] = b0.z; Bs[lc + 3][lr] = b0.w;
        __syncthreads();
#pragma unroll
        for (int k = 0; k < 16; k++) {
            float4 av0 = *(const float4*)&As[k][ty * 8];
            float4 av1 = *(const float4*)&As[k][ty * 8 + 4];
            float4 bv  = *(const float4*)&Bs[k][tx * 4];
            float am[8] = {av0.x, av0.y, av0.z, av0.w, av1.x, av1.y, av1.z, av1.w};
            float bb[4] = {bv.x, bv.y, bv.z, bv.w};
#pragma unroll
            for (int i = 0; i < 8; i++)
#pragma unroll
                for (int j = 0; j < 4; j++) acc[i][j] += am[i] * bb[j];
        }
    }
    float bs0 = bias[n0 + tx * 4 + 0];
    float bs1 = bias[n0 + tx * 4 + 1];
    float bs2 = bias[n0 + tx * 4 + 2];
    float bs3 = bias[n0 + tx * 4 + 3];
#pragma unroll
    for (int i = 0; i < 8; i++) {
        int m = m0 + ty * 8 + i;
        float4 ov;
        ov.x = acc[i][0] + bs0; ov.y = acc[i][1] + bs1;
        ov.z = acc[i][2] + bs2; ov.w = acc[i][3] + bs3;
        *(float4*)&C[(size_t)m * N + n0 + tx * 4] = ov;
    }
}

// ---------------------------------------------------------------------------
// Grid barrier (128 co-resident blocks)
// ---------------------------------------------------------------------------
__device__ __forceinline__ void grid_bar() {
    __threadfence();
    __syncthreads();
    if (threadIdx.x == 0) {
        volatile unsigned* vgen = &g_bar_gen;
        unsigned gen = *vgen;
        unsigned rank = atomicAdd(&g_bar_cnt, 1);
        if (rank == LBLK - 1) {
            atomicExch(&g_bar_cnt, 0);
            __threadfence();
            atomicExch(&g_bar_gen, gen + 1);
        } else {
            while (*vgen == gen) { __nanosleep(64); }
        }
        __threadfence();
    }
    __syncthreads();
}

// ---------------------------------------------------------------------------
// Persistent HMMA BiLSTM layer. 128 CTAs x 256 threads.
// CTA c: dir=c>>6, j0=(c&63)*16 (kstep = c&63), owns 64 gate-rows {i,f,g,o}x16.
// Per step: K-loop (fp16 2-term: Ahi*B + Alo*B, B = h fragments from global,
// written by producers at the previous step), gates -> smem, cell update writes
// h directly as fp16 B-fragments (parity buffer) + fp32 layer output.
// ---------------------------------------------------------------------------
__global__ void __launch_bounds__(256, 1)
lstm_mma(const uint4* __restrict__ Ahi, const uint4* __restrict__ Alo,
         const float* __restrict__ pre, float* __restrict__ Xout) {
    __shared__ float gsm[64 * 33];   // [64 rows][33]

    const int tid = threadIdx.x;
    const int wid = tid >> 5;
    const int lid = tid & 31;
    const int cta = blockIdx.x;
    const int dir = cta >> 6;
    const int my_kstep = cta & 63;

    const int mtile  = wid >> 1;          // gate 0..3
    const int ntbase = (wid & 1) * 2;     // batch ntile pair

    const uint4* Aph = Ahi + (size_t)cta * 8192 + mtile * 32 + lid;
    const uint4* Apl = Alo + (size_t)cta * 8192 + mtile * 32 + lid;
    const float* preD = pre + (size_t)dir * 4096 * 4096;
    const int j0 = my_kstep * 16;

    float creg[2] = {0.f, 0.f};

    for (int t = 0; t < SS; t++) {
        const int sdir = dir ? (SS - 1 - t) : t;

        if (t > 0) {
            // B fragments of h(t-1): parity (t-1)&1
            const uint2* Bf = (const uint2*)g_hfrag[(t - 1) & 1][dir];

            float d0h[4] = {0.f,0.f,0.f,0.f}, d0l[4] = {0.f,0.f,0.f,0.f};
            float d1h[4] = {0.f,0.f,0.f,0.f}, d1l[4] = {0.f,0.f,0.f,0.f};
            uint4 rah[4], ral[4];
            uint2 rb0[4], rb1[4];
#pragma unroll
            for (int i = 0; i < 4; i++) {
                rah[i] = __ldg(Aph + i * 128);
                ral[i] = __ldcg(Apl + i * 128);
                rb0[i] = __ldcg(Bf + (i * 4 + ntbase) * 32 + lid);
                rb1[i] = __ldcg(Bf + (i * 4 + ntbase + 1) * 32 + lid);
            }
#pragma unroll 4
            for (int ks = 0; ks < 64; ks++) {
                int s = ks & 3;
                uint4 ah = rah[s], al = ral[s];
                uint2 b0 = rb0[s], b1 = rb1[s];
                if (ks < 60) {
                    rah[s] = __ldg(Aph + (ks + 4) * 128);
                    ral[s] = __ldcg(Apl + (ks + 4) * 128);
                    rb0[s] = __ldcg(Bf + ((ks + 4) * 4 + ntbase) * 32 + lid);
                    rb1[s] = __ldcg(Bf + ((ks + 4) * 4 + ntbase + 1) * 32 + lid);
                }
                // 4 independent chains, dep distance 4
                MMA_F16(d0h, ah, b0);
                MMA_F16(d1h, ah, b1);
                MMA_F16(d0l, al, b0);
                MMA_F16(d1l, al, b1);
            }
            float d0[4], d1[4];
#pragma unroll
            for (int i = 0; i < 4; i++) {
                d0[i] = d0h[i] + d0l[i];
                d1[i] = d1h[i] + d1l[i];
            }
            // write raw gates to gsm
            int row0 = mtile * 16 + (lid >> 2);
            int n0 = ntbase * 8 + (lid & 3) * 2;
            gsm[row0 * 33 + n0]           = d0[0];
            gsm[row0 * 33 + n0 + 1]       = d0[1];
            gsm[(row0 + 8) * 33 + n0]     = d0[2];
            gsm[(row0 + 8) * 33 + n0 + 1] = d0[3];
            gsm[row0 * 33 + n0 + 8]           = d1[0];
            gsm[row0 * 33 + n0 + 9]           = d1[1];
            gsm[(row0 + 8) * 33 + n0 + 8]     = d1[2];
            gsm[(row0 + 8) * 33 + n0 + 9]     = d1[3];
        }
        __syncthreads();

        // --- cell update: 512 cells (16 j x 32 b), 2 per thread ---
        // writes h(t) as fp16 B-fragments into parity buffer t&1
        const float* prep = preD + (size_t)sdir * BB * G4;
        __half* hf = (__half*)g_hfrag[t & 1][dir];
#pragma unroll
        for (int q = 0; q < 2; q++) {
            int idx = q * 256 + tid;
            int b = idx >> 4;
            int jj = idx & 15;
            const float* pp = prep + (size_t)b * G4 + j0 + jj;
            float gi = pp[0],    gf = pp[1024];
            float gg = pp[2048], go = pp[3072];
            if (t > 0) {
                gi += gsm[(0 * 16 + jj) * 33 + b];
                gf += gsm[(1 * 16 + jj) * 33 + b];
                gg += gsm[(2 * 16 + jj) * 33 + b];
                go += gsm[(3 * 16 + jj) * 33 + b];
            }
            float i_ = 1.f / (1.f + expf(-gi));
            float f_ = 1.f / (1.f + expf(-gf));
            creg[q] = f_ * creg[q] + i_ * tanhf(gg);
            float hv = (1.f / (1.f + expf(-go))) * tanhf(creg[q]);
            // fragment slot: nt=b>>3, gid=b&7, tig=(jj&7)>>1, reg=jj>>3, half=jj&1
            int u32i = ((my_kstep * 4 + (b >> 3)) * 32 + (b & 7) * 4 + ((jj & 7) >> 1)) * 2
                       + (jj >> 3);
            hf[u32i * 2 + (jj & 1)] = __float2half_rn(hv);
            Xout[(size_t)(sdir * BB + b) * 2048 + dir * HH + j0 + jj] = hv;
        }

        grid_bar();
    }
}

// ---------------------------------------------------------------------------
// BN + ReLU + lin2 -> emissions
// ---------------------------------------------------------------------------
__global__ void bn_lin2(const float* __restrict__ X, const float* __restrict__ gamma,
                        const float* __restrict__ beta, const float* __restrict__ w2,
                        const float* __restrict__ b2, float* __restrict__ emis) {
    int m = blockIdx.x;
    int s = m / BB, b = m % BB;
    int tid = threadIdx.x;
    const float inv = rsqrtf(1.f + 1e-5f);
    float acc[NT];
#pragma unroll
    for (int j = 0; j < NT; j++) acc[j] = 0.f;
    for (int k = tid; k < 2048; k += 128) {
        float hv = X[(size_t)m * 2048 + k];
        hv = fmaxf(gamma[k] * inv * hv + beta[k], 0.f);
#pragma unroll
        for (int j = 0; j < NT; j++) acc[j] += hv * w2[j * 2048 + k];
    }
    __shared__ float red[NT][128];
#pragma unroll
    for (int j = 0; j < NT; j++) red[j][tid] = acc[j];
    __syncthreads();
    for (int off = 64; off > 0; off >>= 1) {
        if (tid < off) {
#pragma unroll
            for (int j = 0; j < NT; j++) red[j][tid] += red[j][tid + off];
        }
        __syncthreads();
    }
    if (tid < NT) emis[(size_t)(b * SS + s) * NT + tid] = red[tid][0] + b2[tid];
}

// ---------------------------------------------------------------------------
// CRF log-likelihood -> scalar
// ---------------------------------------------------------------------------
__global__ void crf_kernel(const float* __restrict__ emis, const int* __restrict__ y,
                           const unsigned char* __restrict__ maskb,
                           const float* __restrict__ start, const float* __restrict__ end_,
                           const float* __restrict__ trans, float* __restrict__ out) {
    __shared__ float alpha[BB][12];
    __shared__ float tmp[BB][12];
    __shared__ float tr[NT * NT];
    __shared__ float numv[BB];
    __shared__ float denv[BB];
    __shared__ int mask_mode;

    int tid = threadIdx.x;
    if (tid == 0) {
        int mm = 1;
        for (int i = 0; i < 16; i++) {
            if (maskb[4 * i + 1] | maskb[4 * i + 2] | maskb[4 * i + 3]) { mm = 0; break; }
        }
        mask_mode = mm;
    }
    if (tid < NT * NT) tr[tid] = trans[tid];
    __syncthreads();

    int b = tid / NT;
    int j = tid % NT;
    const int mm = mask_mode;
    const int* mi = (const int*)maskb;

    alpha[b][j] = start[j] + emis[(size_t)(b * SS) * NT + j];
    __syncthreads();

    for (int t = 1; t < SS; t++) {
        float mx = -1e30f;
#pragma unroll
        for (int i = 0; i < NT; i++) {
            float v = alpha[b][i] + tr[i * NT + j];
            mx = fmaxf(mx, v);
        }
        float ssum = 0.f;
#pragma unroll
        for (int i = 0; i < NT; i++)
            ssum += expf(alpha[b][i] + tr[i * NT + j] - mx);
        float nxt = mx + logf(ssum) + emis[(size_t)(b * SS + t) * NT + j];
        bool mk = mm ? (mi[b * SS + t] != 0) : (maskb[b * SS + t] != 0);
        __syncthreads();
        if (mk) alpha[b][j] = nxt;
        __syncthreads();
    }

    tmp[b][j] = alpha[b][j] + end_[j];
    __syncthreads();
    if (j == 0) {
        float mx = tmp[b][0];
#pragma unroll
        for (int i = 1; i < NT; i++) mx = fmaxf(mx, tmp[b][i]);
        float ssum = 0.f;
#pragma unroll
        for (int i = 0; i < NT; i++) ssum += expf(tmp[b][i] - mx);
        denv[b] = mx + logf(ssum);

        const int* yb = y + b * SS;
        float num = start[yb[0]] + emis[(size_t)(b * SS) * NT + yb[0]];
        int len = (mm ? (mi[b * SS] != 0) : (maskb[b * SS] != 0)) ? 1 : 0;
        for (int t = 1; t < SS; t++) {
            bool mk = mm ? (mi[b * SS + t] != 0) : (maskb[b * SS + t] != 0);
            if (mk) {
                num += tr[yb[t - 1] * NT + yb[t]] + emis[(size_t)(b * SS + t) * NT + yb[t]];
                len++;
            }
        }
        int last = yb[(len > 0 ? len : 1) - 1];
        num += end_[last];
        numv[b] = num;
    }
    __syncthreads();
    if (tid == 0) {
        float acc = 0.f;
        for (int bb2 = 0; bb2 < BB; bb2++) acc += numv[bb2] - denv[bb2];
        out[0] = acc;
    }
}

// ---------------------------------------------------------------------------
// Host launcher
// ---------------------------------------------------------------------------
extern "C" void kernel_launch(void* const* d_in, const int* in_sizes, int n_in,
                              void* d_out, int out_size) {
    const int*   x       = (const int*)d_in[0];
    const int*   y       = (const int*)d_in[1];
    const unsigned char* mask = (const unsigned char*)d_in[2];
    const float* emb     = (const float*)d_in[3];
    const float* lin1_w  = (const float*)d_in[4];
    const float* lin1_b  = (const float*)d_in[5];
    const float* wih[4]  = {(const float*)d_in[6],  (const float*)d_in[9],
                            (const float*)d_in[12], (const float*)d_in[15]};
    const float* whh[4]  = {(const float*)d_in[7],  (const float*)d_in[10],
                            (const float*)d_in[13], (const float*)d_in[16]};
    const float* bias[4] = {(const float*)d_in[8],  (const float*)d_in[11],
                            (const float*)d_in[14], (const float*)d_in[17]};
    const float* bn_gamma = (const float*)d_in[18];
    const float* bn_beta  = (const float*)d_in[19];
    const float* lin2_w   = (const float*)d_in[20];
    const float* lin2_b   = (const float*)d_in[21];
    const float* crf_start = (const float*)d_in[22];
    const float* crf_end   = (const float*)d_in[23];
    const float* crf_trans = (const float*)d_in[24];

    float *E, *W1p, *X0, *X1, *pre, *emis;
    uint4 *Ahi, *Alo;
    cudaGetSymbolAddress((void**)&E, g_E);
    cudaGetSymbolAddress((void**)&W1p, g_W1p);
    cudaGetSymbolAddress((void**)&X0, g_X0);
    cudaGetSymbolAddress((void**)&X1, g_X1);
    cudaGetSymbolAddress((void**)&pre, g_pre);
    cudaGetSymbolAddress((void**)&emis, g_emis);
    cudaGetSymbolAddress((void**)&Ahi, g_Ahi);
    cudaGetSymbolAddress((void**)&Alo, g_Alo);

    gather_kernel<<<(4096 * DPAD + 255) / 256, 256>>>(E, x, emb);
    padw_kernel<<<(512 * DPAD + 255) / 256, 256>>>(W1p, lin1_w);
    gemm_bias<<<dim3(512 / 64, 4096 / 128), 256>>>(E, W1p, lin1_b, X0, 512, DPAD);

    float* Xin = X0;
    float* Xout = X1;
    const int Kin[4] = {512, 2048, 2048, 2048};

    for (int l = 0; l < 4; l++) {
        convw_kernel<<<(128 * 64 * 1024) / 256, 256>>>(
            whh[l], (__half*)Ahi, (__half*)Alo);
        for (int dir2 = 0; dir2 < 2; dir2++) {
            gemm_bias<<<dim3(G4 / 64, 4096 / 128), 256>>>(
                Xin, wih[l] + (size_t)dir2 * G4 * Kin[l], bias[l] + dir2 * G4,
                pre + (size_t)dir2 * 4096 * 4096, G4, Kin[l]);
        }
        lstm_mma<<<LBLK, 256>>>(Ahi, Alo, pre, Xout);
        float* tmpp = Xin; Xin = Xout; Xout = tmpp;
    }

    bn_lin2<<<4096, 128>>>(Xin, bn_gamma, bn_beta, lin2_w, lin2_b, emis);
    crf_kernel<<<1, BB * NT>>>(emis, y, mask, crf_start, crf_end, crf_trans,
                               (float*)d_out);
}

// round 8
// speedup vs baseline: 1.9533x; 1.1294x over previous
#include <cuda_runtime.h>
#include <cuda_fp16.h>
#include <cuda_bf16.h>
#include <math.h>
#include <stdint.h>

// ---------------------------------------------------------------------------
// Problem constants
// ---------------------------------------------------------------------------
#define BB 32      // batch
#define SS 128     // seq len
#define DD 300     // emb dim
#define DPAD 304   // padded emb dim
#define HH 1024    // hidden
#define G4 4096    // 4*H
#define NT 9       // tags
#define LBLK 128   // persistent LSTM CTAs (single wave, <148 SMs)
#define DBAR 64    // per-direction barrier arrivals

// ---------------------------------------------------------------------------
// Scratch (static device allocations - allowed)
// ---------------------------------------------------------------------------
__device__ float g_E[4096 * DPAD];
__device__ float g_W1p[512 * DPAD];
__device__ float g_X0[4096 * 2048];
__device__ float g_X1[4096 * 2048];
__device__ float g_pre[2ull * 4096 * 4096];
__device__ float g_emis[BB * SS * NT];
// Whh fp16 hi/lo, A-fragment order: [cta 128][kstep 64][mtile 4][lane 32][4 u32]
__device__ uint4 g_Ahi[128 * 8192];
__device__ uint4 g_Alo[128 * 8192];
// h as fp16 B-fragments, parity double-buffered: [parity][dir][16384 u32]
__device__ uint32_t g_hfrag[2][2][16384];

__device__ unsigned g_bar_cnt[2];
__device__ unsigned g_bar_gen[2];

// mma.sync m16n8k16 fp16 -> f32 (baseline PTX, compiles for plain sm_103)
#define MMA_F16(d, a, b) \
    asm volatile("mma.sync.aligned.m16n8k16.row.col.f32.f16.f16.f32 " \
        "{%0,%1,%2,%3}, {%4,%5,%6,%7}, {%8,%9}, {%0,%1,%2,%3};" \
        : "+f"((d)[0]), "+f"((d)[1]), "+f"((d)[2]), "+f"((d)[3]) \
        : "r"((a).x), "r"((a).y), "r"((a).z), "r"((a).w), \
          "r"((b).x), "r"((b).y))

// ---------------------------------------------------------------------------
// Small prep kernels
// ---------------------------------------------------------------------------
__global__ void gather_kernel(float* __restrict__ E, const int* __restrict__ x,
                              const float* __restrict__ emb) {
    int i = blockIdx.x * blockDim.x + threadIdx.x;
    if (i >= 4096 * DPAD) return;
    int m = i / DPAD, col = i % DPAD;
    int s = m / BB, b = m % BB;
    int tok = x[b * SS + s];
    E[i] = (col < DD) ? emb[(size_t)tok * DD + col] : 0.f;
}

__global__ void padw_kernel(float* __restrict__ Wp, const float* __restrict__ W) {
    int i = blockIdx.x * blockDim.x + threadIdx.x;
    if (i >= 512 * DPAD) return;
    int r = i / DPAD, col = i % DPAD;
    Wp[i] = (col < DD) ? W[r * DD + col] : 0.f;
}

// Whh fp32 -> fp16 hi + fp16 residual, reordered into per-lane mma A-fragments.
__global__ void convw_kernel(const float* __restrict__ whh,
                             __half* __restrict__ Ahi,
                             __half* __restrict__ Alo) {
    int i = blockIdx.x * blockDim.x + threadIdx.x;   // 128*64*1024
    if (i >= 128 * 64 * 1024) return;
    int c = i >> 16;
    int r = (i >> 10) & 63;
    int k = i & 1023;
    int dir = c >> 6, j0 = (c & 63) * 16;
    int gate = r >> 4, jj = r & 15;
    int grow = gate * 1024 + j0 + jj;
    float w = whh[(size_t)dir * G4 * HH + (size_t)grow * HH + k];
    __half hi = __float2half_rn(w);
    __half lo = __float2half_rn(w - __half2float(hi));
    int mtile = gate, m = jj;
    int kstep = k >> 4, kin = k & 15;
    int lane = (m & 7) * 4 + ((kin >> 1) & 3);
    int reg = ((m >> 3) & 1) + ((kin >> 3) << 1);
    size_t idx = (size_t)c * 32768 + kstep * 512 + mtile * 128 + lane * 4 + reg;
    Ahi[idx * 2 + (kin & 1)] = hi;
    Alo[idx * 2 + (kin & 1)] = lo;
}

// ---------------------------------------------------------------------------
// Input-projection GEMM (SIMT fp32): C[M,N] = A[M,K]*B[N,K]^T + bias
// ---------------------------------------------------------------------------
__global__ void gemm_bias(const float* __restrict__ A, const float* __restrict__ Bm,
                          const float* __restrict__ bias, float* __restrict__ C,
                          int N, int K) {
    __shared__ float As[16][132];
    __shared__ float Bs[16][68];
    int tid = threadIdx.x;
    int m0 = blockIdx.y * 128;
    int n0 = blockIdx.x * 64;
    int tx = tid & 15, ty = tid >> 4;
    int lr = tid >> 2, lc = (tid & 3) * 4;

    const float* Ap  = A  + (size_t)(m0 + lr) * K + lc;
    const float* Ap2 = Ap + (size_t)64 * K;
    const float* Bp  = Bm + (size_t)(n0 + lr) * K + lc;

    float acc[8][4];
#pragma unroll
    for (int i = 0; i < 8; i++)
#pragma unroll
        for (int j = 0; j < 4; j++) acc[i][j] = 0.f;

    for (int k0 = 0; k0 < K; k0 += 16) {
        float4 a0 = *(const float4*)(Ap + k0);
        float4 a1 = *(const float4*)(Ap2 + k0);
        float4 b0 = *(const float4*)(Bp + k0);
        __syncthreads();
        As[lc + 0][lr] = a0.x; As[lc + 1][lr] = a0.y;
        As[lc + 2][lr] = a0.z; As[lc + 3][lr] = a0.w;
        As[lc + 0][lr + 64] = a1.x; As[lc + 1][lr + 64] = a1.y;
        As[lc + 2][lr + 64] = a1.z; As[lc + 3][lr + 64] = a1.w;
        Bs[lc + 0][lr] = b0.x; Bs[lc + 1][lr] = b0.y;
        Bs[lc + 2][lr] = b0.z; Bs[lc + 3][lr] = b0.w;
        __syncthreads();
#pragma unroll
        for (int k = 0; k < 16; k++) {
            float4 av0 = *(const float4*)&As[k][ty * 8];
            float4 av1 = *(const float4*)&As[k][ty * 8 + 4];
            float4 bv  = *(const float4*)&Bs[k][tx * 4];
            float am[8] = {av0.x, av0.y, av0.z, av0.w, av1.x, av1.y, av1.z, av1.w};
            float bb[4] = {bv.x, bv.y, bv.z, bv.w};
#pragma unroll
            for (int i = 0; i < 8; i++)
#pragma unroll
                for (int j = 0; j < 4; j++) acc[i][j] += am[i] * bb[j];
        }
    }
    float bs0 = bias[n0 + tx * 4 + 0];
    float bs1 = bias[n0 + tx * 4 + 1];
    float bs2 = bias[n0 + tx * 4 + 2];
    float bs3 = bias[n0 + tx * 4 + 3];
#pragma unroll
    for (int i = 0; i < 8; i++) {
        int m = m0 + ty * 8 + i;
        float4 ov;
        ov.x = acc[i][0] + bs0; ov.y = acc[i][1] + bs1;
        ov.z = acc[i][2] + bs2; ov.w = acc[i][3] + bs3;
        *(float4*)&C[(size_t)m * N + n0 + tx * 4] = ov;
    }
}

// ---------------------------------------------------------------------------
// Per-direction grid barrier (64 co-resident blocks per dir)
// ---------------------------------------------------------------------------
__device__ __forceinline__ void grid_bar_dir(int dir) {
    __threadfence();
    __syncthreads();
    if (threadIdx.x == 0) {
        volatile unsigned* vgen = &g_bar_gen[dir];
        unsigned gen = *vgen;
        unsigned rank = atomicAdd(&g_bar_cnt[dir], 1);
        if (rank == DBAR - 1) {
            atomicExch(&g_bar_cnt[dir], 0);
            __threadfence();
            atomicExch(&g_bar_gen[dir], gen + 1);
        } else {
            while (*vgen == gen) { __nanosleep(64); }
        }
        __threadfence();
    }
    __syncthreads();
}

// ---------------------------------------------------------------------------
// Persistent HMMA BiLSTM layer. 128 CTAs x 512 threads (16 warps).
// Warp wid: ksplit=wid>>3 (32 ksteps each), mtile=(wid>>1)&3, ntbase=(wid&1)*2.
// pre loads hoisted to step start (overlap MMA phase); per-dir barrier.
// ---------------------------------------------------------------------------
__global__ void __launch_bounds__(512, 1)
lstm_mma(const uint4* __restrict__ Ahi, const uint4* __restrict__ Alo,
         const float* __restrict__ pre, float* __restrict__ Xout) {
    __shared__ float psum[2 * 64 * 33];   // [ksplit][64 rows][33]

    const int tid = threadIdx.x;
    const int wid = tid >> 5;
    const int lid = tid & 31;
    const int cta = blockIdx.x;
    const int dir = cta >> 6;
    const int my_kstep = cta & 63;
    const int j0 = my_kstep * 16;

    const int ksplit = wid >> 3;          // 0/1: K halves
    const int mtile  = (wid >> 1) & 3;    // gate 0..3
    const int ntbase = (wid & 1) * 2;     // batch ntile pair
    const int kbase  = ksplit * 32;

    const uint4* Aph = Ahi + (size_t)cta * 8192 + (size_t)kbase * 128 + mtile * 32 + lid;
    const uint4* Apl = Alo + (size_t)cta * 8192 + (size_t)kbase * 128 + mtile * 32 + lid;
    const float* preD = pre + (size_t)dir * 4096 * 4096;

    // cell ownership: one cell per thread
    const int cb = tid >> 4;      // batch 0..31
    const int cj = tid & 15;      // j within slice
    float creg = 0.f;

    for (int t = 0; t < SS; t++) {
        const int sdir = dir ? (SS - 1 - t) : t;

        // --- hoisted pre loads (DRAM latency overlaps MMA phase) ---
        const float* pp = preD + (size_t)sdir * BB * G4 + (size_t)cb * G4 + j0 + cj;
        float pg0 = __ldcg(pp);
        float pg1 = __ldcg(pp + 1024);
        float pg2 = __ldcg(pp + 2048);
        float pg3 = __ldcg(pp + 3072);

        if (t > 0) {
            const uint2* Bf = (const uint2*)g_hfrag[(t - 1) & 1][dir];

            float d0h[4] = {0.f,0.f,0.f,0.f}, d0l[4] = {0.f,0.f,0.f,0.f};
            float d1h[4] = {0.f,0.f,0.f,0.f}, d1l[4] = {0.f,0.f,0.f,0.f};
            uint4 rah[4], ral[4];
            uint2 rb0[4], rb1[4];
#pragma unroll
            for (int i = 0; i < 4; i++) {
                rah[i] = __ldg(Aph + i * 128);
                ral[i] = __ldcg(Apl + i * 128);
                rb0[i] = __ldcg(Bf + ((kbase + i) * 4 + ntbase) * 32 + lid);
                rb1[i] = __ldcg(Bf + ((kbase + i) * 4 + ntbase + 1) * 32 + lid);
            }
#pragma unroll 4
            for (int ks = 0; ks < 32; ks++) {
                int s = ks & 3;
                uint4 ah = rah[s], al = ral[s];
                uint2 b0 = rb0[s], b1 = rb1[s];
                if (ks < 28) {
                    rah[s] = __ldg(Aph + (ks + 4) * 128);
                    ral[s] = __ldcg(Apl + (ks + 4) * 128);
                    rb0[s] = __ldcg(Bf + ((kbase + ks + 4) * 4 + ntbase) * 32 + lid);
                    rb1[s] = __ldcg(Bf + ((kbase + ks + 4) * 4 + ntbase + 1) * 32 + lid);
                }
                MMA_F16(d0h, ah, b0);
                MMA_F16(d1h, ah, b1);
                MMA_F16(d0l, al, b0);
                MMA_F16(d1l, al, b1);
            }
            float d0[4], d1[4];
#pragma unroll
            for (int i = 0; i < 4; i++) {
                d0[i] = d0h[i] + d0l[i];
                d1[i] = d1h[i] + d1l[i];
            }
            float* ps = psum + ksplit * (64 * 33);
            int row0 = mtile * 16 + (lid >> 2);
            int n0 = ntbase * 8 + (lid & 3) * 2;
            ps[row0 * 33 + n0]           = d0[0];
            ps[row0 * 33 + n0 + 1]       = d0[1];
            ps[(row0 + 8) * 33 + n0]     = d0[2];
            ps[(row0 + 8) * 33 + n0 + 1] = d0[3];
            ps[row0 * 33 + n0 + 8]           = d1[0];
            ps[row0 * 33 + n0 + 9]           = d1[1];
            ps[(row0 + 8) * 33 + n0 + 8]     = d1[2];
            ps[(row0 + 8) * 33 + n0 + 9]     = d1[3];
        }
        __syncthreads();

        // --- cell update: one cell per thread (512 cells) ---
        float gi = pg0, gf = pg1, gg = pg2, go = pg3;
        if (t > 0) {
            gi += psum[(0 * 16 + cj) * 33 + cb] + psum[64 * 33 + (0 * 16 + cj) * 33 + cb];
            gf += psum[(1 * 16 + cj) * 33 + cb] + psum[64 * 33 + (1 * 16 + cj) * 33 + cb];
            gg += psum[(2 * 16 + cj) * 33 + cb] + psum[64 * 33 + (2 * 16 + cj) * 33 + cb];
            go += psum[(3 * 16 + cj) * 33 + cb] + psum[64 * 33 + (3 * 16 + cj) * 33 + cb];
        }
        float i_ = 1.f / (1.f + expf(-gi));
        float f_ = 1.f / (1.f + expf(-gf));
        creg = f_ * creg + i_ * tanhf(gg);
        float hv = (1.f / (1.f + expf(-go))) * tanhf(creg);
        // fragment slot: nt=cb>>3, gid=cb&7, tig=(cj&7)>>1, reg=cj>>3, half=cj&1
        __half* hf = (__half*)g_hfrag[t & 1][dir];
        int u32i = ((my_kstep * 4 + (cb >> 3)) * 32 + (cb & 7) * 4 + ((cj & 7) >> 1)) * 2
                   + (cj >> 3);
        hf[u32i * 2 + (cj & 1)] = __float2half_rn(hv);
        Xout[(size_t)(sdir * BB + cb) * 2048 + dir * HH + j0 + cj] = hv;

        grid_bar_dir(dir);
    }
}

// ---------------------------------------------------------------------------
// BN + ReLU + lin2 -> emissions
// ---------------------------------------------------------------------------
__global__ void bn_lin2(const float* __restrict__ X, const float* __restrict__ gamma,
                        const float* __restrict__ beta, const float* __restrict__ w2,
                        const float* __restrict__ b2, float* __restrict__ emis) {
    int m = blockIdx.x;
    int s = m / BB, b = m % BB;
    int tid = threadIdx.x;
    const float inv = rsqrtf(1.f + 1e-5f);
    float acc[NT];
#pragma unroll
    for (int j = 0; j < NT; j++) acc[j] = 0.f;
    for (int k = tid; k < 2048; k += 128) {
        float hv = X[(size_t)m * 2048 + k];
        hv = fmaxf(gamma[k] * inv * hv + beta[k], 0.f);
#pragma unroll
        for (int j = 0; j < NT; j++) acc[j] += hv * w2[j * 2048 + k];
    }
    __shared__ float red[NT][128];
#pragma unroll
    for (int j = 0; j < NT; j++) red[j][tid] = acc[j];
    __syncthreads();
    for (int off = 64; off > 0; off >>= 1) {
        if (tid < off) {
#pragma unroll
            for (int j = 0; j < NT; j++) red[j][tid] += red[j][tid + off];
        }
        __syncthreads();
    }
    if (tid < NT) emis[(size_t)(b * SS + s) * NT + tid] = red[tid][0] + b2[tid];
}

// ---------------------------------------------------------------------------
// CRF log-likelihood -> scalar
// ---------------------------------------------------------------------------
__global__ void crf_kernel(const float* __restrict__ emis, const int* __restrict__ y,
                           const unsigned char* __restrict__ maskb,
                           const float* __restrict__ start, const float* __restrict__ end_,
                           const float* __restrict__ trans, float* __restrict__ out) {
    __shared__ float alpha[BB][12];
    __shared__ float tmp[BB][12];
    __shared__ float tr[NT * NT];
    __shared__ float numv[BB];
    __shared__ float denv[BB];
    __shared__ int mask_mode;

    int tid = threadIdx.x;
    if (tid == 0) {
        int mm = 1;
        for (int i = 0; i < 16; i++) {
            if (maskb[4 * i + 1] | maskb[4 * i + 2] | maskb[4 * i + 3]) { mm = 0; break; }
        }
        mask_mode = mm;
    }
    if (tid < NT * NT) tr[tid] = trans[tid];
    __syncthreads();

    int b = tid / NT;
    int j = tid % NT;
    const int mm = mask_mode;
    const int* mi = (const int*)maskb;

    alpha[b][j] = start[j] + emis[(size_t)(b * SS) * NT + j];
    __syncthreads();

    for (int t = 1; t < SS; t++) {
        float mx = -1e30f;
#pragma unroll
        for (int i = 0; i < NT; i++) {
            float v = alpha[b][i] + tr[i * NT + j];
            mx = fmaxf(mx, v);
        }
        float ssum = 0.f;
#pragma unroll
        for (int i = 0; i < NT; i++)
            ssum += expf(alpha[b][i] + tr[i * NT + j] - mx);
        float nxt = mx + logf(ssum) + emis[(size_t)(b * SS + t) * NT + j];
        bool mk = mm ? (mi[b * SS + t] != 0) : (maskb[b * SS + t] != 0);
        __syncthreads();
        if (mk) alpha[b][j] = nxt;
        __syncthreads();
    }

    tmp[b][j] = alpha[b][j] + end_[j];
    __syncthreads();
    if (j == 0) {
        float mx = tmp[b][0];
#pragma unroll
        for (int i = 1; i < NT; i++) mx = fmaxf(mx, tmp[b][i]);
        float ssum = 0.f;
#pragma unroll
        for (int i = 0; i < NT; i++) ssum += expf(tmp[b][i] - mx);
        denv[b] = mx + logf(ssum);

        const int* yb = y + b * SS;
        float num = start[yb[0]] + emis[(size_t)(b * SS) * NT + yb[0]];
        int len = (mm ? (mi[b * SS] != 0) : (maskb[b * SS] != 0)) ? 1 : 0;
        for (int t = 1; t < SS; t++) {
            bool mk = mm ? (mi[b * SS + t] != 0) : (maskb[b * SS + t] != 0);
            if (mk) {
                num += tr[yb[t - 1] * NT + yb[t]] + emis[(size_t)(b * SS + t) * NT + yb[t]];
                len++;
            }
        }
        int last = yb[(len > 0 ? len : 1) - 1];
        num += end_[last];
        numv[b] = num;
    }
    __syncthreads();
    if (tid == 0) {
        float acc = 0.f;
        for (int bb2 = 0; bb2 < BB; bb2++) acc += numv[bb2] - denv[bb2];
        out[0] = acc;
    }
}

// ---------------------------------------------------------------------------
// Host launcher
// ---------------------------------------------------------------------------
extern "C" void kernel_launch(void* const* d_in, const int* in_sizes, int n_in,
                              void* d_out, int out_size) {
    const int*   x       = (const int*)d_in[0];
    const int*   y       = (const int*)d_in[1];
    const unsigned char* mask = (const unsigned char*)d_in[2];
    const float* emb     = (const float*)d_in[3];
    const float* lin1_w  = (const float*)d_in[4];
    const float* lin1_b  = (const float*)d_in[5];
    const float* wih[4]  = {(const float*)d_in[6],  (const float*)d_in[9],
                            (const float*)d_in[12], (const float*)d_in[15]};
    const float* whh[4]  = {(const float*)d_in[7],  (const float*)d_in[10],
                            (const float*)d_in[13], (const float*)d_in[16]};
    const float* bias[4] = {(const float*)d_in[8],  (const float*)d_in[11],
                            (const float*)d_in[14], (const float*)d_in[17]};
    const float* bn_gamma = (const float*)d_in[18];
    const float* bn_beta  = (const float*)d_in[19];
    const float* lin2_w   = (const float*)d_in[20];
    const float* lin2_b   = (const float*)d_in[21];
    const float* crf_start = (const float*)d_in[22];
    const float* crf_end   = (const float*)d_in[23];
    const float* crf_trans = (const float*)d_in[24];

    float *E, *W1p, *X0, *X1, *pre, *emis;
    uint4 *Ahi, *Alo;
    cudaGetSymbolAddress((void**)&E, g_E);
    cudaGetSymbolAddress((void**)&W1p, g_W1p);
    cudaGetSymbolAddress((void**)&X0, g_X0);
    cudaGetSymbolAddress((void**)&X1, g_X1);
    cudaGetSymbolAddress((void**)&pre, g_pre);
    cudaGetSymbolAddress((void**)&emis, g_emis);
    cudaGetSymbolAddress((void**)&Ahi, g_Ahi);
    cudaGetSymbolAddress((void**)&Alo, g_Alo);

    gather_kernel<<<(4096 * DPAD + 255) / 256, 256>>>(E, x, emb);
    padw_kernel<<<(512 * DPAD + 255) / 256, 256>>>(W1p, lin1_w);
    gemm_bias<<<dim3(512 / 64, 4096 / 128), 256>>>(E, W1p, lin1_b, X0, 512, DPAD);

    float* Xin = X0;
    float* Xout = X1;
    const int Kin[4] = {512, 2048, 2048, 2048};

    for (int l = 0; l < 4; l++) {
        convw_kernel<<<(128 * 64 * 1024) / 256, 256>>>(
            whh[l], (__half*)Ahi, (__half*)Alo);
        for (int dir2 = 0; dir2 < 2; dir2++) {
            gemm_bias<<<dim3(G4 / 64, 4096 / 128), 256>>>(
                Xin, wih[l] + (size_t)dir2 * G4 * Kin[l], bias[l] + dir2 * G4,
                pre + (size_t)dir2 * 4096 * 4096, G4, Kin[l]);
        }
        lstm_mma<<<LBLK, 512>>>(Ahi, Alo, pre, Xout);
        float* tmpp = Xin; Xin = Xout; Xout = tmpp;
    }

    bn_lin2<<<4096, 128>>>(Xin, bn_gamma, bn_beta, lin2_w, lin2_b, emis);
    crf_kernel<<<1, BB * NT>>>(emis, y, mask, crf_start, crf_end, crf_trans,
                               (float*)d_out);
}

// round 9
// speedup vs baseline: 2.0325x; 1.0406x over previous
#include <cuda_runtime.h>
#include <cuda_fp16.h>
#include <cuda_bf16.h>
#include <math.h>
#include <stdint.h>

// ---------------------------------------------------------------------------
// Problem constants
// ---------------------------------------------------------------------------
#define BB 32      // batch
#define SS 128     // seq len
#define DD 300     // emb dim
#define DPAD 304   // padded emb dim
#define HH 1024    // hidden
#define G4 4096    // 4*H
#define NT 9       // tags
#define LBLK 128   // persistent LSTM CTAs (single wave, <148 SMs)
#define DBAR 64    // per-direction barrier arrivals

// ---------------------------------------------------------------------------
// Scratch (static device allocations - allowed)
// ---------------------------------------------------------------------------
__device__ float g_E[4096 * DPAD];
__device__ float g_W1p[512 * DPAD];
__device__ float g_X0[4096 * 2048];
__device__ float g_X1[4096 * 2048];
__device__ float g_pre[2ull * 4096 * 4096];
__device__ float g_emis[BB * SS * NT];
// Whh fp16, A-fragment order: [cta 128][kstep 64][mtile 4][lane 32][4 u32]
__device__ uint4 g_Ahi[128 * 8192];
// h as fp16 B-fragments, parity double-buffered: [parity][dir][16384 u32]
__device__ uint32_t g_hfrag[2][2][16384];

__device__ unsigned g_bar_cnt[2];
__device__ unsigned g_bar_gen[2];

// mma.sync m16n8k16 fp16 -> f32 (baseline PTX, compiles for plain sm_103)
#define MMA_F16(d, a, b) \
    asm volatile("mma.sync.aligned.m16n8k16.row.col.f32.f16.f16.f32 " \
        "{%0,%1,%2,%3}, {%4,%5,%6,%7}, {%8,%9}, {%0,%1,%2,%3};" \
        : "+f"((d)[0]), "+f"((d)[1]), "+f"((d)[2]), "+f"((d)[3]) \
        : "r"((a).x), "r"((a).y), "r"((a).z), "r"((a).w), \
          "r"((b).x), "r"((b).y))

// ---------------------------------------------------------------------------
// Small prep kernels
// ---------------------------------------------------------------------------
__global__ void gather_kernel(float* __restrict__ E, const int* __restrict__ x,
                              const float* __restrict__ emb) {
    int i = blockIdx.x * blockDim.x + threadIdx.x;
    if (i >= 4096 * DPAD) return;
    int m = i / DPAD, col = i % DPAD;
    int s = m / BB, b = m % BB;
    int tok = x[b * SS + s];
    E[i] = (col < DD) ? emb[(size_t)tok * DD + col] : 0.f;
}

__global__ void padw_kernel(float* __restrict__ Wp, const float* __restrict__ W) {
    int i = blockIdx.x * blockDim.x + threadIdx.x;
    if (i >= 512 * DPAD) return;
    int r = i / DPAD, col = i % DPAD;
    Wp[i] = (col < DD) ? W[r * DD + col] : 0.f;
}

// Whh fp32 -> fp16, reordered into per-lane mma A-fragments.
__global__ void convw_kernel(const float* __restrict__ whh,
                             __half* __restrict__ Ahi) {
    int i = blockIdx.x * blockDim.x + threadIdx.x;   // 128*64*1024
    if (i >= 128 * 64 * 1024) return;
    int c = i >> 16;
    int r = (i >> 10) & 63;
    int k = i & 1023;
    int dir = c >> 6, j0 = (c & 63) * 16;
    int gate = r >> 4, jj = r & 15;
    int grow = gate * 1024 + j0 + jj;
    float w = whh[(size_t)dir * G4 * HH + (size_t)grow * HH + k];
    int mtile = gate, m = jj;
    int kstep = k >> 4, kin = k & 15;
    int lane = (m & 7) * 4 + ((kin >> 1) & 3);
    int reg = ((m >> 3) & 1) + ((kin >> 3) << 1);
    size_t idx = (size_t)c * 32768 + kstep * 512 + mtile * 128 + lane * 4 + reg;
    Ahi[idx * 2 + (kin & 1)] = __float2half_rn(w);
}

// ---------------------------------------------------------------------------
// Input-projection GEMM (SIMT fp32): C[M,N] = A[M,K]*B[N,K]^T + bias
// ---------------------------------------------------------------------------
__global__ void gemm_bias(const float* __restrict__ A, const float* __restrict__ Bm,
                          const float* __restrict__ bias, float* __restrict__ C,
                          int N, int K) {
    __shared__ float As[16][132];
    __shared__ float Bs[16][68];
    int tid = threadIdx.x;
    int m0 = blockIdx.y * 128;
    int n0 = blockIdx.x * 64;
    int tx = tid & 15, ty = tid >> 4;
    int lr = tid >> 2, lc = (tid & 3) * 4;

    const float* Ap  = A  + (size_t)(m0 + lr) * K + lc;
    const float* Ap2 = Ap + (size_t)64 * K;
    const float* Bp  = Bm + (size_t)(n0 + lr) * K + lc;

    float acc[8][4];
#pragma unroll
    for (int i = 0; i < 8; i++)
#pragma unroll
        for (int j = 0; j < 4; j++) acc[i][j] = 0.f;

    for (int k0 = 0; k0 < K; k0 += 16) {
        float4 a0 = *(const float4*)(Ap + k0);
        float4 a1 = *(const float4*)(Ap2 + k0);
        float4 b0 = *(const float4*)(Bp + k0);
        __syncthreads();
        As[lc + 0][lr] = a0.x; As[lc + 1][lr] = a0.y;
        As[lc + 2][lr] = a0.z; As[lc + 3][lr] = a0.w;
        As[lc + 0][lr + 64] = a1.x; As[lc + 1][lr + 64] = a1.y;
        As[lc + 2][lr + 64] = a1.z; As[lc + 3][lr + 64] = a1.w;
        Bs[lc + 0][lr] = b0.x; Bs[lc + 1][lr] = b0.y;
        Bs[lc + 2][lr] = b0.z; Bs[lc + 3][lr] = b0.w;
        __syncthreads();
#pragma unroll
        for (int k = 0; k < 16; k++) {
            float4 av0 = *(const float4*)&As[k][ty * 8];
            float4 av1 = *(const float4*)&As[k][ty * 8 + 4];
            float4 bv  = *(const float4*)&Bs[k][tx * 4];
            float am[8] = {av0.x, av0.y, av0.z, av0.w, av1.x, av1.y, av1.z, av1.w};
            float bb[4] = {bv.x, bv.y, bv.z, bv.w};
#pragma unroll
            for (int i = 0; i < 8; i++)
#pragma unroll
                for (int j = 0; j < 4; j++) acc[i][j] += am[i] * bb[j];
        }
    }
    float bs0 = bias[n0 + tx * 4 + 0];
    float bs1 = bias[n0 + tx * 4 + 1];
    float bs2 = bias[n0 + tx * 4 + 2];
    float bs3 = bias[n0 + tx * 4 + 3];
#pragma unroll
    for (int i = 0; i < 8; i++) {
        int m = m0 + ty * 8 + i;
        float4 ov;
        ov.x = acc[i][0] + bs0; ov.y = acc[i][1] + bs1;
        ov.z = acc[i][2] + bs2; ov.w = acc[i][3] + bs3;
        *(float4*)&C[(size_t)m * N + n0 + tx * 4] = ov;
    }
}

// ---------------------------------------------------------------------------
// Per-direction grid barrier (64 co-resident blocks per dir)
// ---------------------------------------------------------------------------
__device__ __forceinline__ void grid_bar_dir(int dir) {
    __threadfence();
    __syncthreads();
    if (threadIdx.x == 0) {
        volatile unsigned* vgen = &g_bar_gen[dir];
        unsigned gen = *vgen;
        unsigned rank = atomicAdd(&g_bar_cnt[dir], 1);
        if (rank == DBAR - 1) {
            atomicExch(&g_bar_cnt[dir], 0);
            __threadfence();
            atomicExch(&g_bar_gen[dir], gen + 1);
        } else {
            while (*vgen == gen) { __nanosleep(64); }
        }
        __threadfence();
    }
    __syncthreads();
}

// ---------------------------------------------------------------------------
// Persistent HMMA BiLSTM layer. 128 CTAs x 512 threads (16 warps).
// Warp wid: ksplit=wid>>3 (32 ksteps each), mtile=(wid>>1)&3, ntbase=(wid&1)*2.
// A = fp16 Whh fragments, L1-resident (128KB/CTA, reread each step via __ldg).
// B = h fp16 fragments from global (cross-CTA, __ldcg).
// ---------------------------------------------------------------------------
__global__ void __launch_bounds__(512, 1)
lstm_mma(const uint4* __restrict__ Ahi, const float* __restrict__ pre,
         float* __restrict__ Xout) {
    __shared__ float psum[2 * 64 * 33];   // [ksplit][64 rows][33]

    const int tid = threadIdx.x;
    const int wid = tid >> 5;
    const int lid = tid & 31;
    const int cta = blockIdx.x;
    const int dir = cta >> 6;
    const int my_kstep = cta & 63;
    const int j0 = my_kstep * 16;

    const int ksplit = wid >> 3;          // 0/1: K halves
    const int mtile  = (wid >> 1) & 3;    // gate 0..3
    const int ntbase = (wid & 1) * 2;     // batch ntile pair
    const int kbase  = ksplit * 32;

    const uint4* Aph = Ahi + (size_t)cta * 8192 + (size_t)kbase * 128 + mtile * 32 + lid;
    const float* preD = pre + (size_t)dir * 4096 * 4096;

    // cell ownership: one cell per thread
    const int cb = tid >> 4;      // batch 0..31
    const int cj = tid & 15;      // j within slice
    float creg = 0.f;

    for (int t = 0; t < SS; t++) {
        const int sdir = dir ? (SS - 1 - t) : t;

        // --- hoisted pre loads (DRAM latency overlaps MMA phase) ---
        const float* pp = preD + (size_t)sdir * BB * G4 + (size_t)cb * G4 + j0 + cj;
        float pg0 = __ldcg(pp);
        float pg1 = __ldcg(pp + 1024);
        float pg2 = __ldcg(pp + 2048);
        float pg3 = __ldcg(pp + 3072);

        if (t > 0) {
            const uint2* Bf = (const uint2*)g_hfrag[(t - 1) & 1][dir];

            float d0a[4] = {0.f,0.f,0.f,0.f}, d0b[4] = {0.f,0.f,0.f,0.f};
            float d1a[4] = {0.f,0.f,0.f,0.f}, d1b[4] = {0.f,0.f,0.f,0.f};
            uint4 rah[4];
            uint2 rb0[4], rb1[4];
#pragma unroll
            for (int i = 0; i < 4; i++) {
                rah[i] = __ldg(Aph + i * 128);
                rb0[i] = __ldcg(Bf + ((kbase + i) * 4 + ntbase) * 32 + lid);
                rb1[i] = __ldcg(Bf + ((kbase + i) * 4 + ntbase + 1) * 32 + lid);
            }
#pragma unroll 4
            for (int ks = 0; ks < 32; ks++) {
                int s = ks & 3;
                uint4 ah = rah[s];
                uint2 b0 = rb0[s], b1 = rb1[s];
                if (ks < 28) {
                    rah[s] = __ldg(Aph + (ks + 4) * 128);
                    rb0[s] = __ldcg(Bf + ((kbase + ks + 4) * 4 + ntbase) * 32 + lid);
                    rb1[s] = __ldcg(Bf + ((kbase + ks + 4) * 4 + ntbase + 1) * 32 + lid);
                }
                // kstep-parity split: 4 independent chains
                if (ks & 1) {
                    MMA_F16(d0b, ah, b0);
                    MMA_F16(d1b, ah, b1);
                } else {
                    MMA_F16(d0a, ah, b0);
                    MMA_F16(d1a, ah, b1);
                }
            }
            float d0[4], d1[4];
#pragma unroll
            for (int i = 0; i < 4; i++) {
                d0[i] = d0a[i] + d0b[i];
                d1[i] = d1a[i] + d1b[i];
            }
            float* ps = psum + ksplit * (64 * 33);
            int row0 = mtile * 16 + (lid >> 2);
            int n0 = ntbase * 8 + (lid & 3) * 2;
            ps[row0 * 33 + n0]           = d0[0];
            ps[row0 * 33 + n0 + 1]       = d0[1];
            ps[(row0 + 8) * 33 + n0]     = d0[2];
            ps[(row0 + 8) * 33 + n0 + 1] = d0[3];
            ps[row0 * 33 + n0 + 8]           = d1[0];
            ps[row0 * 33 + n0 + 9]           = d1[1];
            ps[(row0 + 8) * 33 + n0 + 8]     = d1[2];
            ps[(row0 + 8) * 33 + n0 + 9]     = d1[3];
        }
        __syncthreads();

        // --- cell update: one cell per thread (512 cells) ---
        float gi = pg0, gf = pg1, gg = pg2, go = pg3;
        if (t > 0) {
            gi += psum[(0 * 16 + cj) * 33 + cb] + psum[64 * 33 + (0 * 16 + cj) * 33 + cb];
            gf += psum[(1 * 16 + cj) * 33 + cb] + psum[64 * 33 + (1 * 16 + cj) * 33 + cb];
            gg += psum[(2 * 16 + cj) * 33 + cb] + psum[64 * 33 + (2 * 16 + cj) * 33 + cb];
            go += psum[(3 * 16 + cj) * 33 + cb] + psum[64 * 33 + (3 * 16 + cj) * 33 + cb];
        }
        float i_ = 1.f / (1.f + expf(-gi));
        float f_ = 1.f / (1.f + expf(-gf));
        creg = f_ * creg + i_ * tanhf(gg);
        float hv = (1.f / (1.f + expf(-go))) * tanhf(creg);
        // fragment slot: nt=cb>>3, gid=cb&7, tig=(cj&7)>>1, reg=cj>>3, half=cj&1
        __half* hf = (__half*)g_hfrag[t & 1][dir];
        int u32i = ((my_kstep * 4 + (cb >> 3)) * 32 + (cb & 7) * 4 + ((cj & 7) >> 1)) * 2
                   + (cj >> 3);
        hf[u32i * 2 + (cj & 1)] = __float2half_rn(hv);
        Xout[(size_t)(sdir * BB + cb) * 2048 + dir * HH + j0 + cj] = hv;

        grid_bar_dir(dir);
    }
}

// ---------------------------------------------------------------------------
// BN + ReLU + lin2 -> emissions
// ---------------------------------------------------------------------------
__global__ void bn_lin2(const float* __restrict__ X, const float* __restrict__ gamma,
                        const float* __restrict__ beta, const float* __restrict__ w2,
                        const float* __restrict__ b2, float* __restrict__ emis) {
    int m = blockIdx.x;
    int s = m / BB, b = m % BB;
    int tid = threadIdx.x;
    const float inv = rsqrtf(1.f + 1e-5f);
    float acc[NT];
#pragma unroll
    for (int j = 0; j < NT; j++) acc[j] = 0.f;
    for (int k = tid; k < 2048; k += 128) {
        float hv = X[(size_t)m * 2048 + k];
        hv = fmaxf(gamma[k] * inv * hv + beta[k], 0.f);
#pragma unroll
        for (int j = 0; j < NT; j++) acc[j] += hv * w2[j * 2048 + k];
    }
    __shared__ float red[NT][128];
#pragma unroll
    for (int j = 0; j < NT; j++) red[j][tid] = acc[j];
    __syncthreads();
    for (int off = 64; off > 0; off >>= 1) {
        if (tid < off) {
#pragma unroll
            for (int j = 0; j < NT; j++) red[j][tid] += red[j][tid + off];
        }
        __syncthreads();
    }
    if (tid < NT) emis[(size_t)(b * SS + s) * NT + tid] = red[tid][0] + b2[tid];
}

// ---------------------------------------------------------------------------
// CRF log-likelihood -> scalar
// ---------------------------------------------------------------------------
__global__ void crf_kernel(const float* __restrict__ emis, const int* __restrict__ y,
                           const unsigned char* __restrict__ maskb,
                           const float* __restrict__ start, const float* __restrict__ end_,
                           const float* __restrict__ trans, float* __restrict__ out) {
    __shared__ float alpha[BB][12];
    __shared__ float tmp[BB][12];
    __shared__ float tr[NT * NT];
    __shared__ float numv[BB];
    __shared__ float denv[BB];
    __shared__ int mask_mode;

    int tid = threadIdx.x;
    if (tid == 0) {
        int mm = 1;
        for (int i = 0; i < 16; i++) {
            if (maskb[4 * i + 1] | maskb[4 * i + 2] | maskb[4 * i + 3]) { mm = 0; break; }
        }
        mask_mode = mm;
    }
    if (tid < NT * NT) tr[tid] = trans[tid];
    __syncthreads();

    int b = tid / NT;
    int j = tid % NT;
    const int mm = mask_mode;
    const int* mi = (const int*)maskb;

    alpha[b][j] = start[j] + emis[(size_t)(b * SS) * NT + j];
    __syncthreads();

    for (int t = 1; t < SS; t++) {
        float mx = -1e30f;
#pragma unroll
        for (int i = 0; i < NT; i++) {
            float v = alpha[b][i] + tr[i * NT + j];
            mx = fmaxf(mx, v);
        }
        float ssum = 0.f;
#pragma unroll
        for (int i = 0; i < NT; i++)
            ssum += expf(alpha[b][i] + tr[i * NT + j] - mx);
        float nxt = mx + logf(ssum) + emis[(size_t)(b * SS + t) * NT + j];
        bool mk = mm ? (mi[b * SS + t] != 0) : (maskb[b * SS + t] != 0);
        __syncthreads();
        if (mk) alpha[b][j] = nxt;
        __syncthreads();
    }

    tmp[b][j] = alpha[b][j] + end_[j];
    __syncthreads();
    if (j == 0) {
        float mx = tmp[b][0];
#pragma unroll
        for (int i = 1; i < NT; i++) mx = fmaxf(mx, tmp[b][i]);
        float ssum = 0.f;
#pragma unroll
        for (int i = 0; i < NT; i++) ssum += expf(tmp[b][i] - mx);
        denv[b] = mx + logf(ssum);

        const int* yb = y + b * SS;
        float num = start[yb[0]] + emis[(size_t)(b * SS) * NT + yb[0]];
        int len = (mm ? (mi[b * SS] != 0) : (maskb[b * SS] != 0)) ? 1 : 0;
        for (int t = 1; t < SS; t++) {
            bool mk = mm ? (mi[b * SS + t] != 0) : (maskb[b * SS + t] != 0);
            if (mk) {
                num += tr[yb[t - 1] * NT + yb[t]] + emis[(size_t)(b * SS + t) * NT + yb[t]];
                len++;
            }
        }
        int last = yb[(len > 0 ? len : 1) - 1];
        num += end_[last];
        numv[b] = num;
    }
    __syncthreads();
    if (tid == 0) {
        float acc = 0.f;
        for (int bb2 = 0; bb2 < BB; bb2++) acc += numv[bb2] - denv[bb2];
        out[0] = acc;
    }
}

// ---------------------------------------------------------------------------
// Host launcher
// ---------------------------------------------------------------------------
extern "C" void kernel_launch(void* const* d_in, const int* in_sizes, int n_in,
                              void* d_out, int out_size) {
    const int*   x       = (const int*)d_in[0];
    const int*   y       = (const int*)d_in[1];
    const unsigned char* mask = (const unsigned char*)d_in[2];
    const float* emb     = (const float*)d_in[3];
    const float* lin1_w  = (const float*)d_in[4];
    const float* lin1_b  = (const float*)d_in[5];
    const float* wih[4]  = {(const float*)d_in[6],  (const float*)d_in[9],
                            (const float*)d_in[12], (const float*)d_in[15]};
    const float* whh[4]  = {(const float*)d_in[7],  (const float*)d_in[10],
                            (const float*)d_in[13], (const float*)d_in[16]};
    const float* bias[4] = {(const float*)d_in[8],  (const float*)d_in[11],
                            (const float*)d_in[14], (const float*)d_in[17]};
    const float* bn_gamma = (const float*)d_in[18];
    const float* bn_beta  = (const float*)d_in[19];
    const float* lin2_w   = (const float*)d_in[20];
    const float* lin2_b   = (const float*)d_in[21];
    const float* crf_start = (const float*)d_in[22];
    const float* crf_end   = (const float*)d_in[23];
    const float* crf_trans = (const float*)d_in[24];

    float *E, *W1p, *X0, *X1, *pre, *emis;
    uint4 *Ahi;
    cudaGetSymbolAddress((void**)&E, g_E);
    cudaGetSymbolAddress((void**)&W1p, g_W1p);
    cudaGetSymbolAddress((void**)&X0, g_X0);
    cudaGetSymbolAddress((void**)&X1, g_X1);
    cudaGetSymbolAddress((void**)&pre, g_pre);
    cudaGetSymbolAddress((void**)&emis, g_emis);
    cudaGetSymbolAddress((void**)&Ahi, g_Ahi);

    gather_kernel<<<(4096 * DPAD + 255) / 256, 256>>>(E, x, emb);
    padw_kernel<<<(512 * DPAD + 255) / 256, 256>>>(W1p, lin1_w);
    gemm_bias<<<dim3(512 / 64, 4096 / 128), 256>>>(E, W1p, lin1_b, X0, 512, DPAD);

    float* Xin = X0;
    float* Xout = X1;
    const int Kin[4] = {512, 2048, 2048, 2048};

    for (int l = 0; l < 4; l++) {
        convw_kernel<<<(128 * 64 * 1024) / 256, 256>>>(whh[l], (__half*)Ahi);
        for (int dir2 = 0; dir2 < 2; dir2++) {
            gemm_bias<<<dim3(G4 / 64, 4096 / 128), 256>>>(
                Xin, wih[l] + (size_t)dir2 * G4 * Kin[l], bias[l] + dir2 * G4,
                pre + (size_t)dir2 * 4096 * 4096, G4, Kin[l]);
        }
        lstm_mma<<<LBLK, 512>>>(Ahi, pre, Xout);
        float* tmpp = Xin; Xin = Xout; Xout = tmpp;
    }

    bn_lin2<<<4096, 128>>>(Xin, bn_gamma, bn_beta, lin2_w, lin2_b, emis);
    crf_kernel<<<1, BB * NT>>>(emis, y, mask, crf_start, crf_end, crf_trans,
                               (float*)d_out);
}

// round 10
// speedup vs baseline: 4.0717x; 2.0033x over previous
#include <cuda_runtime.h>
#include <cuda_fp16.h>
#include <cuda_bf16.h>
#include <math.h>
#include <stdint.h>

// ---------------------------------------------------------------------------
// Problem constants
// ---------------------------------------------------------------------------
#define BB 32      // batch
#define SS 128     // seq len
#define DD 300     // emb dim
#define DPAD 304   // padded emb dim
#define HH 1024    // hidden
#define G4 4096    // 4*H
#define NT 9       // tags
#define LBLK 128   // persistent LSTM CTAs (single wave, <148 SMs)
#define DBAR 64    // per-direction barrier arrivals

// ---------------------------------------------------------------------------
// Scratch (static device allocations - allowed)
// ---------------------------------------------------------------------------
__device__ float g_E[4096 * DPAD];
__device__ float g_W1p[512 * DPAD];
__device__ float g_X0[4096 * 2048];
__device__ float g_X1[4096 * 2048];
__device__ float g_pre[2ull * 4096 * 4096];
__device__ float g_emis[BB * SS * NT];
// Whh fp16, A-fragment order: [cta 128][kstep 64][mtile 4][lane 32][4 u32]
__device__ uint4 g_Ahi[128 * 8192];
// h as fp16 B-fragments, parity double-buffered: [parity][dir][16384 u32]
__device__ uint32_t g_hfrag[2][2][16384];
// input-projection fragments
__device__ uint4 g_Xf[64 * 128 * 4 * 32];       // A frags: [rowblk64][kstep<=128][mt4][lane32]
__device__ uint2 g_Wf[256 * 128 * 4 * 32];      // B frags: [nblk32 x256][kstep<=128][nt4][lane32]

__device__ unsigned g_bar_cnt[2];
__device__ unsigned g_bar_gen[2];

// mma.sync m16n8k16 fp16 -> f32 (baseline PTX, compiles for plain sm_103)
#define MMA_F16(d, a, b) \
    asm volatile("mma.sync.aligned.m16n8k16.row.col.f32.f16.f16.f32 " \
        "{%0,%1,%2,%3}, {%4,%5,%6,%7}, {%8,%9}, {%0,%1,%2,%3};" \
        : "+f"((d)[0]), "+f"((d)[1]), "+f"((d)[2]), "+f"((d)[3]) \
        : "r"((a).x), "r"((a).y), "r"((a).z), "r"((a).w), \
          "r"((b).x), "r"((b).y))

// ---------------------------------------------------------------------------
// Small prep kernels
// ---------------------------------------------------------------------------
__global__ void gather_kernel(float* __restrict__ E, const int* __restrict__ x,
                              const float* __restrict__ emb) {
    int i = blockIdx.x * blockDim.x + threadIdx.x;
    if (i >= 4096 * DPAD) return;
    int m = i / DPAD, col = i % DPAD;
    int s = m / BB, b = m % BB;
    int tok = x[b * SS + s];
    E[i] = (col < DD) ? emb[(size_t)tok * DD + col] : 0.f;
}

__global__ void padw_kernel(float* __restrict__ Wp, const float* __restrict__ W) {
    int i = blockIdx.x * blockDim.x + threadIdx.x;
    if (i >= 512 * DPAD) return;
    int r = i / DPAD, col = i % DPAD;
    Wp[i] = (col < DD) ? W[r * DD + col] : 0.f;
}

// Whh fp32 -> fp16, reordered into per-lane mma A-fragments (recurrent weights).
__global__ void convw_kernel(const float* __restrict__ whh,
                             __half* __restrict__ Ahi) {
    int i = blockIdx.x * blockDim.x + threadIdx.x;   // 128*64*1024
    if (i >= 128 * 64 * 1024) return;
    int c = i >> 16;
    int r = (i >> 10) & 63;
    int k = i & 1023;
    int dir = c >> 6, j0 = (c & 63) * 16;
    int gate = r >> 4, jj = r & 15;
    int grow = gate * 1024 + j0 + jj;
    float w = whh[(size_t)dir * G4 * HH + (size_t)grow * HH + k];
    int mtile = gate, m = jj;
    int kstep = k >> 4, kin = k & 15;
    int lane = (m & 7) * 4 + ((kin >> 1) & 3);
    int reg = ((m >> 3) & 1) + ((kin >> 3) << 1);
    size_t idx = (size_t)c * 32768 + kstep * 512 + mtile * 128 + lane * 4 + reg;
    Ahi[idx * 2 + (kin & 1)] = __float2half_rn(w);
}

// X fp32 (4096 x K) -> fp16 A-fragments
__global__ void convx_kernel(const float* __restrict__ X, __half* __restrict__ Xf,
                             int K, int KS) {
    int i = blockIdx.x * blockDim.x + threadIdx.x;
    if (i >= 4096 * K) return;
    int m = i / K, k = i % K;
    int rowblk = m >> 6, r = m & 63;
    int mt = r >> 4, mrow = r & 15;
    int kstep = k >> 4, kin = k & 15;
    int lane = (mrow & 7) * 4 + ((kin >> 1) & 3);
    int reg = ((mrow >> 3) & 1) + ((kin >> 3) << 1);
    size_t e = (((((size_t)rowblk * KS + kstep) * 4 + mt) * 32 + lane) * 4 + reg) * 2
               + (kin & 1);
    Xf[e] = __float2half_rn(X[i]);
}

// Wih fp32 (8192 x K, dir-major) -> fp16 B-fragments
__global__ void convwih_kernel(const float* __restrict__ W, __half* __restrict__ Wf,
                               int K, int KS) {
    int i = blockIdx.x * blockDim.x + threadIdx.x;
    if (i >= 8192 * K) return;
    int n = i / K, k = i % K;
    int nblk = n >> 5, nr = n & 31;
    int nt = nr >> 3, ncol = nr & 7;
    int kstep = k >> 4, kin = k & 15;
    int lane = ncol * 4 + ((kin & 7) >> 1);
    int reg = kin >> 3;
    size_t e = (((((size_t)nblk * KS + kstep) * 4 + nt) * 32 + lane) * 2 + reg) * 2
               + (kin & 1);
    Wf[e] = __float2half_rn(W[i]);
}

// ---------------------------------------------------------------------------
// HMMA input-projection GEMM: pre[dir][m][col] = X[m] . Wih[n] + bias[n]
// M=4096, N=8192 (dir-major), K=KS*16. Grid (64, 32), 256 threads, 8 warps.
// Warp tile 64x32: 4 mtiles x 4 ntiles of m16n8k16 per kstep.
// ---------------------------------------------------------------------------
__global__ void __launch_bounds__(256, 1)
hgemm_pre(const uint4* __restrict__ Xf, const uint2* __restrict__ Wf,
          const float* __restrict__ bias, float* __restrict__ pre, int KS) {
    const int tid = threadIdx.x;
    const int wid = tid >> 5, lane = tid & 31;
    const int warp_m = wid >> 2, warp_n = wid & 3;
    const int rowblk = blockIdx.y * 2 + warp_m;
    const int nblk = blockIdx.x * 4 + warp_n;

    const uint4* Ab = Xf + (size_t)rowblk * KS * 128 + lane;
    const uint2* Bb = Wf + (size_t)nblk * KS * 128 + lane;

    float d[4][4][4];
#pragma unroll
    for (int mt = 0; mt < 4; mt++)
#pragma unroll
        for (int nt = 0; nt < 4; nt++)
#pragma unroll
            for (int q = 0; q < 4; q++) d[mt][nt][q] = 0.f;

    uint4 a[4];
    uint2 b[4];
#pragma unroll
    for (int i = 0; i < 4; i++) {
        a[i] = __ldg(Ab + i * 32);
        b[i] = __ldg(Bb + i * 32);
    }

    for (int ks = 0; ks < KS; ks++) {
        uint4 ca[4];
        uint2 cb[4];
#pragma unroll
        for (int i = 0; i < 4; i++) { ca[i] = a[i]; cb[i] = b[i]; }
        if (ks + 1 < KS) {
            const uint4* An = Ab + (size_t)(ks + 1) * 128;
            const uint2* Bn = Bb + (size_t)(ks + 1) * 128;
#pragma unroll
            for (int i = 0; i < 4; i++) {
                a[i] = __ldg(An + i * 32);
                b[i] = __ldg(Bn + i * 32);
            }
        }
#pragma unroll
        for (int mt = 0; mt < 4; mt++)
#pragma unroll
            for (int nt = 0; nt < 4; nt++)
                MMA_F16(d[mt][nt], ca[mt], cb[nt]);
    }

    // epilogue: bias + store fp32 into pre[dir][m][col]
#pragma unroll
    for (int mt = 0; mt < 4; mt++) {
        int m = rowblk * 64 + mt * 16 + (lane >> 2);
#pragma unroll
        for (int nt = 0; nt < 4; nt++) {
            int nn = nblk * 32 + nt * 8 + (lane & 3) * 2;
            int dir = nn >> 12;
            int col = nn & 4095;
            float bs0 = __ldg(bias + nn);
            float bs1 = __ldg(bias + nn + 1);
            float* outp = pre + (size_t)dir * 4096 * 4096 + (size_t)m * 4096 + col;
            float2 v0 = make_float2(d[mt][nt][0] + bs0, d[mt][nt][1] + bs1);
            *(float2*)outp = v0;
            float2 v1 = make_float2(d[mt][nt][2] + bs0, d[mt][nt][3] + bs1);
            *(float2*)(outp + (size_t)8 * 4096) = v1;
        }
    }
}

// ---------------------------------------------------------------------------
// Input-projection GEMM (SIMT fp32, used only for lin1 now)
// ---------------------------------------------------------------------------
__global__ void gemm_bias(const float* __restrict__ A, const float* __restrict__ Bm,
                          const float* __restrict__ bias, float* __restrict__ C,
                          int N, int K) {
    __shared__ float As[16][132];
    __shared__ float Bs[16][68];
    int tid = threadIdx.x;
    int m0 = blockIdx.y * 128;
    int n0 = blockIdx.x * 64;
    int tx = tid & 15, ty = tid >> 4;
    int lr = tid >> 2, lc = (tid & 3) * 4;

    const float* Ap  = A  + (size_t)(m0 + lr) * K + lc;
    const float* Ap2 = Ap + (size_t)64 * K;
    const float* Bp  = Bm + (size_t)(n0 + lr) * K + lc;

    float acc[8][4];
#pragma unroll
    for (int i = 0; i < 8; i++)
#pragma unroll
        for (int j = 0; j < 4; j++) acc[i][j] = 0.f;

    for (int k0 = 0; k0 < K; k0 += 16) {
        float4 a0 = *(const float4*)(Ap + k0);
        float4 a1 = *(const float4*)(Ap2 + k0);
        float4 b0 = *(const float4*)(Bp + k0);
        __syncthreads();
        As[lc + 0][lr] = a0.x; As[lc + 1][lr] = a0.y;
        As[lc + 2][lr] = a0.z; As[lc + 3][lr] = a0.w;
        As[lc + 0][lr + 64] = a1.x; As[lc + 1][lr + 64] = a1.y;
        As[lc + 2][lr + 64] = a1.z; As[lc + 3][lr + 64] = a1.w;
        Bs[lc + 0][lr] = b0.x; Bs[lc + 1][lr] = b0.y;
        Bs[lc + 2][lr] = b0.z; Bs[lc + 3][lr] = b0.w;
        __syncthreads();
#pragma unroll
        for (int k = 0; k < 16; k++) {
            float4 av0 = *(const float4*)&As[k][ty * 8];
            float4 av1 = *(const float4*)&As[k][ty * 8 + 4];
            float4 bv  = *(const float4*)&Bs[k][tx * 4];
            float am[8] = {av0.x, av0.y, av0.z, av0.w, av1.x, av1.y, av1.z, av1.w};
            float bb[4] = {bv.x, bv.y, bv.z, bv.w};
#pragma unroll
            for (int i = 0; i < 8; i++)
#pragma unroll
                for (int j = 0; j < 4; j++) acc[i][j] += am[i] * bb[j];
        }
    }
    float bs0 = bias[n0 + tx * 4 + 0];
    float bs1 = bias[n0 + tx * 4 + 1];
    float bs2 = bias[n0 + tx * 4 + 2];
    float bs3 = bias[n0 + tx * 4 + 3];
#pragma unroll
    for (int i = 0; i < 8; i++) {
        int m = m0 + ty * 8 + i;
        float4 ov;
        ov.x = acc[i][0] + bs0; ov.y = acc[i][1] + bs1;
        ov.z = acc[i][2] + bs2; ov.w = acc[i][3] + bs3;
        *(float4*)&C[(size_t)m * N + n0 + tx * 4] = ov;
    }
}

// ---------------------------------------------------------------------------
// Per-direction grid barrier (64 co-resident blocks per dir)
// ---------------------------------------------------------------------------
__device__ __forceinline__ void grid_bar_dir(int dir) {
    __threadfence();
    __syncthreads();
    if (threadIdx.x == 0) {
        volatile unsigned* vgen = &g_bar_gen[dir];
        unsigned gen = *vgen;
        unsigned rank = atomicAdd(&g_bar_cnt[dir], 1);
        if (rank == DBAR - 1) {
            atomicExch(&g_bar_cnt[dir], 0);
            __threadfence();
            atomicExch(&g_bar_gen[dir], gen + 1);
        } else {
            while (*vgen == gen) { __nanosleep(64); }
        }
        __threadfence();
    }
    __syncthreads();
}

// ---------------------------------------------------------------------------
// Persistent HMMA BiLSTM layer (unchanged from R9). 128 CTAs x 512 threads.
// ---------------------------------------------------------------------------
__global__ void __launch_bounds__(512, 1)
lstm_mma(const uint4* __restrict__ Ahi, const float* __restrict__ pre,
         float* __restrict__ Xout) {
    __shared__ float psum[2 * 64 * 33];   // [ksplit][64 rows][33]

    const int tid = threadIdx.x;
    const int wid = tid >> 5;
    const int lid = tid & 31;
    const int cta = blockIdx.x;
    const int dir = cta >> 6;
    const int my_kstep = cta & 63;
    const int j0 = my_kstep * 16;

    const int ksplit = wid >> 3;
    const int mtile  = (wid >> 1) & 3;
    const int ntbase = (wid & 1) * 2;
    const int kbase  = ksplit * 32;

    const uint4* Aph = Ahi + (size_t)cta * 8192 + (size_t)kbase * 128 + mtile * 32 + lid;
    const float* preD = pre + (size_t)dir * 4096 * 4096;

    const int cb = tid >> 4;
    const int cj = tid & 15;
    float creg = 0.f;

    for (int t = 0; t < SS; t++) {
        const int sdir = dir ? (SS - 1 - t) : t;

        const float* pp = preD + (size_t)sdir * BB * G4 + (size_t)cb * G4 + j0 + cj;
        float pg0 = __ldcg(pp);
        float pg1 = __ldcg(pp + 1024);
        float pg2 = __ldcg(pp + 2048);
        float pg3 = __ldcg(pp + 3072);

        if (t > 0) {
            const uint2* Bf = (const uint2*)g_hfrag[(t - 1) & 1][dir];

            float d0a[4] = {0.f,0.f,0.f,0.f}, d0b[4] = {0.f,0.f,0.f,0.f};
            float d1a[4] = {0.f,0.f,0.f,0.f}, d1b[4] = {0.f,0.f,0.f,0.f};
            uint4 rah[4];
            uint2 rb0[4], rb1[4];
#pragma unroll
            for (int i = 0; i < 4; i++) {
                rah[i] = __ldg(Aph + i * 128);
                rb0[i] = __ldcg(Bf + ((kbase + i) * 4 + ntbase) * 32 + lid);
                rb1[i] = __ldcg(Bf + ((kbase + i) * 4 + ntbase + 1) * 32 + lid);
            }
#pragma unroll 4
            for (int ks = 0; ks < 32; ks++) {
                int s = ks & 3;
                uint4 ah = rah[s];
                uint2 b0 = rb0[s], b1 = rb1[s];
                if (ks < 28) {
                    rah[s] = __ldg(Aph + (ks + 4) * 128);
                    rb0[s] = __ldcg(Bf + ((kbase + ks + 4) * 4 + ntbase) * 32 + lid);
                    rb1[s] = __ldcg(Bf + ((kbase + ks + 4) * 4 + ntbase + 1) * 32 + lid);
                }
                if (ks & 1) {
                    MMA_F16(d0b, ah, b0);
                    MMA_F16(d1b, ah, b1);
                } else {
                    MMA_F16(d0a, ah, b0);
                    MMA_F16(d1a, ah, b1);
                }
            }
            float d0[4], d1[4];
#pragma unroll
            for (int i = 0; i < 4; i++) {
                d0[i] = d0a[i] + d0b[i];
                d1[i] = d1a[i] + d1b[i];
            }
            float* ps = psum + ksplit * (64 * 33);
            int row0 = mtile * 16 + (lid >> 2);
            int n0 = ntbase * 8 + (lid & 3) * 2;
            ps[row0 * 33 + n0]           = d0[0];
            ps[row0 * 33 + n0 + 1]       = d0[1];
            ps[(row0 + 8) * 33 + n0]     = d0[2];
            ps[(row0 + 8) * 33 + n0 + 1] = d0[3];
            ps[row0 * 33 + n0 + 8]           = d1[0];
            ps[row0 * 33 + n0 + 9]           = d1[1];
            ps[(row0 + 8) * 33 + n0 + 8]     = d1[2];
            ps[(row0 + 8) * 33 + n0 + 9]     = d1[3];
        }
        __syncthreads();

        float gi = pg0, gf = pg1, gg = pg2, go = pg3;
        if (t > 0) {
            gi += psum[(0 * 16 + cj) * 33 + cb] + psum[64 * 33 + (0 * 16 + cj) * 33 + cb];
            gf += psum[(1 * 16 + cj) * 33 + cb] + psum[64 * 33 + (1 * 16 + cj) * 33 + cb];
            gg += psum[(2 * 16 + cj) * 33 + cb] + psum[64 * 33 + (2 * 16 + cj) * 33 + cb];
            go += psum[(3 * 16 + cj) * 33 + cb] + psum[64 * 33 + (3 * 16 + cj) * 33 + cb];
        }
        float i_ = 1.f / (1.f + expf(-gi));
        float f_ = 1.f / (1.f + expf(-gf));
        creg = f_ * creg + i_ * tanhf(gg);
        float hv = (1.f / (1.f + expf(-go))) * tanhf(creg);
        __half* hf = (__half*)g_hfrag[t & 1][dir];
        int u32i = ((my_kstep * 4 + (cb >> 3)) * 32 + (cb & 7) * 4 + ((cj & 7) >> 1)) * 2
                   + (cj >> 3);
        hf[u32i * 2 + (cj & 1)] = __float2half_rn(hv);
        Xout[(size_t)(sdir * BB + cb) * 2048 + dir * HH + j0 + cj] = hv;

        grid_bar_dir(dir);
    }
}

// ---------------------------------------------------------------------------
// BN + ReLU + lin2 -> emissions
// ---------------------------------------------------------------------------
__global__ void bn_lin2(const float* __restrict__ X, const float* __restrict__ gamma,
                        const float* __restrict__ beta, const float* __restrict__ w2,
                        const float* __restrict__ b2, float* __restrict__ emis) {
    int m = blockIdx.x;
    int s = m / BB, b = m % BB;
    int tid = threadIdx.x;
    const float inv = rsqrtf(1.f + 1e-5f);
    float acc[NT];
#pragma unroll
    for (int j = 0; j < NT; j++) acc[j] = 0.f;
    for (int k = tid; k < 2048; k += 128) {
        float hv = X[(size_t)m * 2048 + k];
        hv = fmaxf(gamma[k] * inv * hv + beta[k], 0.f);
#pragma unroll
        for (int j = 0; j < NT; j++) acc[j] += hv * w2[j * 2048 + k];
    }
    __shared__ float red[NT][128];
#pragma unroll
    for (int j = 0; j < NT; j++) red[j][tid] = acc[j];
    __syncthreads();
    for (int off = 64; off > 0; off >>= 1) {
        if (tid < off) {
#pragma unroll
            for (int j = 0; j < NT; j++) red[j][tid] += red[j][tid + off];
        }
        __syncthreads();
    }
    if (tid < NT) emis[(size_t)(b * SS + s) * NT + tid] = red[tid][0] + b2[tid];
}

// ---------------------------------------------------------------------------
// CRF log-likelihood -> scalar
// ---------------------------------------------------------------------------
__global__ void crf_kernel(const float* __restrict__ emis, const int* __restrict__ y,
                           const unsigned char* __restrict__ maskb,
                           const float* __restrict__ start, const float* __restrict__ end_,
                           const float* __restrict__ trans, float* __restrict__ out) {
    __shared__ float alpha[BB][12];
    __shared__ float tmp[BB][12];
    __shared__ float tr[NT * NT];
    __shared__ float numv[BB];
    __shared__ float denv[BB];
    __shared__ int mask_mode;

    int tid = threadIdx.x;
    if (tid == 0) {
        int mm = 1;
        for (int i = 0; i < 16; i++) {
            if (maskb[4 * i + 1] | maskb[4 * i + 2] | maskb[4 * i + 3]) { mm = 0; break; }
        }
        mask_mode = mm;
    }
    if (tid < NT * NT) tr[tid] = trans[tid];
    __syncthreads();

    int b = tid / NT;
    int j = tid % NT;
    const int mm = mask_mode;
    const int* mi = (const int*)maskb;

    alpha[b][j] = start[j] + emis[(size_t)(b * SS) * NT + j];
    __syncthreads();

    for (int t = 1; t < SS; t++) {
        float mx = -1e30f;
#pragma unroll
        for (int i = 0; i < NT; i++) {
            float v = alpha[b][i] + tr[i * NT + j];
            mx = fmaxf(mx, v);
        }
        float ssum = 0.f;
#pragma unroll
        for (int i = 0; i < NT; i++)
            ssum += expf(alpha[b][i] + tr[i * NT + j] - mx);
        float nxt = mx + logf(ssum) + emis[(size_t)(b * SS + t) * NT + j];
        bool mk = mm ? (mi[b * SS + t] != 0) : (maskb[b * SS + t] != 0);
        __syncthreads();
        if (mk) alpha[b][j] = nxt;
        __syncthreads();
    }

    tmp[b][j] = alpha[b][j] + end_[j];
    __syncthreads();
    if (j == 0) {
        float mx = tmp[b][0];
#pragma unroll
        for (int i = 1; i < NT; i++) mx = fmaxf(mx, tmp[b][i]);
        float ssum = 0.f;
#pragma unroll
        for (int i = 0; i < NT; i++) ssum += expf(tmp[b][i] - mx);
        denv[b] = mx + logf(ssum);

        const int* yb = y + b * SS;
        float num = start[yb[0]] + emis[(size_t)(b * SS) * NT + yb[0]];
        int len = (mm ? (mi[b * SS] != 0) : (maskb[b * SS] != 0)) ? 1 : 0;
        for (int t = 1; t < SS; t++) {
            bool mk = mm ? (mi[b * SS + t] != 0) : (maskb[b * SS + t] != 0);
            if (mk) {
                num += tr[yb[t - 1] * NT + yb[t]] + emis[(size_t)(b * SS + t) * NT + yb[t]];
                len++;
            }
        }
        int last = yb[(len > 0 ? len : 1) - 1];
        num += end_[last];
        numv[b] = num;
    }
    __syncthreads();
    if (tid == 0) {
        float acc = 0.f;
        for (int bb2 = 0; bb2 < BB; bb2++) acc += numv[bb2] - denv[bb2];
        out[0] = acc;
    }
}

// ---------------------------------------------------------------------------
// Host launcher
// ---------------------------------------------------------------------------
extern "C" void kernel_launch(void* const* d_in, const int* in_sizes, int n_in,
                              void* d_out, int out_size) {
    const int*   x       = (const int*)d_in[0];
    const int*   y       = (const int*)d_in[1];
    const unsigned char* mask = (const unsigned char*)d_in[2];
    const float* emb     = (const float*)d_in[3];
    const float* lin1_w  = (const float*)d_in[4];
    const float* lin1_b  = (const float*)d_in[5];
    const float* wih[4]  = {(const float*)d_in[6],  (const float*)d_in[9],
                            (const float*)d_in[12], (const float*)d_in[15]};
    const float* whh[4]  = {(const float*)d_in[7],  (const float*)d_in[10],
                            (const float*)d_in[13], (const float*)d_in[16]};
    const float* bias[4] = {(const float*)d_in[8],  (const float*)d_in[11],
                            (const float*)d_in[14], (const float*)d_in[17]};
    const float* bn_gamma = (const float*)d_in[18];
    const float* bn_beta  = (const float*)d_in[19];
    const float* lin2_w   = (const float*)d_in[20];
    const float* lin2_b   = (const float*)d_in[21];
    const float* crf_start = (const float*)d_in[22];
    const float* crf_end   = (const float*)d_in[23];
    const float* crf_trans = (const float*)d_in[24];

    float *E, *W1p, *X0, *X1, *pre, *emis;
    uint4 *Ahi, *Xf;
    uint2 *Wf;
    cudaGetSymbolAddress((void**)&E, g_E);
    cudaGetSymbolAddress((void**)&W1p, g_W1p);
    cudaGetSymbolAddress((void**)&X0, g_X0);
    cudaGetSymbolAddress((void**)&X1, g_X1);
    cudaGetSymbolAddress((void**)&pre, g_pre);
    cudaGetSymbolAddress((void**)&emis, g_emis);
    cudaGetSymbolAddress((void**)&Ahi, g_Ahi);
    cudaGetSymbolAddress((void**)&Xf, g_Xf);
    cudaGetSymbolAddress((void**)&Wf, g_Wf);

    gather_kernel<<<(4096 * DPAD + 255) / 256, 256>>>(E, x, emb);
    padw_kernel<<<(512 * DPAD + 255) / 256, 256>>>(W1p, lin1_w);
    gemm_bias<<<dim3(512 / 64, 4096 / 128), 256>>>(E, W1p, lin1_b, X0, 512, DPAD);

    float* Xin = X0;
    float* Xout = X1;
    const int Kin[4] = {512, 2048, 2048, 2048};

    for (int l = 0; l < 4; l++) {
        const int K = Kin[l];
        const int KS = K / 16;
        convw_kernel<<<(128 * 64 * 1024) / 256, 256>>>(whh[l], (__half*)Ahi);
        convx_kernel<<<(4096 * K + 255) / 256, 256>>>(Xin, (__half*)Xf, K, KS);
        convwih_kernel<<<(8192 * K + 255) / 256, 256>>>(wih[l], (__half*)Wf, K, KS);
        hgemm_pre<<<dim3(64, 32), 256>>>(Xf, Wf, bias[l], pre, KS);
        lstm_mma<<<LBLK, 512>>>(Ahi, pre, Xout);
        float* tmpp = Xin; Xin = Xout; Xout = tmpp;
    }

    bn_lin2<<<4096, 128>>>(Xin, bn_gamma, bn_beta, lin2_w, lin2_b, emis);
    crf_kernel<<<1, BB * NT>>>(emis, y, mask, crf_start, crf_end, crf_trans,
                               (float*)d_out);
}

// round 11
// speedup vs baseline: 4.8105x; 1.1814x over previous
#include <cuda_runtime.h>
#include <cuda_fp16.h>
#include <cuda_bf16.h>
#include <math.h>
#include <stdint.h>

// ---------------------------------------------------------------------------
// Problem constants
// ---------------------------------------------------------------------------
#define BB 32      // batch
#define SS 128     // seq len
#define DD 300     // emb dim
#define DPAD 304   // padded emb dim
#define HH 1024    // hidden
#define G4 4096    // 4*H
#define NT 9       // tags
#define LBLK 128   // persistent LSTM CTAs (single wave, <148 SMs)
#define DBAR 64    // per-direction barrier arrivals

// ---------------------------------------------------------------------------
// Scratch (static device allocations - allowed)
// ---------------------------------------------------------------------------
__device__ float g_E[4096 * DPAD];
__device__ float g_W1p[512 * DPAD];
__device__ float g_X0[4096 * 2048];
__device__ float g_X1[4096 * 2048];
__device__ float g_pre[2ull * 4096 * 4096];
__device__ float g_emis[BB * SS * NT];
// Whh fp16, A-fragment order: [cta 128][kstep 64][mtile 4][lane 32][4 u32]
__device__ uint4 g_Ahi[128 * 8192];
// h as fp16 B-fragments, parity double-buffered: [parity][dir][16384 u32]
__device__ uint32_t g_hfrag[2][2][16384];
// input-projection fragments (ping-pong: lstm(l) writes [1^(l&1)] while hgemm(l) reads [l&1])
__device__ uint4 g_Xf[2][64 * 128 * 4 * 32];    // A frags: [rowblk64][kstep<=128][mt4][lane32]
__device__ uint2 g_Wf[256 * 128 * 4 * 32];      // B frags: [nblk32 x256][kstep<=128][nt4][lane32]

__device__ unsigned g_bar_cnt[2];
__device__ unsigned g_bar_gen[2];

// mma.sync m16n8k16 fp16 -> f32 (baseline PTX, compiles for plain sm_103)
#define MMA_F16(d, a, b) \
    asm volatile("mma.sync.aligned.m16n8k16.row.col.f32.f16.f16.f32 " \
        "{%0,%1,%2,%3}, {%4,%5,%6,%7}, {%8,%9}, {%0,%1,%2,%3};" \
        : "+f"((d)[0]), "+f"((d)[1]), "+f"((d)[2]), "+f"((d)[3]) \
        : "r"((a).x), "r"((a).y), "r"((a).z), "r"((a).w), \
          "r"((b).x), "r"((b).y))

// ---------------------------------------------------------------------------
// Small prep kernels
// ---------------------------------------------------------------------------
__global__ void gather_kernel(float* __restrict__ E, const int* __restrict__ x,
                              const float* __restrict__ emb) {
    int i = blockIdx.x * blockDim.x + threadIdx.x;
    if (i >= 4096 * DPAD) return;
    int m = i / DPAD, col = i % DPAD;
    int s = m / BB, b = m % BB;
    int tok = x[b * SS + s];
    E[i] = (col < DD) ? emb[(size_t)tok * DD + col] : 0.f;
}

__global__ void padw_kernel(float* __restrict__ Wp, const float* __restrict__ W) {
    int i = blockIdx.x * blockDim.x + threadIdx.x;
    if (i >= 512 * DPAD) return;
    int r = i / DPAD, col = i % DPAD;
    Wp[i] = (col < DD) ? W[r * DD + col] : 0.f;
}

// Whh fp32 -> fp16, reordered into per-lane mma A-fragments (recurrent weights).
__global__ void convw_kernel(const float* __restrict__ whh,
                             __half* __restrict__ Ahi) {
    int i = blockIdx.x * blockDim.x + threadIdx.x;   // 128*64*1024
    if (i >= 128 * 64 * 1024) return;
    int c = i >> 16;
    int r = (i >> 10) & 63;
    int k = i & 1023;
    int dir = c >> 6, j0 = (c & 63) * 16;
    int gate = r >> 4, jj = r & 15;
    int grow = gate * 1024 + j0 + jj;
    float w = whh[(size_t)dir * G4 * HH + (size_t)grow * HH + k];
    int mtile = gate, m = jj;
    int kstep = k >> 4, kin = k & 15;
    int lane = (m & 7) * 4 + ((kin >> 1) & 3);
    int reg = ((m >> 3) & 1) + ((kin >> 3) << 1);
    size_t idx = (size_t)c * 32768 + kstep * 512 + mtile * 128 + lane * 4 + reg;
    Ahi[idx * 2 + (kin & 1)] = __float2half_rn(w);
}

// X fp32 (4096 x K) -> fp16 A-fragments (only needed for layer 0 input)
__global__ void convx_kernel(const float* __restrict__ X, __half* __restrict__ Xf,
                             int K, int KS) {
    int i = blockIdx.x * blockDim.x + threadIdx.x;
    if (i >= 4096 * K) return;
    int m = i / K, k = i % K;
    int rowblk = m >> 6, r = m & 63;
    int mt = r >> 4, mrow = r & 15;
    int kstep = k >> 4, kin = k & 15;
    int lane = (mrow & 7) * 4 + ((kin >> 1) & 3);
    int reg = ((mrow >> 3) & 1) + ((kin >> 3) << 1);
    size_t e = (((((size_t)rowblk * KS + kstep) * 4 + mt) * 32 + lane) * 4 + reg) * 2
               + (kin & 1);
    Xf[e] = __float2half_rn(X[i]);
}

// Wih fp32 (8192 x K, dir-major) -> fp16 B-fragments
__global__ void convwih_kernel(const float* __restrict__ W, __half* __restrict__ Wf,
                               int K, int KS) {
    int i = blockIdx.x * blockDim.x + threadIdx.x;
    if (i >= 8192 * K) return;
    int n = i / K, k = i % K;
    int nblk = n >> 5, nr = n & 31;
    int nt = nr >> 3, ncol = nr & 7;
    int kstep = k >> 4, kin = k & 15;
    int lane = ncol * 4 + ((kin & 7) >> 1);
    int reg = kin >> 3;
    size_t e = (((((size_t)nblk * KS + kstep) * 4 + nt) * 32 + lane) * 2 + reg) * 2
               + (kin & 1);
    Wf[e] = __float2half_rn(W[i]);
}

// ---------------------------------------------------------------------------
// HMMA input-projection GEMM: pre[dir][m][col] = X[m] . Wih[n] + bias[n]
// M=4096, N=8192 (dir-major), K=KS*16. Grid (32, 32), 512 threads, 16 warps.
// CTA tile 128(M) x 256(N); warp tile 64x32 (4 mt x 4 nt m16n8k16 per kstep).
// 4 warps/SMSP for HMMA latency hiding.
// ---------------------------------------------------------------------------
__global__ void __launch_bounds__(512, 1)
hgemm_pre(const uint4* __restrict__ Xf, const uint2* __restrict__ Wf,
          const float* __restrict__ bias, float* __restrict__ pre, int KS) {
    const int tid = threadIdx.x;
    const int wid = tid >> 5, lane = tid & 31;
    const int rowblk = blockIdx.y * 2 + (wid >> 3);
    const int nblk = blockIdx.x * 8 + (wid & 7);

    const uint4* Ab = Xf + (size_t)rowblk * KS * 128 + lane;
    const uint2* Bb = Wf + (size_t)nblk * KS * 128 + lane;

    float d[4][4][4];
#pragma unroll
    for (int mt = 0; mt < 4; mt++)
#pragma unroll
        for (int nt = 0; nt < 4; nt++)
#pragma unroll
            for (int q = 0; q < 4; q++) d[mt][nt][q] = 0.f;

    uint4 a[4];
    uint2 b[4];
#pragma unroll
    for (int i = 0; i < 4; i++) {
        a[i] = __ldg(Ab + i * 32);
        b[i] = __ldg(Bb + i * 32);
    }

    for (int ks = 0; ks < KS; ks++) {
        uint4 ca[4];
        uint2 cb[4];
#pragma unroll
        for (int i = 0; i < 4; i++) { ca[i] = a[i]; cb[i] = b[i]; }
        if (ks + 1 < KS) {
            const uint4* An = Ab + (size_t)(ks + 1) * 128;
            const uint2* Bn = Bb + (size_t)(ks + 1) * 128;
#pragma unroll
            for (int i = 0; i < 4; i++) {
                a[i] = __ldg(An + i * 32);
                b[i] = __ldg(Bn + i * 32);
            }
        }
#pragma unroll
        for (int mt = 0; mt < 4; mt++)
#pragma unroll
            for (int nt = 0; nt < 4; nt++)
                MMA_F16(d[mt][nt], ca[mt], cb[nt]);
    }

    // epilogue: bias + store fp32 into pre[dir][m][col]
#pragma unroll
    for (int mt = 0; mt < 4; mt++) {
        int m = rowblk * 64 + mt * 16 + (lane >> 2);
#pragma unroll
        for (int nt = 0; nt < 4; nt++) {
            int nn = nblk * 32 + nt * 8 + (lane & 3) * 2;
            int dir = nn >> 12;
            int col = nn & 4095;
            float bs0 = __ldg(bias + nn);
            float bs1 = __ldg(bias + nn + 1);
            float* outp = pre + (size_t)dir * 4096 * 4096 + (size_t)m * 4096 + col;
            float2 v0 = make_float2(d[mt][nt][0] + bs0, d[mt][nt][1] + bs1);
            *(float2*)outp = v0;
            float2 v1 = make_float2(d[mt][nt][2] + bs0, d[mt][nt][3] + bs1);
            *(float2*)(outp + (size_t)8 * 4096) = v1;
        }
    }
}

// ---------------------------------------------------------------------------
// SIMT fp32 GEMM (used only for lin1)
// ---------------------------------------------------------------------------
__global__ void gemm_bias(const float* __restrict__ A, const float* __restrict__ Bm,
                          const float* __restrict__ bias, float* __restrict__ C,
                          int N, int K) {
    __shared__ float As[16][132];
    __shared__ float Bs[16][68];
    int tid = threadIdx.x;
    int m0 = blockIdx.y * 128;
    int n0 = blockIdx.x * 64;
    int tx = tid & 15, ty = tid >> 4;
    int lr = tid >> 2, lc = (tid & 3) * 4;

    const float* Ap  = A  + (size_t)(m0 + lr) * K + lc;
    const float* Ap2 = Ap + (size_t)64 * K;
    const float* Bp  = Bm + (size_t)(n0 + lr) * K + lc;

    float acc[8][4];
#pragma unroll
    for (int i = 0; i < 8; i++)
#pragma unroll
        for (int j = 0; j < 4; j++) acc[i][j] = 0.f;

    for (int k0 = 0; k0 < K; k0 += 16) {
        float4 a0 = *(const float4*)(Ap + k0);
        float4 a1 = *(const float4*)(Ap2 + k0);
        float4 b0 = *(const float4*)(Bp + k0);
        __syncthreads();
        As[lc + 0][lr] = a0.x; As[lc + 1][lr] = a0.y;
        As[lc + 2][lr] = a0.z; As[lc + 3][lr] = a0.w;
        As[lc + 0][lr + 64] = a1.x; As[lc + 1][lr + 64] = a1.y;
        As[lc + 2][lr + 64] = a1.z; As[lc + 3][lr + 64] = a1.w;
        Bs[lc + 0][lr] = b0.x; Bs[lc + 1][lr] = b0.y;
        Bs[lc + 2][lr] = b0.z; Bs[lc + 3][lr] = b0.w;
        __syncthreads();
#pragma unroll
        for (int k = 0; k < 16; k++) {
            float4 av0 = *(const float4*)&As[k][ty * 8];
            float4 av1 = *(const float4*)&As[k][ty * 8 + 4];
            float4 bv  = *(const float4*)&Bs[k][tx * 4];
            float am[8] = {av0.x, av0.y, av0.z, av0.w, av1.x, av1.y, av1.z, av1.w};
            float bb[4] = {bv.x, bv.y, bv.z, bv.w};
#pragma unroll
            for (int i = 0; i < 8; i++)
#pragma unroll
                for (int j = 0; j < 4; j++) acc[i][j] += am[i] * bb[j];
        }
    }
    float bs0 = bias[n0 + tx * 4 + 0];
    float bs1 = bias[n0 + tx * 4 + 1];
    float bs2 = bias[n0 + tx * 4 + 2];
    float bs3 = bias[n0 + tx * 4 + 3];
#pragma unroll
    for (int i = 0; i < 8; i++) {
        int m = m0 + ty * 8 + i;
        float4 ov;
        ov.x = acc[i][0] + bs0; ov.y = acc[i][1] + bs1;
        ov.z = acc[i][2] + bs2; ov.w = acc[i][3] + bs3;
        *(float4*)&C[(size_t)m * N + n0 + tx * 4] = ov;
    }
}

// ---------------------------------------------------------------------------
// Per-direction grid barrier (64 co-resident blocks per dir)
// ---------------------------------------------------------------------------
__device__ __forceinline__ void grid_bar_dir(int dir) {
    __threadfence();
    __syncthreads();
    if (threadIdx.x == 0) {
        volatile unsigned* vgen = &g_bar_gen[dir];
        unsigned gen = *vgen;
        unsigned rank = atomicAdd(&g_bar_cnt[dir], 1);
        if (rank == DBAR - 1) {
            atomicExch(&g_bar_cnt[dir], 0);
            __threadfence();
            atomicExch(&g_bar_gen[dir], gen + 1);
        } else {
            while (*vgen == gen) { __nanosleep(64); }
        }
        __threadfence();
    }
    __syncthreads();
}

// ---------------------------------------------------------------------------
// Persistent HMMA BiLSTM layer. 128 CTAs x 512 threads.
// Epilogue additionally writes h directly as fp16 A-fragments for the NEXT
// layer's hgemm (Xfout, ping-pong buffer) — replaces convx.
// ---------------------------------------------------------------------------
__global__ void __launch_bounds__(512, 1)
lstm_mma(const uint4* __restrict__ Ahi, const float* __restrict__ pre,
         float* __restrict__ Xout, __half* __restrict__ Xfout) {
    __shared__ float psum[2 * 64 * 33];   // [ksplit][64 rows][33]

    const int tid = threadIdx.x;
    const int wid = tid >> 5;
    const int lid = tid & 31;
    const int cta = blockIdx.x;
    const int dir = cta >> 6;
    const int my_kstep = cta & 63;
    const int j0 = my_kstep * 16;

    const int ksplit = wid >> 3;
    const int mtile  = (wid >> 1) & 3;
    const int ntbase = (wid & 1) * 2;
    const int kbase  = ksplit * 32;

    const uint4* Aph = Ahi + (size_t)cta * 8192 + (size_t)kbase * 128 + mtile * 32 + lid;
    const float* preD = pre + (size_t)dir * 4096 * 4096;

    const int cb = tid >> 4;
    const int cj = tid & 15;
    float creg = 0.f;

    // precomputed pieces of the Xf fragment index (k fixed per thread)
    const int kx = dir * HH + j0 + cj;
    const int xkstep = kx >> 4, xkin = kx & 15;

    for (int t = 0; t < SS; t++) {
        const int sdir = dir ? (SS - 1 - t) : t;

        const float* pp = preD + (size_t)sdir * BB * G4 + (size_t)cb * G4 + j0 + cj;
        float pg0 = __ldcg(pp);
        float pg1 = __ldcg(pp + 1024);
        float pg2 = __ldcg(pp + 2048);
        float pg3 = __ldcg(pp + 3072);

        if (t > 0) {
            const uint2* Bf = (const uint2*)g_hfrag[(t - 1) & 1][dir];

            float d0a[4] = {0.f,0.f,0.f,0.f}, d0b[4] = {0.f,0.f,0.f,0.f};
            float d1a[4] = {0.f,0.f,0.f,0.f}, d1b[4] = {0.f,0.f,0.f,0.f};
            uint4 rah[4];
            uint2 rb0[4], rb1[4];
#pragma unroll
            for (int i = 0; i < 4; i++) {
                rah[i] = __ldg(Aph + i * 128);
                rb0[i] = __ldcg(Bf + ((kbase + i) * 4 + ntbase) * 32 + lid);
                rb1[i] = __ldcg(Bf + ((kbase + i) * 4 + ntbase + 1) * 32 + lid);
            }
#pragma unroll 4
            for (int ks = 0; ks < 32; ks++) {
                int s = ks & 3;
                uint4 ah = rah[s];
                uint2 b0 = rb0[s], b1 = rb1[s];
                if (ks < 28) {
                    rah[s] = __ldg(Aph + (ks + 4) * 128);
                    rb0[s] = __ldcg(Bf + ((kbase + ks + 4) * 4 + ntbase) * 32 + lid);
                    rb1[s] = __ldcg(Bf + ((kbase + ks + 4) * 4 + ntbase + 1) * 32 + lid);
                }
                if (ks & 1) {
                    MMA_F16(d0b, ah, b0);
                    MMA_F16(d1b, ah, b1);
                } else {
                    MMA_F16(d0a, ah, b0);
                    MMA_F16(d1a, ah, b1);
                }
            }
            float d0[4], d1[4];
#pragma unroll
            for (int i = 0; i < 4; i++) {
                d0[i] = d0a[i] + d0b[i];
                d1[i] = d1a[i] + d1b[i];
            }
            float* ps = psum + ksplit * (64 * 33);
            int row0 = mtile * 16 + (lid >> 2);
            int n0 = ntbase * 8 + (lid & 3) * 2;
            ps[row0 * 33 + n0]           = d0[0];
            ps[row0 * 33 + n0 + 1]       = d0[1];
            ps[(row0 + 8) * 33 + n0]     = d0[2];
            ps[(row0 + 8) * 33 + n0 + 1] = d0[3];
            ps[row0 * 33 + n0 + 8]           = d1[0];
            ps[row0 * 33 + n0 + 9]           = d1[1];
            ps[(row0 + 8) * 33 + n0 + 8]     = d1[2];
            ps[(row0 + 8) * 33 + n0 + 9]     = d1[3];
        }
        __syncthreads();

        float gi = pg0, gf = pg1, gg = pg2, go = pg3;
        if (t > 0) {
            gi += psum[(0 * 16 + cj) * 33 + cb] + psum[64 * 33 + (0 * 16 + cj) * 33 + cb];
            gf += psum[(1 * 16 + cj) * 33 + cb] + psum[64 * 33 + (1 * 16 + cj) * 33 + cb];
            gg += psum[(2 * 16 + cj) * 33 + cb] + psum[64 * 33 + (2 * 16 + cj) * 33 + cb];
            go += psum[(3 * 16 + cj) * 33 + cb] + psum[64 * 33 + (3 * 16 + cj) * 33 + cb];
        }
        float i_ = 1.f / (1.f + expf(-gi));
        float f_ = 1.f / (1.f + expf(-gf));
        creg = f_ * creg + i_ * tanhf(gg);
        float hv = (1.f / (1.f + expf(-go))) * tanhf(creg);
        __half hvh = __float2half_rn(hv);

        // recurrent h fragments (parity buffer)
        __half* hf = (__half*)g_hfrag[t & 1][dir];
        int u32i = ((my_kstep * 4 + (cb >> 3)) * 32 + (cb & 7) * 4 + ((cj & 7) >> 1)) * 2
                   + (cj >> 3);
        hf[u32i * 2 + (cj & 1)] = hvh;

        // fp32 layer output
        Xout[(size_t)(sdir * BB + cb) * 2048 + dir * HH + j0 + cj] = hv;

        // fused convx: write fp16 A-fragment for next layer's hgemm (K=2048, KS=128)
        if (Xfout) {
            int m = sdir * BB + cb;
            int rowblk = m >> 6, r = m & 63;
            int mt = r >> 4, mrow = r & 15;
            int lane2 = (mrow & 7) * 4 + ((xkin >> 1) & 3);
            int reg = ((mrow >> 3) & 1) + ((xkin >> 3) << 1);
            size_t e = (((((size_t)rowblk * 128 + xkstep) * 4 + mt) * 32 + lane2) * 4
                        + reg) * 2 + (xkin & 1);
            Xfout[e] = hvh;
        }

        grid_bar_dir(dir);
    }
}

// ---------------------------------------------------------------------------
// BN + ReLU + lin2 -> emissions
// ---------------------------------------------------------------------------
__global__ void bn_lin2(const float* __restrict__ X, const float* __restrict__ gamma,
                        const float* __restrict__ beta, const float* __restrict__ w2,
                        const float* __restrict__ b2, float* __restrict__ emis) {
    int m = blockIdx.x;
    int s = m / BB, b = m % BB;
    int tid = threadIdx.x;
    const float inv = rsqrtf(1.f + 1e-5f);
    float acc[NT];
#pragma unroll
    for (int j = 0; j < NT; j++) acc[j] = 0.f;
    for (int k = tid; k < 2048; k += 128) {
        float hv = X[(size_t)m * 2048 + k];
        hv = fmaxf(gamma[k] * inv * hv + beta[k], 0.f);
#pragma unroll
        for (int j = 0; j < NT; j++) acc[j] += hv * w2[j * 2048 + k];
    }
    __shared__ float red[NT][128];
#pragma unroll
    for (int j = 0; j < NT; j++) red[j][tid] = acc[j];
    __syncthreads();
    for (int off = 64; off > 0; off >>= 1) {
        if (tid < off) {
#pragma unroll
            for (int j = 0; j < NT; j++) red[j][tid] += red[j][tid + off];
        }
        __syncthreads();
    }
    if (tid < NT) emis[(size_t)(b * SS + s) * NT + tid] = red[tid][0] + b2[tid];
}

// ---------------------------------------------------------------------------
// CRF log-likelihood -> scalar
// ---------------------------------------------------------------------------
__global__ void crf_kernel(const float* __restrict__ emis, const int* __restrict__ y,
                           const unsigned char* __restrict__ maskb,
                           const float* __restrict__ start, const float* __restrict__ end_,
                           const float* __restrict__ trans, float* __restrict__ out) {
    __shared__ float alpha[BB][12];
    __shared__ float tmp[BB][12];
    __shared__ float tr[NT * NT];
    __shared__ float numv[BB];
    __shared__ float denv[BB];
    __shared__ int mask_mode;

    int tid = threadIdx.x;
    if (tid == 0) {
        int mm = 1;
        for (int i = 0; i < 16; i++) {
            if (maskb[4 * i + 1] | maskb[4 * i + 2] | maskb[4 * i + 3]) { mm = 0; break; }
        }
        mask_mode = mm;
    }
    if (tid < NT * NT) tr[tid] = trans[tid];
    __syncthreads();

    int b = tid / NT;
    int j = tid % NT;
    const int mm = mask_mode;
    const int* mi = (const int*)maskb;

    alpha[b][j] = start[j] + emis[(size_t)(b * SS) * NT + j];
    __syncthreads();

    for (int t = 1; t < SS; t++) {
        float mx = -1e30f;
#pragma unroll
        for (int i = 0; i < NT; i++) {
            float v = alpha[b][i] + tr[i * NT + j];
            mx = fmaxf(mx, v);
        }
        float ssum = 0.f;
#pragma unroll
        for (int i = 0; i < NT; i++)
            ssum += expf(alpha[b][i] + tr[i * NT + j] - mx);
        float nxt = mx + logf(ssum) + emis[(size_t)(b * SS + t) * NT + j];
        bool mk = mm ? (mi[b * SS + t] != 0) : (maskb[b * SS + t] != 0);
        __syncthreads();
        if (mk) alpha[b][j] = nxt;
        __syncthreads();
    }

    tmp[b][j] = alpha[b][j] + end_[j];
    __syncthreads();
    if (j == 0) {
        float mx = tmp[b][0];
#pragma unroll
        for (int i = 1; i < NT; i++) mx = fmaxf(mx, tmp[b][i]);
        float ssum = 0.f;
#pragma unroll
        for (int i = 0; i < NT; i++) ssum += expf(tmp[b][i] - mx);
        denv[b] = mx + logf(ssum);

        const int* yb = y + b * SS;
        float num = start[yb[0]] + emis[(size_t)(b * SS) * NT + yb[0]];
        int len = (mm ? (mi[b * SS] != 0) : (maskb[b * SS] != 0)) ? 1 : 0;
        for (int t = 1; t < SS; t++) {
            bool mk = mm ? (mi[b * SS + t] != 0) : (maskb[b * SS + t] != 0);
            if (mk) {
                num += tr[yb[t - 1] * NT + yb[t]] + emis[(size_t)(b * SS + t) * NT + yb[t]];
                len++;
            }
        }
        int last = yb[(len > 0 ? len : 1) - 1];
        num += end_[last];
        numv[b] = num;
    }
    __syncthreads();
    if (tid == 0) {
        float acc = 0.f;
        for (int bb2 = 0; bb2 < BB; bb2++) acc += numv[bb2] - denv[bb2];
        out[0] = acc;
    }
}

// ---------------------------------------------------------------------------
// Host launcher
// ---------------------------------------------------------------------------
extern "C" void kernel_launch(void* const* d_in, const int* in_sizes, int n_in,
                              void* d_out, int out_size) {
    const int*   x       = (const int*)d_in[0];
    const int*   y       = (const int*)d_in[1];
    const unsigned char* mask = (const unsigned char*)d_in[2];
    const float* emb     = (const float*)d_in[3];
    const float* lin1_w  = (const float*)d_in[4];
    const float* lin1_b  = (const float*)d_in[5];
    const float* wih[4]  = {(const float*)d_in[6],  (const float*)d_in[9],
                            (const float*)d_in[12], (const float*)d_in[15]};
    const float* whh[4]  = {(const float*)d_in[7],  (const float*)d_in[10],
                            (const float*)d_in[13], (const float*)d_in[16]};
    const float* bias[4] = {(const float*)d_in[8],  (const float*)d_in[11],
                            (const float*)d_in[14], (const float*)d_in[17]};
    const float* bn_gamma = (const float*)d_in[18];
    const float* bn_beta  = (const float*)d_in[19];
    const float* lin2_w   = (const float*)d_in[20];
    const float* lin2_b   = (const float*)d_in[21];
    const float* crf_start = (const float*)d_in[22];
    const float* crf_end   = (const float*)d_in[23];
    const float* crf_trans = (const float*)d_in[24];

    float *E, *W1p, *X0, *X1, *pre, *emis;
    uint4 *Ahi, *Xf;
    uint2 *Wf;
    cudaGetSymbolAddress((void**)&E, g_E);
    cudaGetSymbolAddress((void**)&W1p, g_W1p);
    cudaGetSymbolAddress((void**)&X0, g_X0);
    cudaGetSymbolAddress((void**)&X1, g_X1);
    cudaGetSymbolAddress((void**)&pre, g_pre);
    cudaGetSymbolAddress((void**)&emis, g_emis);
    cudaGetSymbolAddress((void**)&Ahi, g_Ahi);
    cudaGetSymbolAddress((void**)&Xf, g_Xf);
    cudaGetSymbolAddress((void**)&Wf, g_Wf);

    const size_t XF_STRIDE = (size_t)64 * 128 * 4 * 32;   // uint4 per buffer

    gather_kernel<<<(4096 * DPAD + 255) / 256, 256>>>(E, x, emb);
    padw_kernel<<<(512 * DPAD + 255) / 256, 256>>>(W1p, lin1_w);
    gemm_bias<<<dim3(512 / 64, 4096 / 128), 256>>>(E, W1p, lin1_b, X0, 512, DPAD);

    float* Xin = X0;
    float* Xout = X1;
    const int Kin[4] = {512, 2048, 2048, 2048};

    // layer-0 input fragments via convx; later layers fused into lstm epilogue
    convx_kernel<<<(4096 * 512 + 255) / 256, 256>>>(Xin, (__half*)Xf, 512, 32);

    for (int l = 0; l < 4; l++) {
        const int K = Kin[l];
        const int KS = K / 16;
        uint4* XfIn  = Xf + (size_t)(l & 1) * XF_STRIDE;
        __half* XfOut = (l < 3) ? (__half*)(Xf + (size_t)((l + 1) & 1) * XF_STRIDE)
                                : (__half*)0;
        convw_kernel<<<(128 * 64 * 1024) / 256, 256>>>(whh[l], (__half*)Ahi);
        convwih_kernel<<<(8192 * K + 255) / 256, 256>>>(wih[l], (__half*)Wf, K, KS);
        hgemm_pre<<<dim3(32, 32), 512>>>(XfIn, Wf, bias[l], pre, KS);
        lstm_mma<<<LBLK, 512>>>(Ahi, pre, Xout, XfOut);
        float* tmpp = Xin; Xin = Xout; Xout = tmpp;
    }

    bn_lin2<<<4096, 128>>>(Xin, bn_gamma, bn_beta, lin2_w, lin2_b, emis);
    crf_kernel<<<1, BB * NT>>>(emis, y, mask, crf_start, crf_end, crf_trans,
                               (float*)d_out);
}

// round 12
// speedup vs baseline: 4.9554x; 1.0301x over previous
#include <cuda_runtime.h>
#include <cuda_fp16.h>
#include <cuda_bf16.h>
#include <math.h>
#include <stdint.h>

// ---------------------------------------------------------------------------
// Problem constants
// ---------------------------------------------------------------------------
#define BB 32      // batch
#define SS 128     // seq len
#define DD 300     // emb dim
#define DPAD 304   // padded emb dim
#define HH 1024    // hidden
#define G4 4096    // 4*H
#define NT 9       // tags
#define LBLK 128   // persistent LSTM CTAs (single wave, <148 SMs)
#define DBAR 64    // per-direction barrier arrivals

// lstm dynamic smem: Bsm u32[16384] (64KB) + psum float[2*64*33]
#define LSTM_SMEM (65536 + 2 * 64 * 33 * 4)

// ---------------------------------------------------------------------------
// Scratch (static device allocations - allowed)
// ---------------------------------------------------------------------------
__device__ float g_E[4096 * DPAD];
__device__ float g_W1p[512 * DPAD];
__device__ float g_X0[4096 * 2048];
__device__ float g_X1[4096 * 2048];
__device__ float g_pre[2ull * 4096 * 4096];
__device__ float g_emis[BB * SS * NT];
// Whh fp16, A-fragment order: [cta 128][kstep 64][mtile 4][lane 32][4 u32]
__device__ uint4 g_Ahi[128 * 8192];
// h as fp16 B-fragments, parity double-buffered: [parity][dir][16384 u32]
__device__ uint32_t g_hfrag[2][2][16384];
// input-projection fragments (ping-pong: lstm(l) writes [1^(l&1)] while hgemm(l) reads [l&1])
__device__ uint4 g_Xf[2][64 * 128 * 4 * 32];    // A frags: [rowblk64][kstep<=128][mt4][lane32]
__device__ uint2 g_Wf[256 * 128 * 4 * 32];      // B frags: [nblk32 x256][kstep<=128][nt4][lane32]

__device__ unsigned g_bar_cnt[2];
__device__ unsigned g_bar_gen[2];

// mma.sync m16n8k16 fp16 -> f32 (baseline PTX, compiles for plain sm_103)
#define MMA_F16(d, a, b) \
    asm volatile("mma.sync.aligned.m16n8k16.row.col.f32.f16.f16.f32 " \
        "{%0,%1,%2,%3}, {%4,%5,%6,%7}, {%8,%9}, {%0,%1,%2,%3};" \
        : "+f"((d)[0]), "+f"((d)[1]), "+f"((d)[2]), "+f"((d)[3]) \
        : "r"((a).x), "r"((a).y), "r"((a).z), "r"((a).w), \
          "r"((b).x), "r"((b).y))

// ---------------------------------------------------------------------------
// Small prep kernels
// ---------------------------------------------------------------------------
__global__ void gather_kernel(float* __restrict__ E, const int* __restrict__ x,
                              const float* __restrict__ emb) {
    int i = blockIdx.x * blockDim.x + threadIdx.x;
    if (i >= 4096 * DPAD) return;
    int m = i / DPAD, col = i % DPAD;
    int s = m / BB, b = m % BB;
    int tok = x[b * SS + s];
    E[i] = (col < DD) ? emb[(size_t)tok * DD + col] : 0.f;
}

__global__ void padw_kernel(float* __restrict__ Wp, const float* __restrict__ W) {
    int i = blockIdx.x * blockDim.x + threadIdx.x;
    if (i >= 512 * DPAD) return;
    int r = i / DPAD, col = i % DPAD;
    Wp[i] = (col < DD) ? W[r * DD + col] : 0.f;
}

// Whh fp32 -> fp16, reordered into per-lane mma A-fragments (recurrent weights).
__global__ void convw_kernel(const float* __restrict__ whh,
                             __half* __restrict__ Ahi) {
    int i = blockIdx.x * blockDim.x + threadIdx.x;   // 128*64*1024
    if (i >= 128 * 64 * 1024) return;
    int c = i >> 16;
    int r = (i >> 10) & 63;
    int k = i & 1023;
    int dir = c >> 6, j0 = (c & 63) * 16;
    int gate = r >> 4, jj = r & 15;
    int grow = gate * 1024 + j0 + jj;
    float w = whh[(size_t)dir * G4 * HH + (size_t)grow * HH + k];
    int mtile = gate, m = jj;
    int kstep = k >> 4, kin = k & 15;
    int lane = (m & 7) * 4 + ((kin >> 1) & 3);
    int reg = ((m >> 3) & 1) + ((kin >> 3) << 1);
    size_t idx = (size_t)c * 32768 + kstep * 512 + mtile * 128 + lane * 4 + reg;
    Ahi[idx * 2 + (kin & 1)] = __float2half_rn(w);
}

// X fp32 (4096 x K) -> fp16 A-fragments (only needed for layer 0 input)
__global__ void convx_kernel(const float* __restrict__ X, __half* __restrict__ Xf,
                             int K, int KS) {
    int i = blockIdx.x * blockDim.x + threadIdx.x;
    if (i >= 4096 * K) return;
    int m = i / K, k = i % K;
    int rowblk = m >> 6, r = m & 63;
    int mt = r >> 4, mrow = r & 15;
    int kstep = k >> 4, kin = k & 15;
    int lane = (mrow & 7) * 4 + ((kin >> 1) & 3);
    int reg = ((mrow >> 3) & 1) + ((kin >> 3) << 1);
    size_t e = (((((size_t)rowblk * KS + kstep) * 4 + mt) * 32 + lane) * 4 + reg) * 2
               + (kin & 1);
    Xf[e] = __float2half_rn(X[i]);
}

// Wih fp32 (8192 x K, dir-major) -> fp16 B-fragments
__global__ void convwih_kernel(const float* __restrict__ W, __half* __restrict__ Wf,
                               int K, int KS) {
    int i = blockIdx.x * blockDim.x + threadIdx.x;
    if (i >= 8192 * K) return;
    int n = i / K, k = i % K;
    int nblk = n >> 5, nr = n & 31;
    int nt = nr >> 3, ncol = nr & 7;
    int kstep = k >> 4, kin = k & 15;
    int lane = ncol * 4 + ((kin & 7) >> 1);
    int reg = kin >> 3;
    size_t e = (((((size_t)nblk * KS + kstep) * 4 + nt) * 32 + lane) * 2 + reg) * 2
               + (kin & 1);
    Wf[e] = __float2half_rn(W[i]);
}

// ---------------------------------------------------------------------------
// HMMA input-projection GEMM: pre[dir][m][col] = X[m] . Wih[n] + bias[n]
// Grid (32, 32), 512 threads; CTA tile 128x256; warp tile 64x32.
// ---------------------------------------------------------------------------
__global__ void __launch_bounds__(512, 1)
hgemm_pre(const uint4* __restrict__ Xf, const uint2* __restrict__ Wf,
          const float* __restrict__ bias, float* __restrict__ pre, int KS) {
    const int tid = threadIdx.x;
    const int wid = tid >> 5, lane = tid & 31;
    const int rowblk = blockIdx.y * 2 + (wid >> 3);
    const int nblk = blockIdx.x * 8 + (wid & 7);

    const uint4* Ab = Xf + (size_t)rowblk * KS * 128 + lane;
    const uint2* Bb = Wf + (size_t)nblk * KS * 128 + lane;

    float d[4][4][4];
#pragma unroll
    for (int mt = 0; mt < 4; mt++)
#pragma unroll
        for (int nt = 0; nt < 4; nt++)
#pragma unroll
            for (int q = 0; q < 4; q++) d[mt][nt][q] = 0.f;

    uint4 a[4];
    uint2 b[4];
#pragma unroll
    for (int i = 0; i < 4; i++) {
        a[i] = __ldg(Ab + i * 32);
        b[i] = __ldg(Bb + i * 32);
    }

    for (int ks = 0; ks < KS; ks++) {
        uint4 ca[4];
        uint2 cb[4];
#pragma unroll
        for (int i = 0; i < 4; i++) { ca[i] = a[i]; cb[i] = b[i]; }
        if (ks + 1 < KS) {
            const uint4* An = Ab + (size_t)(ks + 1) * 128;
            const uint2* Bn = Bb + (size_t)(ks + 1) * 128;
#pragma unroll
            for (int i = 0; i < 4; i++) {
                a[i] = __ldg(An + i * 32);
                b[i] = __ldg(Bn + i * 32);
            }
        }
#pragma unroll
        for (int mt = 0; mt < 4; mt++)
#pragma unroll
            for (int nt = 0; nt < 4; nt++)
                MMA_F16(d[mt][nt], ca[mt], cb[nt]);
    }

#pragma unroll
    for (int mt = 0; mt < 4; mt++) {
        int m = rowblk * 64 + mt * 16 + (lane >> 2);
#pragma unroll
        for (int nt = 0; nt < 4; nt++) {
            int nn = nblk * 32 + nt * 8 + (lane & 3) * 2;
            int dir = nn >> 12;
            int col = nn & 4095;
            float bs0 = __ldg(bias + nn);
            float bs1 = __ldg(bias + nn + 1);
            float* outp = pre + (size_t)dir * 4096 * 4096 + (size_t)m * 4096 + col;
            float2 v0 = make_float2(d[mt][nt][0] + bs0, d[mt][nt][1] + bs1);
            *(float2*)outp = v0;
            float2 v1 = make_float2(d[mt][nt][2] + bs0, d[mt][nt][3] + bs1);
            *(float2*)(outp + (size_t)8 * 4096) = v1;
        }
    }
}

// ---------------------------------------------------------------------------
// SIMT fp32 GEMM (used only for lin1)
// ---------------------------------------------------------------------------
__global__ void gemm_bias(const float* __restrict__ A, const float* __restrict__ Bm,
                          const float* __restrict__ bias, float* __restrict__ C,
                          int N, int K) {
    __shared__ float As[16][132];
    __shared__ float Bs[16][68];
    int tid = threadIdx.x;
    int m0 = blockIdx.y * 128;
    int n0 = blockIdx.x * 64;
    int tx = tid & 15, ty = tid >> 4;
    int lr = tid >> 2, lc = (tid & 3) * 4;

    const float* Ap  = A  + (size_t)(m0 + lr) * K + lc;
    const float* Ap2 = Ap + (size_t)64 * K;
    const float* Bp  = Bm + (size_t)(n0 + lr) * K + lc;

    float acc[8][4];
#pragma unroll
    for (int i = 0; i < 8; i++)
#pragma unroll
        for (int j = 0; j < 4; j++) acc[i][j] = 0.f;

    for (int k0 = 0; k0 < K; k0 += 16) {
        float4 a0 = *(const float4*)(Ap + k0);
        float4 a1 = *(const float4*)(Ap2 + k0);
        float4 b0 = *(const float4*)(Bp + k0);
        __syncthreads();
        As[lc + 0][lr] = a0.x; As[lc + 1][lr] = a0.y;
        As[lc + 2][lr] = a0.z; As[lc + 3][lr] = a0.w;
        As[lc + 0][lr + 64] = a1.x; As[lc + 1][lr + 64] = a1.y;
        As[lc + 2][lr + 64] = a1.z; As[lc + 3][lr + 64] = a1.w;
        Bs[lc + 0][lr] = b0.x; Bs[lc + 1][lr] = b0.y;
        Bs[lc + 2][lr] = b0.z; Bs[lc + 3][lr] = b0.w;
        __syncthreads();
#pragma unroll
        for (int k = 0; k < 16; k++) {
            float4 av0 = *(const float4*)&As[k][ty * 8];
            float4 av1 = *(const float4*)&As[k][ty * 8 + 4];
            float4 bv  = *(const float4*)&Bs[k][tx * 4];
            float am[8] = {av0.x, av0.y, av0.z, av0.w, av1.x, av1.y, av1.z, av1.w};
            float bb[4] = {bv.x, bv.y, bv.z, bv.w};
#pragma unroll
            for (int i = 0; i < 8; i++)
#pragma unroll
                for (int j = 0; j < 4; j++) acc[i][j] += am[i] * bb[j];
        }
    }
    float bs0 = bias[n0 + tx * 4 + 0];
    float bs1 = bias[n0 + tx * 4 + 1];
    float bs2 = bias[n0 + tx * 4 + 2];
    float bs3 = bias[n0 + tx * 4 + 3];
#pragma unroll
    for (int i = 0; i < 8; i++) {
        int m = m0 + ty * 8 + i;
        float4 ov;
        ov.x = acc[i][0] + bs0; ov.y = acc[i][1] + bs1;
        ov.z = acc[i][2] + bs2; ov.w = acc[i][3] + bs3;
        *(float4*)&C[(size_t)m * N + n0 + tx * 4] = ov;
    }
}

// ---------------------------------------------------------------------------
// Per-direction grid barrier (64 co-resident blocks per dir)
// ---------------------------------------------------------------------------
__device__ __forceinline__ void grid_bar_dir(int dir) {
    __threadfence();
    __syncthreads();
    if (threadIdx.x == 0) {
        volatile unsigned* vgen = &g_bar_gen[dir];
        unsigned gen = *vgen;
        unsigned rank = atomicAdd(&g_bar_cnt[dir], 1);
        if (rank == DBAR - 1) {
            atomicExch(&g_bar_cnt[dir], 0);
            __threadfence();
            atomicExch(&g_bar_gen[dir], gen + 1);
        } else {
            while (*vgen == gen) { __nanosleep(64); }
        }
        __threadfence();
    }
    __syncthreads();
}

// ---------------------------------------------------------------------------
// Persistent HMMA BiLSTM layer. 128 CTAs x 512 threads.
// B fragments staged once per step into smem (kills 4x L2 redundancy).
// Epilogue writes h as fp16 A-frags for next hgemm (layers 0-2) or fp32 Xout
// (layer 3 only).
// ---------------------------------------------------------------------------
__global__ void __launch_bounds__(512, 1)
lstm_mma(const uint4* __restrict__ Ahi, const float* __restrict__ pre,
         float* __restrict__ Xout, __half* __restrict__ Xfout) {
    extern __shared__ __align__(16) uint32_t smd[];
    uint32_t* Bsm = smd;                        // u32[16384] = 64 KB
    float* psum = (float*)(smd + 16384);        // [ksplit][64 rows][33]

    const int tid = threadIdx.x;
    const int wid = tid >> 5;
    const int lid = tid & 31;
    const int cta = blockIdx.x;
    const int dir = cta >> 6;
    const int my_kstep = cta & 63;
    const int j0 = my_kstep * 16;

    const int ksplit = wid >> 3;
    const int mtile  = (wid >> 1) & 3;
    const int ntbase = (wid & 1) * 2;
    const int kbase  = ksplit * 32;

    const uint4* Aph = Ahi + (size_t)cta * 8192 + (size_t)kbase * 128 + mtile * 32 + lid;
    const float* preD = pre + (size_t)dir * 4096 * 4096;

    const int cb = tid >> 4;
    const int cj = tid & 15;
    float creg = 0.f;

    const int kx = dir * HH + j0 + cj;
    const int xkstep = kx >> 4, xkin = kx & 15;

    for (int t = 0; t < SS; t++) {
        const int sdir = dir ? (SS - 1 - t) : t;

        const float* pp = preD + (size_t)sdir * BB * G4 + (size_t)cb * G4 + j0 + cj;
        float pg0 = __ldcg(pp);
        float pg1 = __ldcg(pp + 1024);
        float pg2 = __ldcg(pp + 2048);
        float pg3 = __ldcg(pp + 3072);

        if (t > 0) {
            // --- stage full B image (64 KB) into smem, once per CTA ---
            const uint4* src = (const uint4*)g_hfrag[(t - 1) & 1][dir];
            uint4* dst = (uint4*)Bsm;
#pragma unroll
            for (int i = 0; i < 8; i++)
                dst[tid + i * 512] = __ldcg(src + tid + i * 512);
            __syncthreads();

            float d0a[4] = {0.f,0.f,0.f,0.f}, d0b[4] = {0.f,0.f,0.f,0.f};
            float d1a[4] = {0.f,0.f,0.f,0.f}, d1b[4] = {0.f,0.f,0.f,0.f};
            uint4 rah[4];
#pragma unroll
            for (int i = 0; i < 4; i++)
                rah[i] = __ldg(Aph + i * 128);

            const uint32_t* Bw = Bsm + (((kbase * 4 + ntbase) * 32 + lid) << 1);
#pragma unroll 4
            for (int ks = 0; ks < 32; ks++) {
                int s = ks & 3;
                uint4 ah = rah[s];
                if (ks < 28) rah[s] = __ldg(Aph + (ks + 4) * 128);
                const uint32_t* bp = Bw + ks * 256;   // +4 nt groups *32 lanes *2
                uint2 b0 = *(const uint2*)bp;
                uint2 b1 = *(const uint2*)(bp + 64);
                if (ks & 1) {
                    MMA_F16(d0b, ah, b0);
                    MMA_F16(d1b, ah, b1);
                } else {
                    MMA_F16(d0a, ah, b0);
                    MMA_F16(d1a, ah, b1);
                }
            }
            float d0[4], d1[4];
#pragma unroll
            for (int i = 0; i < 4; i++) {
                d0[i] = d0a[i] + d0b[i];
                d1[i] = d1a[i] + d1b[i];
            }
            float* ps = psum + ksplit * (64 * 33);
            int row0 = mtile * 16 + (lid >> 2);
            int n0 = ntbase * 8 + (lid & 3) * 2;
            ps[row0 * 33 + n0]           = d0[0];
            ps[row0 * 33 + n0 + 1]       = d0[1];
            ps[(row0 + 8) * 33 + n0]     = d0[2];
            ps[(row0 + 8) * 33 + n0 + 1] = d0[3];
            ps[row0 * 33 + n0 + 8]           = d1[0];
            ps[row0 * 33 + n0 + 9]           = d1[1];
            ps[(row0 + 8) * 33 + n0 + 8]     = d1[2];
            ps[(row0 + 8) * 33 + n0 + 9]     = d1[3];
        }
        __syncthreads();

        float gi = pg0, gf = pg1, gg = pg2, go = pg3;
        if (t > 0) {
            gi += psum[(0 * 16 + cj) * 33 + cb] + psum[64 * 33 + (0 * 16 + cj) * 33 + cb];
            gf += psum[(1 * 16 + cj) * 33 + cb] + psum[64 * 33 + (1 * 16 + cj) * 33 + cb];
            gg += psum[(2 * 16 + cj) * 33 + cb] + psum[64 * 33 + (2 * 16 + cj) * 33 + cb];
            go += psum[(3 * 16 + cj) * 33 + cb] + psum[64 * 33 + (3 * 16 + cj) * 33 + cb];
        }
        float i_ = 1.f / (1.f + expf(-gi));
        float f_ = 1.f / (1.f + expf(-gf));
        creg = f_ * creg + i_ * tanhf(gg);
        float hv = (1.f / (1.f + expf(-go))) * tanhf(creg);
        __half hvh = __float2half_rn(hv);

        // recurrent h fragments (parity buffer)
        __half* hf = (__half*)g_hfrag[t & 1][dir];
        int u32i = ((my_kstep * 4 + (cb >> 3)) * 32 + (cb & 7) * 4 + ((cj & 7) >> 1)) * 2
                   + (cj >> 3);
        hf[u32i * 2 + (cj & 1)] = hvh;

        if (Xfout) {
            // fused convx: fp16 A-fragment for next layer's hgemm (KS=128)
            int m = sdir * BB + cb;
            int rowblk = m >> 6, r = m & 63;
            int mt = r >> 4, mrow = r & 15;
            int lane2 = (mrow & 7) * 4 + ((xkin >> 1) & 3);
            int reg = ((mrow >> 3) & 1) + ((xkin >> 3) << 1);
            size_t e = (((((size_t)rowblk * 128 + xkstep) * 4 + mt) * 32 + lane2) * 4
                        + reg) * 2 + (xkin & 1);
            Xfout[e] = hvh;
        } else {
            // final layer: fp32 output for bn_lin2
            Xout[(size_t)(sdir * BB + cb) * 2048 + dir * HH + j0 + cj] = hv;
        }

        grid_bar_dir(dir);
    }
}

// ---------------------------------------------------------------------------
// BN + ReLU + lin2 -> emissions
// ---------------------------------------------------------------------------
__global__ void bn_lin2(const float* __restrict__ X, const float* __restrict__ gamma,
                        const float* __restrict__ beta, const float* __restrict__ w2,
                        const float* __restrict__ b2, float* __restrict__ emis) {
    int m = blockIdx.x;
    int s = m / BB, b = m % BB;
    int tid = threadIdx.x;
    const float inv = rsqrtf(1.f + 1e-5f);
    float acc[NT];
#pragma unroll
    for (int j = 0; j < NT; j++) acc[j] = 0.f;
    for (int k = tid; k < 2048; k += 128) {
        float hv = X[(size_t)m * 2048 + k];
        hv = fmaxf(gamma[k] * inv * hv + beta[k], 0.f);
#pragma unroll
        for (int j = 0; j < NT; j++) acc[j] += hv * w2[j * 2048 + k];
    }
    __shared__ float red[NT][128];
#pragma unroll
    for (int j = 0; j < NT; j++) red[j][tid] = acc[j];
    __syncthreads();
    for (int off = 64; off > 0; off >>= 1) {
        if (tid < off) {
#pragma unroll
            for (int j = 0; j < NT; j++) red[j][tid] += red[j][tid + off];
        }
        __syncthreads();
    }
    if (tid < NT) emis[(size_t)(b * SS + s) * NT + tid] = red[tid][0] + b2[tid];
}

// ---------------------------------------------------------------------------
// CRF log-likelihood -> scalar
// ---------------------------------------------------------------------------
__global__ void crf_kernel(const float* __restrict__ emis, const int* __restrict__ y,
                           const unsigned char* __restrict__ maskb,
                           const float* __restrict__ start, const float* __restrict__ end_,
                           const float* __restrict__ trans, float* __restrict__ out) {
    __shared__ float alpha[BB][12];
    __shared__ float tmp[BB][12];
    __shared__ float tr[NT * NT];
    __shared__ float numv[BB];
    __shared__ float denv[BB];
    __shared__ int mask_mode;

    int tid = threadIdx.x;
    if (tid == 0) {
        int mm = 1;
        for (int i = 0; i < 16; i++) {
            if (maskb[4 * i + 1] | maskb[4 * i + 2] | maskb[4 * i + 3]) { mm = 0; break; }
        }
        mask_mode = mm;
    }
    if (tid < NT * NT) tr[tid] = trans[tid];
    __syncthreads();

    int b = tid / NT;
    int j = tid % NT;
    const int mm = mask_mode;
    const int* mi = (const int*)maskb;

    alpha[b][j] = start[j] + emis[(size_t)(b * SS) * NT + j];
    __syncthreads();

    for (int t = 1; t < SS; t++) {
        float mx = -1e30f;
#pragma unroll
        for (int i = 0; i < NT; i++) {
            float v = alpha[b][i] + tr[i * NT + j];
            mx = fmaxf(mx, v);
        }
        float ssum = 0.f;
#pragma unroll
        for (int i = 0; i < NT; i++)
            ssum += expf(alpha[b][i] + tr[i * NT + j] - mx);
        float nxt = mx + logf(ssum) + emis[(size_t)(b * SS + t) * NT + j];
        bool mk = mm ? (mi[b * SS + t] != 0) : (maskb[b * SS + t] != 0);
        __syncthreads();
        if (mk) alpha[b][j] = nxt;
        __syncthreads();
    }

    tmp[b][j] = alpha[b][j] + end_[j];
    __syncthreads();
    if (j == 0) {
        float mx = tmp[b][0];
#pragma unroll
        for (int i = 1; i < NT; i++) mx = fmaxf(mx, tmp[b][i]);
        float ssum = 0.f;
#pragma unroll
        for (int i = 0; i < NT; i++) ssum += expf(tmp[b][i] - mx);
        denv[b] = mx + logf(ssum);

        const int* yb = y + b * SS;
        float num = start[yb[0]] + emis[(size_t)(b * SS) * NT + yb[0]];
        int len = (mm ? (mi[b * SS] != 0) : (maskb[b * SS] != 0)) ? 1 : 0;
        for (int t = 1; t < SS; t++) {
            bool mk = mm ? (mi[b * SS + t] != 0) : (maskb[b * SS + t] != 0);
            if (mk) {
                num += tr[yb[t - 1] * NT + yb[t]] + emis[(size_t)(b * SS + t) * NT + yb[t]];
                len++;
            }
        }
        int last = yb[(len > 0 ? len : 1) - 1];
        num += end_[last];
        numv[b] = num;
    }
    __syncthreads();
    if (tid == 0) {
        float acc = 0.f;
        for (int bb2 = 0; bb2 < BB; bb2++) acc += numv[bb2] - denv[bb2];
        out[0] = acc;
    }
}

// ---------------------------------------------------------------------------
// Host launcher
// ---------------------------------------------------------------------------
extern "C" void kernel_launch(void* const* d_in, const int* in_sizes, int n_in,
                              void* d_out, int out_size) {
    const int*   x       = (const int*)d_in[0];
    const int*   y       = (const int*)d_in[1];
    const unsigned char* mask = (const unsigned char*)d_in[2];
    const float* emb     = (const float*)d_in[3];
    const float* lin1_w  = (const float*)d_in[4];
    const float* lin1_b  = (const float*)d_in[5];
    const float* wih[4]  = {(const float*)d_in[6],  (const float*)d_in[9],
                            (const float*)d_in[12], (const float*)d_in[15]};
    const float* whh[4]  = {(const float*)d_in[7],  (const float*)d_in[10],
                            (const float*)d_in[13], (const float*)d_in[16]};
    const float* bias[4] = {(const float*)d_in[8],  (const float*)d_in[11],
                            (const float*)d_in[14], (const float*)d_in[17]};
    const float* bn_gamma = (const float*)d_in[18];
    const float* bn_beta  = (const float*)d_in[19];
    const float* lin2_w   = (const float*)d_in[20];
    const float* lin2_b   = (const float*)d_in[21];
    const float* crf_start = (const float*)d_in[22];
    const float* crf_end   = (const float*)d_in[23];
    const float* crf_trans = (const float*)d_in[24];

    float *E, *W1p, *X0, *X1, *pre, *emis;
    uint4 *Ahi, *Xf;
    uint2 *Wf;
    cudaGetSymbolAddress((void**)&E, g_E);
    cudaGetSymbolAddress((void**)&W1p, g_W1p);
    cudaGetSymbolAddress((void**)&X0, g_X0);
    cudaGetSymbolAddress((void**)&X1, g_X1);
    cudaGetSymbolAddress((void**)&pre, g_pre);
    cudaGetSymbolAddress((void**)&emis, g_emis);
    cudaGetSymbolAddress((void**)&Ahi, g_Ahi);
    cudaGetSymbolAddress((void**)&Xf, g_Xf);
    cudaGetSymbolAddress((void**)&Wf, g_Wf);

    static bool attr_set = false;
    if (!attr_set) {
        cudaFuncSetAttribute(lstm_mma, cudaFuncAttributeMaxDynamicSharedMemorySize,
                             LSTM_SMEM);
        attr_set = true;
    }

    const size_t XF_STRIDE = (size_t)64 * 128 * 4 * 32;   // uint4 per buffer

    gather_kernel<<<(4096 * DPAD + 255) / 256, 256>>>(E, x, emb);
    padw_kernel<<<(512 * DPAD + 255) / 256, 256>>>(W1p, lin1_w);
    gemm_bias<<<dim3(512 / 64, 4096 / 128), 256>>>(E, W1p, lin1_b, X0, 512, DPAD);

    float* Xin = X0;
    float* Xout = X1;
    const int Kin[4] = {512, 2048, 2048, 2048};

    // layer-0 input fragments via convx; later layers fused into lstm epilogue
    convx_kernel<<<(4096 * 512 + 255) / 256, 256>>>(Xin, (__half*)Xf, 512, 32);

    for (int l = 0; l < 4; l++) {
        const int K = Kin[l];
        const int KS = K / 16;
        uint4* XfIn  = Xf + (size_t)(l & 1) * XF_STRIDE;
        __half* XfOut = (l < 3) ? (__half*)(Xf + (size_t)((l + 1) & 1) * XF_STRIDE)
                                : (__half*)0;
        convw_kernel<<<(128 * 64 * 1024) / 256, 256>>>(whh[l], (__half*)Ahi);
        convwih_kernel<<<(8192 * K + 255) / 256, 256>>>(wih[l], (__half*)Wf, K, KS);
        hgemm_pre<<<dim3(32, 32), 512>>>(XfIn, Wf, bias[l], pre, KS);
        lstm_mma<<<LBLK, 512, LSTM_SMEM>>>(Ahi, pre, Xout, XfOut);
        float* tmpp = Xin; Xin = Xout; Xout = tmpp;
    }

    bn_lin2<<<4096, 128>>>(Xin, bn_gamma, bn_beta, lin2_w, lin2_b, emis);
    crf_kernel<<<1, BB * NT>>>(emis, y, mask, crf_start, crf_end, crf_trans,
                               (float*)d_out);
}

// round 13
// speedup vs baseline: 5.3079x; 1.0711x over previous
#include <cuda_runtime.h>
#include <cuda_fp16.h>
#include <cuda_bf16.h>
#include <math.h>
#include <stdint.h>

// ---------------------------------------------------------------------------
// Problem constants
// ---------------------------------------------------------------------------
#define BB 32      // batch
#define SS 128     // seq len
#define DD 300     // emb dim
#define DPAD 304   // padded emb dim
#define HH 1024    // hidden
#define G4 4096    // 4*H
#define NT 9       // tags
#define LBLK 128   // persistent LSTM CTAs (single wave, <148 SMs)
#define DBAR 64    // per-direction barrier arrivals

// lstm dynamic smem: Bsm u32[16384] (64KB) + psum float[2*64*33] + hstage 1KB
#define LSTM_SMEM (65536 + 2 * 64 * 33 * 4 + 1024)

// ---------------------------------------------------------------------------
// Scratch (static device allocations - allowed)
// ---------------------------------------------------------------------------
__device__ float g_E[4096 * DPAD];
__device__ float g_W1p[512 * DPAD];
__device__ float g_X0[4096 * 2048];
__device__ float g_X1[4096 * 2048];
__device__ float g_pre[2ull * 4096 * 4096];
__device__ float g_emis[BB * SS * NT];
// Whh fp16, A-fragment order: [cta 128][kstep 64][mtile 4][lane 32][4 u32]
__device__ uint4 g_Ahi[128 * 8192];
// h as fp16 B-fragments, parity double-buffered: [parity][dir][16384 u32]
__device__ uint32_t g_hfrag[2][2][16384];
// input-projection fragments (ping-pong: lstm(l) writes [1^(l&1)] while hgemm(l) reads [l&1])
__device__ uint4 g_Xf[2][64 * 128 * 4 * 32];    // A frags: [rowblk64][kstep<=128][mt4][lane32]
__device__ uint2 g_Wf[256 * 128 * 4 * 32];      // B frags: [nblk32 x256][kstep<=128][nt4][lane32]

__device__ unsigned g_bar_cnt[2];
__device__ unsigned g_bar_gen[2];

// mma.sync m16n8k16 fp16 -> f32 (baseline PTX, compiles for plain sm_103)
#define MMA_F16(d, a, b) \
    asm volatile("mma.sync.aligned.m16n8k16.row.col.f32.f16.f16.f32 " \
        "{%0,%1,%2,%3}, {%4,%5,%6,%7}, {%8,%9}, {%0,%1,%2,%3};" \
        : "+f"((d)[0]), "+f"((d)[1]), "+f"((d)[2]), "+f"((d)[3]) \
        : "r"((a).x), "r"((a).y), "r"((a).z), "r"((a).w), \
          "r"((b).x), "r"((b).y))

// ---------------------------------------------------------------------------
// Small prep kernels
// ---------------------------------------------------------------------------
__global__ void gather_kernel(float* __restrict__ E, const int* __restrict__ x,
                              const float* __restrict__ emb) {
    int i = blockIdx.x * blockDim.x + threadIdx.x;
    if (i >= 4096 * DPAD) return;
    int m = i / DPAD, col = i % DPAD;
    int s = m / BB, b = m % BB;
    int tok = x[b * SS + s];
    E[i] = (col < DD) ? emb[(size_t)tok * DD + col] : 0.f;
}

__global__ void padw_kernel(float* __restrict__ Wp, const float* __restrict__ W) {
    int i = blockIdx.x * blockDim.x + threadIdx.x;
    if (i >= 512 * DPAD) return;
    int r = i / DPAD, col = i % DPAD;
    Wp[i] = (col < DD) ? W[r * DD + col] : 0.f;
}

// Whh fp32 -> fp16, reordered into per-lane mma A-fragments (recurrent weights).
__global__ void convw_kernel(const float* __restrict__ whh,
                             __half* __restrict__ Ahi) {
    int i = blockIdx.x * blockDim.x + threadIdx.x;   // 128*64*1024
    if (i >= 128 * 64 * 1024) return;
    int c = i >> 16;
    int r = (i >> 10) & 63;
    int k = i & 1023;
    int dir = c >> 6, j0 = (c & 63) * 16;
    int gate = r >> 4, jj = r & 15;
    int grow = gate * 1024 + j0 + jj;
    float w = whh[(size_t)dir * G4 * HH + (size_t)grow * HH + k];
    int mtile = gate, m = jj;
    int kstep = k >> 4, kin = k & 15;
    int lane = (m & 7) * 4 + ((kin >> 1) & 3);
    int reg = ((m >> 3) & 1) + ((kin >> 3) << 1);
    size_t idx = (size_t)c * 32768 + kstep * 512 + mtile * 128 + lane * 4 + reg;
    Ahi[idx * 2 + (kin & 1)] = __float2half_rn(w);
}

// X fp32 (4096 x K) -> fp16 A-fragments (only needed for layer 0 input)
__global__ void convx_kernel(const float* __restrict__ X, __half* __restrict__ Xf,
                             int K, int KS) {
    int i = blockIdx.x * blockDim.x + threadIdx.x;
    if (i >= 4096 * K) return;
    int m = i / K, k = i % K;
    int rowblk = m >> 6, r = m & 63;
    int mt = r >> 4, mrow = r & 15;
    int kstep = k >> 4, kin = k & 15;
    int lane = (mrow & 7) * 4 + ((kin >> 1) & 3);
    int reg = ((mrow >> 3) & 1) + ((kin >> 3) << 1);
    size_t e = (((((size_t)rowblk * KS + kstep) * 4 + mt) * 32 + lane) * 4 + reg) * 2
               + (kin & 1);
    Xf[e] = __float2half_rn(X[i]);
}

// Wih fp32 (8192 x K, dir-major) -> fp16 B-fragments
__global__ void convwih_kernel(const float* __restrict__ W, __half* __restrict__ Wf,
                               int K, int KS) {
    int i = blockIdx.x * blockDim.x + threadIdx.x;
    if (i >= 8192 * K) return;
    int n = i / K, k = i % K;
    int nblk = n >> 5, nr = n & 31;
    int nt = nr >> 3, ncol = nr & 7;
    int kstep = k >> 4, kin = k & 15;
    int lane = ncol * 4 + ((kin & 7) >> 1);
    int reg = kin >> 3;
    size_t e = (((((size_t)nblk * KS + kstep) * 4 + nt) * 32 + lane) * 2 + reg) * 2
               + (kin & 1);
    Wf[e] = __float2half_rn(W[i]);
}

// ---------------------------------------------------------------------------
// HMMA input-projection GEMM: pre[dir][m][col] = X[m] . Wih[n] + bias[n]
// Grid (32, 32), 512 threads; CTA tile 128x256; warp tile 64x32.
// ---------------------------------------------------------------------------
__global__ void __launch_bounds__(512, 1)
hgemm_pre(const uint4* __restrict__ Xf, const uint2* __restrict__ Wf,
          const float* __restrict__ bias, float* __restrict__ pre, int KS) {
    const int tid = threadIdx.x;
    const int wid = tid >> 5, lane = tid & 31;
    const int rowblk = blockIdx.y * 2 + (wid >> 3);
    const int nblk = blockIdx.x * 8 + (wid & 7);

    const uint4* Ab = Xf + (size_t)rowblk * KS * 128 + lane;
    const uint2* Bb = Wf + (size_t)nblk * KS * 128 + lane;

    float d[4][4][4];
#pragma unroll
    for (int mt = 0; mt < 4; mt++)
#pragma unroll
        for (int nt = 0; nt < 4; nt++)
#pragma unroll
            for (int q = 0; q < 4; q++) d[mt][nt][q] = 0.f;

    uint4 a[4];
    uint2 b[4];
#pragma unroll
    for (int i = 0; i < 4; i++) {
        a[i] = __ldg(Ab + i * 32);
        b[i] = __ldg(Bb + i * 32);
    }

    for (int ks = 0; ks < KS; ks++) {
        uint4 ca[4];
        uint2 cb[4];
#pragma unroll
        for (int i = 0; i < 4; i++) { ca[i] = a[i]; cb[i] = b[i]; }
        if (ks + 1 < KS) {
            const uint4* An = Ab + (size_t)(ks + 1) * 128;
            const uint2* Bn = Bb + (size_t)(ks + 1) * 128;
#pragma unroll
            for (int i = 0; i < 4; i++) {
                a[i] = __ldg(An + i * 32);
                b[i] = __ldg(Bn + i * 32);
            }
        }
#pragma unroll
        for (int mt = 0; mt < 4; mt++)
#pragma unroll
            for (int nt = 0; nt < 4; nt++)
                MMA_F16(d[mt][nt], ca[mt], cb[nt]);
    }

#pragma unroll
    for (int mt = 0; mt < 4; mt++) {
        int m = rowblk * 64 + mt * 16 + (lane >> 2);
#pragma unroll
        for (int nt = 0; nt < 4; nt++) {
            int nn = nblk * 32 + nt * 8 + (lane & 3) * 2;
            int dir = nn >> 12;
            int col = nn & 4095;
            float bs0 = __ldg(bias + nn);
            float bs1 = __ldg(bias + nn + 1);
            float* outp = pre + (size_t)dir * 4096 * 4096 + (size_t)m * 4096 + col;
            float2 v0 = make_float2(d[mt][nt][0] + bs0, d[mt][nt][1] + bs1);
            *(float2*)outp = v0;
            float2 v1 = make_float2(d[mt][nt][2] + bs0, d[mt][nt][3] + bs1);
            *(float2*)(outp + (size_t)8 * 4096) = v1;
        }
    }
}

// ---------------------------------------------------------------------------
// SIMT fp32 GEMM (used only for lin1)
// ---------------------------------------------------------------------------
__global__ void gemm_bias(const float* __restrict__ A, const float* __restrict__ Bm,
                          const float* __restrict__ bias, float* __restrict__ C,
                          int N, int K) {
    __shared__ float As[16][132];
    __shared__ float Bs[16][68];
    int tid = threadIdx.x;
    int m0 = blockIdx.y * 128;
    int n0 = blockIdx.x * 64;
    int tx = tid & 15, ty = tid >> 4;
    int lr = tid >> 2, lc = (tid & 3) * 4;

    const float* Ap  = A  + (size_t)(m0 + lr) * K + lc;
    const float* Ap2 = Ap + (size_t)64 * K;
    const float* Bp  = Bm + (size_t)(n0 + lr) * K + lc;

    float acc[8][4];
#pragma unroll
    for (int i = 0; i < 8; i++)
#pragma unroll
        for (int j = 0; j < 4; j++) acc[i][j] = 0.f;

    for (int k0 = 0; k0 < K; k0 += 16) {
        float4 a0 = *(const float4*)(Ap + k0);
        float4 a1 = *(const float4*)(Ap2 + k0);
        float4 b0 = *(const float4*)(Bp + k0);
        __syncthreads();
        As[lc + 0][lr] = a0.x; As[lc + 1][lr] = a0.y;
        As[lc + 2][lr] = a0.z; As[lc + 3][lr] = a0.w;
        As[lc + 0][lr + 64] = a1.x; As[lc + 1][lr + 64] = a1.y;
        As[lc + 2][lr + 64] = a1.z; As[lc + 3][lr + 64] = a1.w;
        Bs[lc + 0][lr] = b0.x; Bs[lc + 1][lr] = b0.y;
        Bs[lc + 2][lr] = b0.z; Bs[lc + 3][lr] = b0.w;
        __syncthreads();
#pragma unroll
        for (int k = 0; k < 16; k++) {
            float4 av0 = *(const float4*)&As[k][ty * 8];
            float4 av1 = *(const float4*)&As[k][ty * 8 + 4];
            float4 bv  = *(const float4*)&Bs[k][tx * 4];
            float am[8] = {av0.x, av0.y, av0.z, av0.w, av1.x, av1.y, av1.z, av1.w};
            float bb[4] = {bv.x, bv.y, bv.z, bv.w};
#pragma unroll
            for (int i = 0; i < 8; i++)
#pragma unroll
                for (int j = 0; j < 4; j++) acc[i][j] += am[i] * bb[j];
        }
    }
    float bs0 = bias[n0 + tx * 4 + 0];
    float bs1 = bias[n0 + tx * 4 + 1];
    float bs2 = bias[n0 + tx * 4 + 2];
    float bs3 = bias[n0 + tx * 4 + 3];
#pragma unroll
    for (int i = 0; i < 8; i++) {
        int m = m0 + ty * 8 + i;
        float4 ov;
        ov.x = acc[i][0] + bs0; ov.y = acc[i][1] + bs1;
        ov.z = acc[i][2] + bs2; ov.w = acc[i][3] + bs3;
        *(float4*)&C[(size_t)m * N + n0 + tx * 4] = ov;
    }
}

// ---------------------------------------------------------------------------
// Persistent HMMA BiLSTM layer. 128 CTAs x 512 threads.
// Split arrive/wait barrier: coalesced h-frag publish + fence + arrive, then
// shadow work (Xf/Xout stores, pre(t+1) prefetch), then wait at next iter top.
// ---------------------------------------------------------------------------
__global__ void __launch_bounds__(512, 1)
lstm_mma(const uint4* __restrict__ Ahi, const float* __restrict__ pre,
         float* __restrict__ Xout, __half* __restrict__ Xfout) {
    extern __shared__ __align__(16) uint32_t smd[];
    uint32_t* Bsm = smd;                           // u32[16384] = 64 KB
    float* psum = (float*)(smd + 16384);           // [ksplit][64 rows][33]
    __half* hstage = (__half*)(smd + 16384 + 2 * 64 * 33);  // 512 halves

    const int tid = threadIdx.x;
    const int wid = tid >> 5;
    const int lid = tid & 31;
    const int cta = blockIdx.x;
    const int dir = cta >> 6;
    const int my_kstep = cta & 63;
    const int j0 = my_kstep * 16;

    const int ksplit = wid >> 3;
    const int mtile  = (wid >> 1) & 3;
    const int ntbase = (wid & 1) * 2;
    const int kbase  = ksplit * 32;

    const uint4* Aph = Ahi + (size_t)cta * 8192 + (size_t)kbase * 128 + mtile * 32 + lid;
    const float* preD = pre + (size_t)dir * 4096 * 4096;

    const int cb = tid >> 4;
    const int cj = tid & 15;
    float creg = 0.f;

    const int kx = dir * HH + j0 + cj;
    const int xkstep = kx >> 4, xkin = kx & 15;

    // local half index within this CTA's contiguous 1KB h-frag slice
    const int hloc = (((cb >> 3) * 32 + (cb & 7) * 4 + ((cj & 7) >> 1)) * 2
                      + (cj >> 3)) * 2 + (cj & 1);

    volatile unsigned* vgen = &g_bar_gen[dir];
    const unsigned base = *vgen;   // safe: gen can't advance until all CTAs arrive t=0

    // prologue: pre loads for t=0
    float pg0, pg1, pg2, pg3;
    {
        const int sd0 = dir ? (SS - 1) : 0;
        const float* pp = preD + (size_t)sd0 * BB * G4 + (size_t)cb * G4 + j0 + cj;
        pg0 = __ldcg(pp);
        pg1 = __ldcg(pp + 1024);
        pg2 = __ldcg(pp + 2048);
        pg3 = __ldcg(pp + 3072);
    }

    for (int t = 0; t < SS; t++) {
        const int sdir = dir ? (SS - 1 - t) : t;

        if (t > 0) {
            // --- wait for all CTAs of this dir to finish step t-1 ---
            if (tid == 0) {
                while (*vgen < base + (unsigned)t) { __nanosleep(32); }
                __threadfence();
            }
            __syncthreads();

            // --- stage full B image (64 KB) into smem ---
            const uint4* src = (const uint4*)g_hfrag[(t - 1) & 1][dir];
            uint4* dst = (uint4*)Bsm;
#pragma unroll
            for (int i = 0; i < 8; i++)
                dst[tid + i * 512] = __ldcg(src + tid + i * 512);
            __syncthreads();

            float d0a[4] = {0.f,0.f,0.f,0.f}, d0b[4] = {0.f,0.f,0.f,0.f};
            float d1a[4] = {0.f,0.f,0.f,0.f}, d1b[4] = {0.f,0.f,0.f,0.f};
            uint4 rah[4];
#pragma unroll
            for (int i = 0; i < 4; i++)
                rah[i] = __ldg(Aph + i * 128);

            const uint32_t* Bw = Bsm + (((kbase * 4 + ntbase) * 32 + lid) << 1);
#pragma unroll 4
            for (int ks = 0; ks < 32; ks++) {
                int s = ks & 3;
                uint4 ah = rah[s];
                if (ks < 28) rah[s] = __ldg(Aph + (ks + 4) * 128);
                const uint32_t* bp = Bw + ks * 256;
                uint2 b0 = *(const uint2*)bp;
                uint2 b1 = *(const uint2*)(bp + 64);
                if (ks & 1) {
                    MMA_F16(d0b, ah, b0);
                    MMA_F16(d1b, ah, b1);
                } else {
                    MMA_F16(d0a, ah, b0);
                    MMA_F16(d1a, ah, b1);
                }
            }
            float d0[4], d1[4];
#pragma unroll
            for (int i = 0; i < 4; i++) {
                d0[i] = d0a[i] + d0b[i];
                d1[i] = d1a[i] + d1b[i];
            }
            float* ps = psum + ksplit * (64 * 33);
            int row0 = mtile * 16 + (lid >> 2);
            int n0 = ntbase * 8 + (lid & 3) * 2;
            ps[row0 * 33 + n0]           = d0[0];
            ps[row0 * 33 + n0 + 1]       = d0[1];
            ps[(row0 + 8) * 33 + n0]     = d0[2];
            ps[(row0 + 8) * 33 + n0 + 1] = d0[3];
            ps[row0 * 33 + n0 + 8]           = d1[0];
            ps[row0 * 33 + n0 + 9]           = d1[1];
            ps[(row0 + 8) * 33 + n0 + 8]     = d1[2];
            ps[(row0 + 8) * 33 + n0 + 9]     = d1[3];
            __syncthreads();
        }

        // --- cell update ---
        float gi = pg0, gf = pg1, gg = pg2, go = pg3;
        if (t > 0) {
            gi += psum[(0 * 16 + cj) * 33 + cb] + psum[64 * 33 + (0 * 16 + cj) * 33 + cb];
            gf += psum[(1 * 16 + cj) * 33 + cb] + psum[64 * 33 + (1 * 16 + cj) * 33 + cb];
            gg += psum[(2 * 16 + cj) * 33 + cb] + psum[64 * 33 + (2 * 16 + cj) * 33 + cb];
            go += psum[(3 * 16 + cj) * 33 + cb] + psum[64 * 33 + (3 * 16 + cj) * 33 + cb];
        }
        float i_ = 1.f / (1.f + expf(-gi));
        float f_ = 1.f / (1.f + expf(-gf));
        creg = f_ * creg + i_ * tanhf(gg);
        float hv = (1.f / (1.f + expf(-go))) * tanhf(creg);
        __half hvh = __float2half_rn(hv);

        // --- coalesced h-frag publish: smem stage -> 64 x uint4 STG ---
        hstage[hloc] = hvh;
        __syncthreads();
        if (tid < 64) {
            uint4 v = ((const uint4*)hstage)[tid];
            *(((uint4*)(g_hfrag[t & 1][dir] + my_kstep * 256)) + tid) = v;
        }
        __threadfence();
        __syncthreads();

        // --- arrive ---
        if (tid == 0) {
            unsigned rank = atomicAdd(&g_bar_cnt[dir], 1);
            if (rank == DBAR - 1) {
                atomicExch(&g_bar_cnt[dir], 0);
                __threadfence();
                atomicExch(&g_bar_gen[dir], base + (unsigned)t + 1);
            }
        }

        // --- shadow work (hidden behind other CTAs' arrivals) ---
        if (Xfout) {
            int m = sdir * BB + cb;
            int rowblk = m >> 6, r = m & 63;
            int mt = r >> 4, mrow = r & 15;
            int lane2 = (mrow & 7) * 4 + ((xkin >> 1) & 3);
            int reg = ((mrow >> 3) & 1) + ((xkin >> 3) << 1);
            size_t e = (((((size_t)rowblk * 128 + xkstep) * 4 + mt) * 32 + lane2) * 4
                        + reg) * 2 + (xkin & 1);
            Xfout[e] = hvh;
        } else {
            Xout[(size_t)(sdir * BB + cb) * 2048 + dir * HH + j0 + cj] = hv;
        }
        if (t + 1 < SS) {
            const int sdn = dir ? (SS - 2 - t) : (t + 1);
            const float* pp = preD + (size_t)sdn * BB * G4 + (size_t)cb * G4 + j0 + cj;
            pg0 = __ldcg(pp);
            pg1 = __ldcg(pp + 1024);
            pg2 = __ldcg(pp + 2048);
            pg3 = __ldcg(pp + 3072);
        }
    }
}

// ---------------------------------------------------------------------------
// BN + ReLU + lin2 -> emissions
// ---------------------------------------------------------------------------
__global__ void bn_lin2(const float* __restrict__ X, const float* __restrict__ gamma,
                        const float* __restrict__ beta, const float* __restrict__ w2,
                        const float* __restrict__ b2, float* __restrict__ emis) {
    int m = blockIdx.x;
    int s = m / BB, b = m % BB;
    int tid = threadIdx.x;
    const float inv = rsqrtf(1.f + 1e-5f);
    float acc[NT];
#pragma unroll
    for (int j = 0; j < NT; j++) acc[j] = 0.f;
    for (int k = tid; k < 2048; k += 128) {
        float hv = X[(size_t)m * 2048 + k];
        hv = fmaxf(gamma[k] * inv * hv + beta[k], 0.f);
#pragma unroll
        for (int j = 0; j < NT; j++) acc[j] += hv * w2[j * 2048 + k];
    }
    __shared__ float red[NT][128];
#pragma unroll
    for (int j = 0; j < NT; j++) red[j][tid] = acc[j];
    __syncthreads();
    for (int off = 64; off > 0; off >>= 1) {
        if (tid < off) {
#pragma unroll
            for (int j = 0; j < NT; j++) red[j][tid] += red[j][tid + off];
        }
        __syncthreads();
    }
    if (tid < NT) emis[(size_t)(b * SS + s) * NT + tid] = red[tid][0] + b2[tid];
}

// ---------------------------------------------------------------------------
// CRF log-likelihood -> scalar
// ---------------------------------------------------------------------------
__global__ void crf_kernel(const float* __restrict__ emis, const int* __restrict__ y,
                           const unsigned char* __restrict__ maskb,
                           const float* __restrict__ start, const float* __restrict__ end_,
                           const float* __restrict__ trans, float* __restrict__ out) {
    __shared__ float alpha[BB][12];
    __shared__ float tmp[BB][12];
    __shared__ float tr[NT * NT];
    __shared__ float numv[BB];
    __shared__ float denv[BB];
    __shared__ int mask_mode;

    int tid = threadIdx.x;
    if (tid == 0) {
        int mm = 1;
        for (int i = 0; i < 16; i++) {
            if (maskb[4 * i + 1] | maskb[4 * i + 2] | maskb[4 * i + 3]) { mm = 0; break; }
        }
        mask_mode = mm;
    }
    if (tid < NT * NT) tr[tid] = trans[tid];
    __syncthreads();

    int b = tid / NT;
    int j = tid % NT;
    const int mm = mask_mode;
    const int* mi = (const int*)maskb;

    alpha[b][j] = start[j] + emis[(size_t)(b * SS) * NT + j];
    __syncthreads();

    for (int t = 1; t < SS; t++) {
        float mx = -1e30f;
#pragma unroll
        for (int i = 0; i < NT; i++) {
            float v = alpha[b][i] + tr[i * NT + j];
            mx = fmaxf(mx, v);
        }
        float ssum = 0.f;
#pragma unroll
        for (int i = 0; i < NT; i++)
            ssum += expf(alpha[b][i] + tr[i * NT + j] - mx);
        float nxt = mx + logf(ssum) + emis[(size_t)(b * SS + t) * NT + j];
        bool mk = mm ? (mi[b * SS + t] != 0) : (maskb[b * SS + t] != 0);
        __syncthreads();
        if (mk) alpha[b][j] = nxt;
        __syncthreads();
    }

    tmp[b][j] = alpha[b][j] + end_[j];
    __syncthreads();
    if (j == 0) {
        float mx = tmp[b][0];
#pragma unroll
        for (int i = 1; i < NT; i++) mx = fmaxf(mx, tmp[b][i]);
        float ssum = 0.f;
#pragma unroll
        for (int i = 0; i < NT; i++) ssum += expf(tmp[b][i] - mx);
        denv[b] = mx + logf(ssum);

        const int* yb = y + b * SS;
        float num = start[yb[0]] + emis[(size_t)(b * SS) * NT + yb[0]];
        int len = (mm ? (mi[b * SS] != 0) : (maskb[b * SS] != 0)) ? 1 : 0;
        for (int t = 1; t < SS; t++) {
            bool mk = mm ? (mi[b * SS + t] != 0) : (maskb[b * SS + t] != 0);
            if (mk) {
                num += tr[yb[t - 1] * NT + yb[t]] + emis[(size_t)(b * SS + t) * NT + yb[t]];
                len++;
            }
        }
        int last = yb[(len > 0 ? len : 1) - 1];
        num += end_[last];
        numv[b] = num;
    }
    __syncthreads();
    if (tid == 0) {
        float acc = 0.f;
        for (int bb2 = 0; bb2 < BB; bb2++) acc += numv[bb2] - denv[bb2];
        out[0] = acc;
    }
}

// ---------------------------------------------------------------------------
// Host launcher
// ---------------------------------------------------------------------------
extern "C" void kernel_launch(void* const* d_in, const int* in_sizes, int n_in,
                              void* d_out, int out_size) {
    const int*   x       = (const int*)d_in[0];
    const int*   y       = (const int*)d_in[1];
    const unsigned char* mask = (const unsigned char*)d_in[2];
    const float* emb     = (const float*)d_in[3];
    const float* lin1_w  = (const float*)d_in[4];
    const float* lin1_b  = (const float*)d_in[5];
    const float* wih[4]  = {(const float*)d_in[6],  (const float*)d_in[9],
                            (const float*)d_in[12], (const float*)d_in[15]};
    const float* whh[4]  = {(const float*)d_in[7],  (const float*)d_in[10],
                            (const float*)d_in[13], (const float*)d_in[16]};
    const float* bias[4] = {(const float*)d_in[8],  (const float*)d_in[11],
                            (const float*)d_in[14], (const float*)d_in[17]};
    const float* bn_gamma = (const float*)d_in[18];
    const float* bn_beta  = (const float*)d_in[19];
    const float* lin2_w   = (const float*)d_in[20];
    const float* lin2_b   = (const float*)d_in[21];
    const float* crf_start = (const float*)d_in[22];
    const float* crf_end   = (const float*)d_in[23];
    const float* crf_trans = (const float*)d_in[24];

    float *E, *W1p, *X0, *X1, *pre, *emis;
    uint4 *Ahi, *Xf;
    uint2 *Wf;
    cudaGetSymbolAddress((void**)&E, g_E);
    cudaGetSymbolAddress((void**)&W1p, g_W1p);
    cudaGetSymbolAddress((void**)&X0, g_X0);
    cudaGetSymbolAddress((void**)&X1, g_X1);
    cudaGetSymbolAddress((void**)&pre, g_pre);
    cudaGetSymbolAddress((void**)&emis, g_emis);
    cudaGetSymbolAddress((void**)&Ahi, g_Ahi);
    cudaGetSymbolAddress((void**)&Xf, g_Xf);
    cudaGetSymbolAddress((void**)&Wf, g_Wf);

    static bool attr_set = false;
    if (!attr_set) {
        cudaFuncSetAttribute(lstm_mma, cudaFuncAttributeMaxDynamicSharedMemorySize,
                             LSTM_SMEM);
        attr_set = true;
    }

    const size_t XF_STRIDE = (size_t)64 * 128 * 4 * 32;   // uint4 per buffer

    gather_kernel<<<(4096 * DPAD + 255) / 256, 256>>>(E, x, emb);
    padw_kernel<<<(512 * DPAD + 255) / 256, 256>>>(W1p, lin1_w);
    gemm_bias<<<dim3(512 / 64, 4096 / 128), 256>>>(E, W1p, lin1_b, X0, 512, DPAD);

    float* Xin = X0;
    float* Xout = X1;
    const int Kin[4] = {512, 2048, 2048, 2048};

    // layer-0 input fragments via convx; later layers fused into lstm epilogue
    convx_kernel<<<(4096 * 512 + 255) / 256, 256>>>(Xin, (__half*)Xf, 512, 32);

    for (int l = 0; l < 4; l++) {
        const int K = Kin[l];
        const int KS = K / 16;
        uint4* XfIn  = Xf + (size_t)(l & 1) * XF_STRIDE;
        __half* XfOut = (l < 3) ? (__half*)(Xf + (size_t)((l + 1) & 1) * XF_STRIDE)
                                : (__half*)0;
        convw_kernel<<<(128 * 64 * 1024) / 256, 256>>>(whh[l], (__half*)Ahi);
        convwih_kernel<<<(8192 * K + 255) / 256, 256>>>(wih[l], (__half*)Wf, K, KS);
        hgemm_pre<<<dim3(32, 32), 512>>>(XfIn, Wf, bias[l], pre, KS);
        lstm_mma<<<LBLK, 512, LSTM_SMEM>>>(Ahi, pre, Xout, XfOut);
        float* tmpp = Xin; Xin = Xout; Xout = tmpp;
    }

    bn_lin2<<<4096, 128>>>(Xin, bn_gamma, bn_beta, lin2_w, lin2_b, emis);
    crf_kernel<<<1, BB * NT>>>(emis, y, mask, crf_start, crf_end, crf_trans,
                               (float*)d_out);
}

// round 14
// speedup vs baseline: 5.3972x; 1.0168x over previous
#include <cuda_runtime.h>
#include <cuda_fp16.h>
#include <cuda_bf16.h>
#include <math.h>
#include <stdint.h>

// ---------------------------------------------------------------------------
// Problem constants
// ---------------------------------------------------------------------------
#define BB 32      // batch
#define SS 128     // seq len
#define DD 300     // emb dim
#define HH 1024    // hidden
#define G4 4096    // 4*H
#define NT 9       // tags
#define LBLK 128   // persistent LSTM CTAs (single wave, <148 SMs)
#define DBAR 64    // per-direction barrier arrivals

// lstm dynamic smem: Bsm u32[16384] (64KB) + psum float[2*64*33] + hstage 1KB
#define LSTM_SMEM (65536 + 2 * 64 * 33 * 4 + 1024)

// ---------------------------------------------------------------------------
// Scratch (static device allocations - allowed)
// ---------------------------------------------------------------------------
__device__ float g_X1[4096 * 2048];             // fp32 layer-3 output for bn_lin2
__device__ float g_pre[2ull * 4096 * 4096];
__device__ float g_emis[BB * SS * NT];
// Whh fp16, A-fragment order: [cta 128][kstep 64][mtile 4][lane 32][4 u32]
__device__ uint4 g_Ahi[128 * 8192];
// h as fp16 B-fragments, parity double-buffered: [parity][dir][16384 u32]
__device__ uint32_t g_hfrag[2][2][16384];
// input-projection A-fragments, ping-pong
__device__ uint4 g_Xf[2][64 * 128 * 4 * 32];
// Wih B-fragments (reused per layer)
__device__ uint2 g_Wf[256 * 128 * 4 * 32];
// lin1 weight B-fragments (N=512, KS=19)
__device__ uint2 g_WfL1[16 * 19 * 4 * 32];

__device__ unsigned g_bar_cnt[2];
__device__ unsigned g_bar_gen[2];

// mma.sync m16n8k16 fp16 -> f32 (baseline PTX, compiles for plain sm_103)
#define MMA_F16(d, a, b) \
    asm volatile("mma.sync.aligned.m16n8k16.row.col.f32.f16.f16.f32 " \
        "{%0,%1,%2,%3}, {%4,%5,%6,%7}, {%8,%9}, {%0,%1,%2,%3};" \
        : "+f"((d)[0]), "+f"((d)[1]), "+f"((d)[2]), "+f"((d)[3]) \
        : "r"((a).x), "r"((a).y), "r"((a).z), "r"((a).w), \
          "r"((b).x), "r"((b).y))

__device__ __forceinline__ uint32_t pack_h2(float a, float b) {
    return (uint32_t)__half_as_ushort(__float2half_rn(a)) |
           ((uint32_t)__half_as_ushort(__float2half_rn(b)) << 16);
}

// ---------------------------------------------------------------------------
// Whh fp32 -> fp16 A-fragments, one u32 (k-pair) per thread.
// ---------------------------------------------------------------------------
__global__ void convw_kernel(const float* __restrict__ whh,
                             uint32_t* __restrict__ Ahi) {
    int i = blockIdx.x * blockDim.x + threadIdx.x;   // 128*64*512
    if (i >= 128 * 64 * 512) return;
    int c = i >> 15;
    int r = (i >> 9) & 63;
    int kp = i & 511;
    int kstep = kp >> 3, p = kp & 7;
    int k0 = kstep * 16 + p * 2;
    int dir = c >> 6, j0 = (c & 63) * 16;
    int gate = r >> 4, jj = r & 15;
    int grow = gate * 1024 + j0 + jj;
    const float* wp = whh + (size_t)dir * G4 * HH + (size_t)grow * HH + k0;
    float w0 = wp[0], w1 = wp[1];
    int lane = (jj & 7) * 4 + (p & 3);
    int reg = ((jj >> 3) & 1) + ((p >> 2) << 1);
    size_t idx = (size_t)c * 32768 + kstep * 512 + gate * 128 + lane * 4 + reg;
    Ahi[idx] = pack_h2(w0, w1);
}

// ---------------------------------------------------------------------------
// Wih fp32 (8192 x K) -> fp16 B-fragments, one u32 per thread.
// ---------------------------------------------------------------------------
__global__ void convwih_kernel(const float* __restrict__ W,
                               uint32_t* __restrict__ Wf, int K, int KS) {
    int i = blockIdx.x * blockDim.x + threadIdx.x;   // 8192*(K/2)
    int KH = K >> 1;
    if (i >= 8192 * KH) return;
    int n = i / KH, kp = i % KH;
    int kstep = kp >> 3, p = kp & 7;
    int k0 = kstep * 16 + p * 2;
    const float* wp = W + (size_t)n * K + k0;
    float w0 = wp[0], w1 = wp[1];
    int nblk = n >> 5, nr = n & 31;
    int nt = nr >> 3, ncol = nr & 7;
    int lane = ncol * 4 + (p & 3);
    int reg = p >> 2;
    size_t idx = ((((size_t)nblk * KS + kstep) * 4 + nt) * 32 + lane) * 2 + reg;
    Wf[idx] = pack_h2(w0, w1);
}

// ---------------------------------------------------------------------------
// Embedding gather -> fp16 A-fragments (K=304, KS=19, zero pad 300..303)
// ---------------------------------------------------------------------------
__global__ void convE_kernel(const int* __restrict__ x, const float* __restrict__ emb,
                             __half* __restrict__ Ef) {
    int i = blockIdx.x * blockDim.x + threadIdx.x;   // 4096*304
    if (i >= 4096 * 304) return;
    int m = i / 304, k = i % 304;
    int s = m / BB, b = m % BB;
    int tok = x[b * SS + s];
    float v = (k < DD) ? emb[(size_t)tok * DD + k] : 0.f;
    int rowblk = m >> 6, r = m & 63;
    int mt = r >> 4, mrow = r & 15;
    int kstep = k >> 4, kin = k & 15;
    int lane = (mrow & 7) * 4 + ((kin >> 1) & 3);
    int reg = ((mrow >> 3) & 1) + ((kin >> 3) << 1);
    size_t e = (((((size_t)rowblk * 19 + kstep) * 4 + mt) * 32 + lane) * 4 + reg) * 2
               + (kin & 1);
    Ef[e] = __float2half_rn(v);
}

// lin1 weight (512 x 300) -> B-fragments (N=512, KS=19, zero pad)
__global__ void convW1_kernel(const float* __restrict__ W, __half* __restrict__ Wf) {
    int i = blockIdx.x * blockDim.x + threadIdx.x;   // 512*304
    if (i >= 512 * 304) return;
    int n = i / 304, k = i % 304;
    float v = (k < DD) ? W[(size_t)n * DD + k] : 0.f;
    int nblk = n >> 5, nr = n & 31;
    int nt = nr >> 3, ncol = nr & 7;
    int kstep = k >> 4, kin = k & 15;
    int lane = ncol * 4 + ((kin & 7) >> 1);
    int reg = kin >> 3;
    size_t e = (((((size_t)nblk * 19 + kstep) * 4 + nt) * 32 + lane) * 2 + reg) * 2
               + (kin & 1);
    Wf[e] = __float2half_rn(v);
}

// ---------------------------------------------------------------------------
// HMMA lin1: X0frag[m][n] = E[m] . W1[n] + b1[n], written directly as
// fp16 A-fragments (KS=32) for layer-0 hgemm. Grid (2, 32), 512 threads.
// ---------------------------------------------------------------------------
__global__ void __launch_bounds__(512, 1)
hgemm_lin1(const uint4* __restrict__ Ef, const uint2* __restrict__ Wf,
           const float* __restrict__ bias, __half* __restrict__ Xf0) {
    const int tid = threadIdx.x;
    const int wid = tid >> 5, lane = tid & 31;
    const int rowblk = blockIdx.y * 2 + (wid >> 3);
    const int nblk = blockIdx.x * 8 + (wid & 7);

    const uint4* Ab = Ef + (size_t)rowblk * 19 * 128 + lane;
    const uint2* Bb = Wf + (size_t)nblk * 19 * 128 + lane;

    float d[4][4][4];
#pragma unroll
    for (int mt = 0; mt < 4; mt++)
#pragma unroll
        for (int nt = 0; nt < 4; nt++)
#pragma unroll
            for (int q = 0; q < 4; q++) d[mt][nt][q] = 0.f;

    uint4 a[4];
    uint2 b[4];
#pragma unroll
    for (int i = 0; i < 4; i++) {
        a[i] = __ldg(Ab + i * 32);
        b[i] = __ldg(Bb + i * 32);
    }
    for (int ks = 0; ks < 19; ks++) {
        uint4 ca[4];
        uint2 cb[4];
#pragma unroll
        for (int i = 0; i < 4; i++) { ca[i] = a[i]; cb[i] = b[i]; }
        if (ks + 1 < 19) {
            const uint4* An = Ab + (size_t)(ks + 1) * 128;
            const uint2* Bn = Bb + (size_t)(ks + 1) * 128;
#pragma unroll
            for (int i = 0; i < 4; i++) {
                a[i] = __ldg(An + i * 32);
                b[i] = __ldg(Bn + i * 32);
            }
        }
#pragma unroll
        for (int mt = 0; mt < 4; mt++)
#pragma unroll
            for (int nt = 0; nt < 4; nt++)
                MMA_F16(d[mt][nt], ca[mt], cb[nt]);
    }

    // epilogue: bias + write fp16 A-fragments (KS=32) for layer-0 hgemm
#pragma unroll
    for (int mt = 0; mt < 4; mt++) {
#pragma unroll
        for (int nt = 0; nt < 4; nt++) {
#pragma unroll
            for (int q = 0; q < 4; q++) {
                int n = nblk * 32 + nt * 8 + (lane & 3) * 2 + (q & 1);
                int mm = rowblk * 64 + mt * 16 + (lane >> 2) + ((q >> 1) << 3);
                float val = d[mt][nt][q] + __ldg(bias + n);
                int kstep = n >> 4, kin = n & 15;
                int rb = mm >> 6, r = mm & 63;
                int mtA = r >> 4, mr = r & 15;
                int lane2 = (mr & 7) * 4 + ((kin >> 1) & 3);
                int reg = ((mr >> 3) & 1) + ((kin >> 3) << 1);
                size_t e = (((((size_t)rb * 32 + kstep) * 4 + mtA) * 32 + lane2) * 4
                            + reg) * 2 + (kin & 1);
                Xf0[e] = __float2half_rn(val);
            }
        }
    }
}

// ---------------------------------------------------------------------------
// HMMA input-projection GEMM: pre[dir][m][col] = X[m] . Wih[n] + bias[n]
// Grid (32, 32), 512 threads; CTA tile 128x256; warp tile 64x32.
// ---------------------------------------------------------------------------
__global__ void __launch_bounds__(512, 1)
hgemm_pre(const uint4* __restrict__ Xf, const uint2* __restrict__ Wf,
          const float* __restrict__ bias, float* __restrict__ pre, int KS) {
    const int tid = threadIdx.x;
    const int wid = tid >> 5, lane = tid & 31;
    const int rowblk = blockIdx.y * 2 + (wid >> 3);
    const int nblk = blockIdx.x * 8 + (wid & 7);

    const uint4* Ab = Xf + (size_t)rowblk * KS * 128 + lane;
    const uint2* Bb = Wf + (size_t)nblk * KS * 128 + lane;

    float d[4][4][4];
#pragma unroll
    for (int mt = 0; mt < 4; mt++)
#pragma unroll
        for (int nt = 0; nt < 4; nt++)
#pragma unroll
            for (int q = 0; q < 4; q++) d[mt][nt][q] = 0.f;

    uint4 a[4];
    uint2 b[4];
#pragma unroll
    for (int i = 0; i < 4; i++) {
        a[i] = __ldg(Ab + i * 32);
        b[i] = __ldg(Bb + i * 32);
    }

    for (int ks = 0; ks < KS; ks++) {
        uint4 ca[4];
        uint2 cb[4];
#pragma unroll
        for (int i = 0; i < 4; i++) { ca[i] = a[i]; cb[i] = b[i]; }
        if (ks + 1 < KS) {
            const uint4* An = Ab + (size_t)(ks + 1) * 128;
            const uint2* Bn = Bb + (size_t)(ks + 1) * 128;
#pragma unroll
            for (int i = 0; i < 4; i++) {
                a[i] = __ldg(An + i * 32);
                b[i] = __ldg(Bn + i * 32);
            }
        }
#pragma unroll
        for (int mt = 0; mt < 4; mt++)
#pragma unroll
            for (int nt = 0; nt < 4; nt++)
                MMA_F16(d[mt][nt], ca[mt], cb[nt]);
    }

#pragma unroll
    for (int mt = 0; mt < 4; mt++) {
        int m = rowblk * 64 + mt * 16 + (lane >> 2);
#pragma unroll
        for (int nt = 0; nt < 4; nt++) {
            int nn = nblk * 32 + nt * 8 + (lane & 3) * 2;
            int dir = nn >> 12;
            int col = nn & 4095;
            float bs0 = __ldg(bias + nn);
            float bs1 = __ldg(bias + nn + 1);
            float* outp = pre + (size_t)dir * 4096 * 4096 + (size_t)m * 4096 + col;
            float2 v0 = make_float2(d[mt][nt][0] + bs0, d[mt][nt][1] + bs1);
            *(float2*)outp = v0;
            float2 v1 = make_float2(d[mt][nt][2] + bs0, d[mt][nt][3] + bs1);
            *(float2*)(outp + (size_t)8 * 4096) = v1;
        }
    }
}

// ---------------------------------------------------------------------------
// Persistent HMMA BiLSTM layer. 128 CTAs x 512 threads.
// Split arrive/wait barrier; coalesced h-frag publish; shadow work after arrive.
// ---------------------------------------------------------------------------
__global__ void __launch_bounds__(512, 1)
lstm_mma(const uint4* __restrict__ Ahi, const float* __restrict__ pre,
         float* __restrict__ Xout, __half* __restrict__ Xfout) {
    extern __shared__ __align__(16) uint32_t smd[];
    uint32_t* Bsm = smd;                           // u32[16384] = 64 KB
    float* psum = (float*)(smd + 16384);           // [ksplit][64 rows][33]
    __half* hstage = (__half*)(smd + 16384 + 2 * 64 * 33);  // 512 halves

    const int tid = threadIdx.x;
    const int wid = tid >> 5;
    const int lid = tid & 31;
    const int cta = blockIdx.x;
    const int dir = cta >> 6;
    const int my_kstep = cta & 63;
    const int j0 = my_kstep * 16;

    const int ksplit = wid >> 3;
    const int mtile  = (wid >> 1) & 3;
    const int ntbase = (wid & 1) * 2;
    const int kbase  = ksplit * 32;

    const uint4* Aph = Ahi + (size_t)cta * 8192 + (size_t)kbase * 128 + mtile * 32 + lid;
    const float* preD = pre + (size_t)dir * 4096 * 4096;

    const int cb = tid >> 4;
    const int cj = tid & 15;
    float creg = 0.f;

    const int kx = dir * HH + j0 + cj;
    const int xkstep = kx >> 4, xkin = kx & 15;

    const int hloc = (((cb >> 3) * 32 + (cb & 7) * 4 + ((cj & 7) >> 1)) * 2
                      + (cj >> 3)) * 2 + (cj & 1);

    volatile unsigned* vgen = &g_bar_gen[dir];
    const unsigned base = *vgen;

    float pg0, pg1, pg2, pg3;
    {
        const int sd0 = dir ? (SS - 1) : 0;
        const float* pp = preD + (size_t)sd0 * BB * G4 + (size_t)cb * G4 + j0 + cj;
        pg0 = __ldcg(pp);
        pg1 = __ldcg(pp + 1024);
        pg2 = __ldcg(pp + 2048);
        pg3 = __ldcg(pp + 3072);
    }

    for (int t = 0; t < SS; t++) {
        const int sdir = dir ? (SS - 1 - t) : t;

        if (t > 0) {
            if (tid == 0) {
                while (*vgen < base + (unsigned)t) { __nanosleep(32); }
                __threadfence();
            }
            __syncthreads();

            const uint4* src = (const uint4*)g_hfrag[(t - 1) & 1][dir];
            uint4* dst = (uint4*)Bsm;
#pragma unroll
            for (int i = 0; i < 8; i++)
                dst[tid + i * 512] = __ldcg(src + tid + i * 512);
            __syncthreads();

            float d0a[4] = {0.f,0.f,0.f,0.f}, d0b[4] = {0.f,0.f,0.f,0.f};
            float d1a[4] = {0.f,0.f,0.f,0.f}, d1b[4] = {0.f,0.f,0.f,0.f};
            uint4 rah[4];
#pragma unroll
            for (int i = 0; i < 4; i++)
                rah[i] = __ldg(Aph + i * 128);

            const uint32_t* Bw = Bsm + (((kbase * 4 + ntbase) * 32 + lid) << 1);
#pragma unroll 4
            for (int ks = 0; ks < 32; ks++) {
                int s = ks & 3;
                uint4 ah = rah[s];
                if (ks < 28) rah[s] = __ldg(Aph + (ks + 4) * 128);
                const uint32_t* bp = Bw + ks * 256;
                uint2 b0 = *(const uint2*)bp;
                uint2 b1 = *(const uint2*)(bp + 64);
                if (ks & 1) {
                    MMA_F16(d0b, ah, b0);
                    MMA_F16(d1b, ah, b1);
                } else {
                    MMA_F16(d0a, ah, b0);
                    MMA_F16(d1a, ah, b1);
                }
            }
            float d0[4], d1[4];
#pragma unroll
            for (int i = 0; i < 4; i++) {
                d0[i] = d0a[i] + d0b[i];
                d1[i] = d1a[i] + d1b[i];
            }
            float* ps = psum + ksplit * (64 * 33);
            int row0 = mtile * 16 + (lid >> 2);
            int n0 = ntbase * 8 + (lid & 3) * 2;
            ps[row0 * 33 + n0]           = d0[0];
            ps[row0 * 33 + n0 + 1]       = d0[1];
            ps[(row0 + 8) * 33 + n0]     = d0[2];
            ps[(row0 + 8) * 33 + n0 + 1] = d0[3];
            ps[row0 * 33 + n0 + 8]           = d1[0];
            ps[row0 * 33 + n0 + 9]           = d1[1];
            ps[(row0 + 8) * 33 + n0 + 8]     = d1[2];
            ps[(row0 + 8) * 33 + n0 + 9]     = d1[3];
            __syncthreads();
        }

        float gi = pg0, gf = pg1, gg = pg2, go = pg3;
        if (t > 0) {
            gi += psum[(0 * 16 + cj) * 33 + cb] + psum[64 * 33 + (0 * 16 + cj) * 33 + cb];
            gf += psum[(1 * 16 + cj) * 33 + cb] + psum[64 * 33 + (1 * 16 + cj) * 33 + cb];
            gg += psum[(2 * 16 + cj) * 33 + cb] + psum[64 * 33 + (2 * 16 + cj) * 33 + cb];
            go += psum[(3 * 16 + cj) * 33 + cb] + psum[64 * 33 + (3 * 16 + cj) * 33 + cb];
        }
        float i_ = 1.f / (1.f + expf(-gi));
        float f_ = 1.f / (1.f + expf(-gf));
        creg = f_ * creg + i_ * tanhf(gg);
        float hv = (1.f / (1.f + expf(-go))) * tanhf(creg);
        __half hvh = __float2half_rn(hv);

        hstage[hloc] = hvh;
        __syncthreads();
        if (tid < 64) {
            uint4 v = ((const uint4*)hstage)[tid];
            *(((uint4*)(g_hfrag[t & 1][dir] + my_kstep * 256)) + tid) = v;
        }
        __threadfence();
        __syncthreads();

        if (tid == 0) {
            unsigned rank = atomicAdd(&g_bar_cnt[dir], 1);
            if (rank == DBAR - 1) {
                atomicExch(&g_bar_cnt[dir], 0);
                __threadfence();
                atomicExch(&g_bar_gen[dir], base + (unsigned)t + 1);
            }
        }

        if (Xfout) {
            int m = sdir * BB + cb;
            int rowblk = m >> 6, r = m & 63;
            int mt = r >> 4, mrow = r & 15;
            int lane2 = (mrow & 7) * 4 + ((xkin >> 1) & 3);
            int reg = ((mrow >> 3) & 1) + ((xkin >> 3) << 1);
            size_t e = (((((size_t)rowblk * 128 + xkstep) * 4 + mt) * 32 + lane2) * 4
                        + reg) * 2 + (xkin & 1);
            Xfout[e] = hvh;
        } else {
            Xout[(size_t)(sdir * BB + cb) * 2048 + dir * HH + j0 + cj] = hv;
        }
        if (t + 1 < SS) {
            const int sdn = dir ? (SS - 2 - t) : (t + 1);
            const float* pp = preD + (size_t)sdn * BB * G4 + (size_t)cb * G4 + j0 + cj;
            pg0 = __ldcg(pp);
            pg1 = __ldcg(pp + 1024);
            pg2 = __ldcg(pp + 2048);
            pg3 = __ldcg(pp + 3072);
        }
    }
}

// ---------------------------------------------------------------------------
// BN + ReLU + lin2 -> emissions
// ---------------------------------------------------------------------------
__global__ void bn_lin2(const float* __restrict__ X, const float* __restrict__ gamma,
                        const float* __restrict__ beta, const float* __restrict__ w2,
                        const float* __restrict__ b2, float* __restrict__ emis) {
    int m = blockIdx.x;
    int s = m / BB, b = m % BB;
    int tid = threadIdx.x;
    const float inv = rsqrtf(1.f + 1e-5f);
    float acc[NT];
#pragma unroll
    for (int j = 0; j < NT; j++) acc[j] = 0.f;
    for (int k = tid; k < 2048; k += 128) {
        float hv = X[(size_t)m * 2048 + k];
        hv = fmaxf(gamma[k] * inv * hv + beta[k], 0.f);
#pragma unroll
        for (int j = 0; j < NT; j++) acc[j] += hv * w2[j * 2048 + k];
    }
    __shared__ float red[NT][128];
#pragma unroll
    for (int j = 0; j < NT; j++) red[j][tid] = acc[j];
    __syncthreads();
    for (int off = 64; off > 0; off >>= 1) {
        if (tid < off) {
#pragma unroll
            for (int j = 0; j < NT; j++) red[j][tid] += red[j][tid + off];
        }
        __syncthreads();
    }
    if (tid < NT) emis[(size_t)(b * SS + s) * NT + tid] = red[tid][0] + b2[tid];
}

// ---------------------------------------------------------------------------
// CRF log-likelihood -> scalar
// ---------------------------------------------------------------------------
__global__ void crf_kernel(const float* __restrict__ emis, const int* __restrict__ y,
                           const unsigned char* __restrict__ maskb,
                           const float* __restrict__ start, const float* __restrict__ end_,
                           const float* __restrict__ trans, float* __restrict__ out) {
    __shared__ float alpha[BB][12];
    __shared__ float tmp[BB][12];
    __shared__ float tr[NT * NT];
    __shared__ float numv[BB];
    __shared__ float denv[BB];
    __shared__ int mask_mode;

    int tid = threadIdx.x;
    if (tid == 0) {
        int mm = 1;
        for (int i = 0; i < 16; i++) {
            if (maskb[4 * i + 1] | maskb[4 * i + 2] | maskb[4 * i + 3]) { mm = 0; break; }
        }
        mask_mode = mm;
    }
    if (tid < NT * NT) tr[tid] = trans[tid];
    __syncthreads();

    int b = tid / NT;
    int j = tid % NT;
    const int mm = mask_mode;
    const int* mi = (const int*)maskb;

    alpha[b][j] = start[j] + emis[(size_t)(b * SS) * NT + j];
    __syncthreads();

    for (int t = 1; t < SS; t++) {
        float mx = -1e30f;
#pragma unroll
        for (int i = 0; i < NT; i++) {
            float v = alpha[b][i] + tr[i * NT + j];
            mx = fmaxf(mx, v);
        }
        float ssum = 0.f;
#pragma unroll
        for (int i = 0; i < NT; i++)
            ssum += expf(alpha[b][i] + tr[i * NT + j] - mx);
        float nxt = mx + logf(ssum) + emis[(size_t)(b * SS + t) * NT + j];
        bool mk = mm ? (mi[b * SS + t] != 0) : (maskb[b * SS + t] != 0);
        __syncthreads();
        if (mk) alpha[b][j] = nxt;
        __syncthreads();
    }

    tmp[b][j] = alpha[b][j] + end_[j];
    __syncthreads();
    if (j == 0) {
        float mx = tmp[b][0];
#pragma unroll
        for (int i = 1; i < NT; i++) mx = fmaxf(mx, tmp[b][i]);
        float ssum = 0.f;
#pragma unroll
        for (int i = 0; i < NT; i++) ssum += expf(tmp[b][i] - mx);
        denv[b] = mx + logf(ssum);

        const int* yb = y + b * SS;
        float num = start[yb[0]] + emis[(size_t)(b * SS) * NT + yb[0]];
        int len = (mm ? (mi[b * SS] != 0) : (maskb[b * SS] != 0)) ? 1 : 0;
        for (int t = 1; t < SS; t++) {
            bool mk = mm ? (mi[b * SS + t] != 0) : (maskb[b * SS + t] != 0);
            if (mk) {
                num += tr[yb[t - 1] * NT + yb[t]] + emis[(size_t)(b * SS + t) * NT + yb[t]];
                len++;
            }
        }
        int last = yb[(len > 0 ? len : 1) - 1];
        num += end_[last];
        numv[b] = num;
    }
    __syncthreads();
    if (tid == 0) {
        float acc = 0.f;
        for (int bb2 = 0; bb2 < BB; bb2++) acc += numv[bb2] - denv[bb2];
        out[0] = acc;
    }
}

// ---------------------------------------------------------------------------
// Host launcher
// ---------------------------------------------------------------------------
extern "C" void kernel_launch(void* const* d_in, const int* in_sizes, int n_in,
                              void* d_out, int out_size) {
    const int*   x       = (const int*)d_in[0];
    const int*   y       = (const int*)d_in[1];
    const unsigned char* mask = (const unsigned char*)d_in[2];
    const float* emb     = (const float*)d_in[3];
    const float* lin1_w  = (const float*)d_in[4];
    const float* lin1_b  = (const float*)d_in[5];
    const float* wih[4]  = {(const float*)d_in[6],  (const float*)d_in[9],
                            (const float*)d_in[12], (const float*)d_in[15]};
    const float* whh[4]  = {(const float*)d_in[7],  (const float*)d_in[10],
                            (const float*)d_in[13], (const float*)d_in[16]};
    const float* bias[4] = {(const float*)d_in[8],  (const float*)d_in[11],
                            (const float*)d_in[14], (const float*)d_in[17]};
    const float* bn_gamma = (const float*)d_in[18];
    const float* bn_beta  = (const float*)d_in[19];
    const float* lin2_w   = (const float*)d_in[20];
    const float* lin2_b   = (const float*)d_in[21];
    const float* crf_start = (const float*)d_in[22];
    const float* crf_end   = (const float*)d_in[23];
    const float* crf_trans = (const float*)d_in[24];

    float *X1, *pre, *emis;
    uint4 *Ahi, *Xf;
    uint2 *Wf, *WfL1;
    cudaGetSymbolAddress((void**)&X1, g_X1);
    cudaGetSymbolAddress((void**)&pre, g_pre);
    cudaGetSymbolAddress((void**)&emis, g_emis);
    cudaGetSymbolAddress((void**)&Ahi, g_Ahi);
    cudaGetSymbolAddress((void**)&Xf, g_Xf);
    cudaGetSymbolAddress((void**)&Wf, g_Wf);
    cudaGetSymbolAddress((void**)&WfL1, g_WfL1);

    static bool attr_set = false;
    if (!attr_set) {
        cudaFuncSetAttribute(lstm_mma, cudaFuncAttributeMaxDynamicSharedMemorySize,
                             LSTM_SMEM);
        attr_set = true;
    }

    const size_t XF_STRIDE = (size_t)64 * 128 * 4 * 32;   // uint4 per buffer

    // lin1 path: gather+convert E into Xf[1] (scratch), W1 frags, HMMA -> Xf[0]
    convE_kernel<<<(4096 * 304 + 255) / 256, 256>>>(x, emb,
                                                    (__half*)(Xf + XF_STRIDE));
    convW1_kernel<<<(512 * 304 + 255) / 256, 256>>>(lin1_w, (__half*)WfL1);
    hgemm_lin1<<<dim3(2, 32), 512>>>(Xf + XF_STRIDE, WfL1, lin1_b, (__half*)Xf);

    const int Kin[4] = {512, 2048, 2048, 2048};

    for (int l = 0; l < 4; l++) {
        const int K = Kin[l];
        const int KS = K / 16;
        uint4* XfIn  = Xf + (size_t)(l & 1) * XF_STRIDE;
        __half* XfOut = (l < 3) ? (__half*)(Xf + (size_t)((l + 1) & 1) * XF_STRIDE)
                                : (__half*)0;
        convw_kernel<<<(128 * 64 * 512) / 256, 256>>>(whh[l], (uint32_t*)Ahi);
        convwih_kernel<<<(8192 * (K / 2) + 255) / 256, 256>>>(
            wih[l], (uint32_t*)Wf, K, KS);
        hgemm_pre<<<dim3(32, 32), 512>>>(XfIn, Wf, bias[l], pre, KS);
        lstm_mma<<<LBLK, 512, LSTM_SMEM>>>(Ahi, pre, X1, XfOut);
    }

    bn_lin2<<<4096, 128>>>(X1, bn_gamma, bn_beta, lin2_w, lin2_b, emis);
    crf_kernel<<<1, BB * NT>>>(emis, y, mask, crf_start, crf_end, crf_trans,
                               (float*)d_out);
}

// round 15
// speedup vs baseline: 5.4186x; 1.0040x over previous
#include <cuda_runtime.h>
#include <cuda_fp16.h>
#include <cuda_bf16.h>
#include <math.h>
#include <stdint.h>

// ---------------------------------------------------------------------------
// Problem constants
// ---------------------------------------------------------------------------
#define BB 32      // batch
#define SS 128     // seq len
#define DD 300     // emb dim
#define HH 1024    // hidden
#define G4 4096    // 4*H
#define NT 9       // tags
#define LBLK 128   // persistent LSTM CTAs (single wave, <148 SMs)
#define DBAR 64    // per-direction barrier arrivals

// lstm dynamic smem: Bsm u32[16384] (64KB) + psum float[2*64*33] + hstage 1KB
#define LSTM_SMEM (65536 + 2 * 64 * 33 * 4 + 1024)

// ---------------------------------------------------------------------------
// Scratch (static device allocations - allowed)
// ---------------------------------------------------------------------------
__device__ float g_X1[4096 * 2048];             // fp32 layer-3 output for bn_lin2
__device__ __half g_pre[2ull * 4096 * 4096];    // fp16 input projections
__device__ float g_emis[BB * SS * NT];
// Whh fp16, A-fragment order: [cta 128][kstep 64][mtile 4][lane 32][4 u32]
__device__ uint4 g_Ahi[128 * 8192];
// h as fp16 B-fragments, parity double-buffered: [parity][dir][16384 u32]
__device__ uint32_t g_hfrag[2][2][16384];
// input-projection A-fragments, ping-pong
__device__ uint4 g_Xf[2][64 * 128 * 4 * 32];
// Wih B-fragments (reused per layer)
__device__ uint2 g_Wf[256 * 128 * 4 * 32];
// lin1 weight B-fragments (N=512, KS=19)
__device__ uint2 g_WfL1[16 * 19 * 4 * 32];

__device__ unsigned g_bar_cnt[2];
__device__ unsigned g_bar_gen[2];

// mma.sync m16n8k16 fp16 -> f32 (baseline PTX, compiles for plain sm_103)
#define MMA_F16(d, a, b) \
    asm volatile("mma.sync.aligned.m16n8k16.row.col.f32.f16.f16.f32 " \
        "{%0,%1,%2,%3}, {%4,%5,%6,%7}, {%8,%9}, {%0,%1,%2,%3};" \
        : "+f"((d)[0]), "+f"((d)[1]), "+f"((d)[2]), "+f"((d)[3]) \
        : "r"((a).x), "r"((a).y), "r"((a).z), "r"((a).w), \
          "r"((b).x), "r"((b).y))

__device__ __forceinline__ uint32_t pack_h2(float a, float b) {
    return (uint32_t)__half_as_ushort(__float2half_rn(a)) |
           ((uint32_t)__half_as_ushort(__float2half_rn(b)) << 16);
}

// ---------------------------------------------------------------------------
// Whh fp32 -> fp16 A-fragments, one u32 (k-pair) per thread.
// ---------------------------------------------------------------------------
__global__ void convw_kernel(const float* __restrict__ whh,
                             uint32_t* __restrict__ Ahi) {
    int i = blockIdx.x * blockDim.x + threadIdx.x;   // 128*64*512
    if (i >= 128 * 64 * 512) return;
    int c = i >> 15;
    int r = (i >> 9) & 63;
    int kp = i & 511;
    int kstep = kp >> 3, p = kp & 7;
    int k0 = kstep * 16 + p * 2;
    int dir = c >> 6, j0 = (c & 63) * 16;
    int gate = r >> 4, jj = r & 15;
    int grow = gate * 1024 + j0 + jj;
    const float* wp = whh + (size_t)dir * G4 * HH + (size_t)grow * HH + k0;
    float w0 = wp[0], w1 = wp[1];
    int lane = (jj & 7) * 4 + (p & 3);
    int reg = ((jj >> 3) & 1) + ((p >> 2) << 1);
    size_t idx = (size_t)c * 32768 + kstep * 512 + gate * 128 + lane * 4 + reg;
    Ahi[idx] = pack_h2(w0, w1);
}

// ---------------------------------------------------------------------------
// Wih fp32 (8192 x K) -> fp16 B-fragments, one u32 per thread.
// ---------------------------------------------------------------------------
__global__ void convwih_kernel(const float* __restrict__ W,
                               uint32_t* __restrict__ Wf, int K, int KS) {
    int i = blockIdx.x * blockDim.x + threadIdx.x;   // 8192*(K/2)
    int KH = K >> 1;
    if (i >= 8192 * KH) return;
    int n = i / KH, kp = i % KH;
    int kstep = kp >> 3, p = kp & 7;
    int k0 = kstep * 16 + p * 2;
    const float* wp = W + (size_t)n * K + k0;
    float w0 = wp[0], w1 = wp[1];
    int nblk = n >> 5, nr = n & 31;
    int nt = nr >> 3, ncol = nr & 7;
    int lane = ncol * 4 + (p & 3);
    int reg = p >> 2;
    size_t idx = ((((size_t)nblk * KS + kstep) * 4 + nt) * 32 + lane) * 2 + reg;
    Wf[idx] = pack_h2(w0, w1);
}

// ---------------------------------------------------------------------------
// Embedding gather -> fp16 A-fragments (K=304, KS=19, zero pad 300..303)
// ---------------------------------------------------------------------------
__global__ void convE_kernel(const int* __restrict__ x, const float* __restrict__ emb,
                             __half* __restrict__ Ef) {
    int i = blockIdx.x * blockDim.x + threadIdx.x;   // 4096*304
    if (i >= 4096 * 304) return;
    int m = i / 304, k = i % 304;
    int s = m / BB, b = m % BB;
    int tok = x[b * SS + s];
    float v = (k < DD) ? emb[(size_t)tok * DD + k] : 0.f;
    int rowblk = m >> 6, r = m & 63;
    int mt = r >> 4, mrow = r & 15;
    int kstep = k >> 4, kin = k & 15;
    int lane = (mrow & 7) * 4 + ((kin >> 1) & 3);
    int reg = ((mrow >> 3) & 1) + ((kin >> 3) << 1);
    size_t e = (((((size_t)rowblk * 19 + kstep) * 4 + mt) * 32 + lane) * 4 + reg) * 2
               + (kin & 1);
    Ef[e] = __float2half_rn(v);
}

// lin1 weight (512 x 300) -> B-fragments (N=512, KS=19, zero pad)
__global__ void convW1_kernel(const float* __restrict__ W, __half* __restrict__ Wf) {
    int i = blockIdx.x * blockDim.x + threadIdx.x;   // 512*304
    if (i >= 512 * 304) return;
    int n = i / 304, k = i % 304;
    float v = (k < DD) ? W[(size_t)n * DD + k] : 0.f;
    int nblk = n >> 5, nr = n & 31;
    int nt = nr >> 3, ncol = nr & 7;
    int kstep = k >> 4, kin = k & 15;
    int lane = ncol * 4 + ((kin & 7) >> 1);
    int reg = kin >> 3;
    size_t e = (((((size_t)nblk * 19 + kstep) * 4 + nt) * 32 + lane) * 2 + reg) * 2
               + (kin & 1);
    Wf[e] = __float2half_rn(v);
}

// ---------------------------------------------------------------------------
// HMMA lin1: X0frag[m][n] = E[m] . W1[n] + b1[n], written directly as
// fp16 A-fragments (KS=32) for layer-0 hgemm. Grid (2, 32), 512 threads.
// ---------------------------------------------------------------------------
__global__ void __launch_bounds__(512, 1)
hgemm_lin1(const uint4* __restrict__ Ef, const uint2* __restrict__ Wf,
           const float* __restrict__ bias, __half* __restrict__ Xf0) {
    const int tid = threadIdx.x;
    const int wid = tid >> 5, lane = tid & 31;
    const int rowblk = blockIdx.y * 2 + (wid >> 3);
    const int nblk = blockIdx.x * 8 + (wid & 7);

    const uint4* Ab = Ef + (size_t)rowblk * 19 * 128 + lane;
    const uint2* Bb = Wf + (size_t)nblk * 19 * 128 + lane;

    float d[4][4][4];
#pragma unroll
    for (int mt = 0; mt < 4; mt++)
#pragma unroll
        for (int nt = 0; nt < 4; nt++)
#pragma unroll
            for (int q = 0; q < 4; q++) d[mt][nt][q] = 0.f;

    uint4 a[4];
    uint2 b[4];
#pragma unroll
    for (int i = 0; i < 4; i++) {
        a[i] = __ldg(Ab + i * 32);
        b[i] = __ldg(Bb + i * 32);
    }
    for (int ks = 0; ks < 19; ks++) {
        uint4 ca[4];
        uint2 cb[4];
#pragma unroll
        for (int i = 0; i < 4; i++) { ca[i] = a[i]; cb[i] = b[i]; }
        if (ks + 1 < 19) {
            const uint4* An = Ab + (size_t)(ks + 1) * 128;
            const uint2* Bn = Bb + (size_t)(ks + 1) * 128;
#pragma unroll
            for (int i = 0; i < 4; i++) {
                a[i] = __ldg(An + i * 32);
                b[i] = __ldg(Bn + i * 32);
            }
        }
#pragma unroll
        for (int mt = 0; mt < 4; mt++)
#pragma unroll
            for (int nt = 0; nt < 4; nt++)
                MMA_F16(d[mt][nt], ca[mt], cb[nt]);
    }

    // epilogue: bias + write fp16 A-fragments (KS=32) for layer-0 hgemm
#pragma unroll
    for (int mt = 0; mt < 4; mt++) {
#pragma unroll
        for (int nt = 0; nt < 4; nt++) {
#pragma unroll
            for (int q = 0; q < 4; q++) {
                int n = nblk * 32 + nt * 8 + (lane & 3) * 2 + (q & 1);
                int mm = rowblk * 64 + mt * 16 + (lane >> 2) + ((q >> 1) << 3);
                float val = d[mt][nt][q] + __ldg(bias + n);
                int kstep = n >> 4, kin = n & 15;
                int rb = mm >> 6, r = mm & 63;
                int mtA = r >> 4, mr = r & 15;
                int lane2 = (mr & 7) * 4 + ((kin >> 1) & 3);
                int reg = ((mr >> 3) & 1) + ((kin >> 3) << 1);
                size_t e = (((((size_t)rb * 32 + kstep) * 4 + mtA) * 32 + lane2) * 4
                            + reg) * 2 + (kin & 1);
                Xf0[e] = __float2half_rn(val);
            }
        }
    }
}

// ---------------------------------------------------------------------------
// HMMA input-projection GEMM: pre[dir][m][col] = X[m] . Wih[n] + bias[n]
// Grid (32, 32), 512 threads; output stored fp16 (__half2 pairs).
// ---------------------------------------------------------------------------
__global__ void __launch_bounds__(512, 1)
hgemm_pre(const uint4* __restrict__ Xf, const uint2* __restrict__ Wf,
          const float* __restrict__ bias, __half* __restrict__ pre, int KS) {
    const int tid = threadIdx.x;
    const int wid = tid >> 5, lane = tid & 31;
    const int rowblk = blockIdx.y * 2 + (wid >> 3);
    const int nblk = blockIdx.x * 8 + (wid & 7);

    const uint4* Ab = Xf + (size_t)rowblk * KS * 128 + lane;
    const uint2* Bb = Wf + (size_t)nblk * KS * 128 + lane;

    float d[4][4][4];
#pragma unroll
    for (int mt = 0; mt < 4; mt++)
#pragma unroll
        for (int nt = 0; nt < 4; nt++)
#pragma unroll
            for (int q = 0; q < 4; q++) d[mt][nt][q] = 0.f;

    uint4 a[4];
    uint2 b[4];
#pragma unroll
    for (int i = 0; i < 4; i++) {
        a[i] = __ldg(Ab + i * 32);
        b[i] = __ldg(Bb + i * 32);
    }

    for (int ks = 0; ks < KS; ks++) {
        uint4 ca[4];
        uint2 cb[4];
#pragma unroll
        for (int i = 0; i < 4; i++) { ca[i] = a[i]; cb[i] = b[i]; }
        if (ks + 1 < KS) {
            const uint4* An = Ab + (size_t)(ks + 1) * 128;
            const uint2* Bn = Bb + (size_t)(ks + 1) * 128;
#pragma unroll
            for (int i = 0; i < 4; i++) {
                a[i] = __ldg(An + i * 32);
                b[i] = __ldg(Bn + i * 32);
            }
        }
#pragma unroll
        for (int mt = 0; mt < 4; mt++)
#pragma unroll
            for (int nt = 0; nt < 4; nt++)
                MMA_F16(d[mt][nt], ca[mt], cb[nt]);
    }

#pragma unroll
    for (int mt = 0; mt < 4; mt++) {
        int m = rowblk * 64 + mt * 16 + (lane >> 2);
#pragma unroll
        for (int nt = 0; nt < 4; nt++) {
            int nn = nblk * 32 + nt * 8 + (lane & 3) * 2;
            int dir = nn >> 12;
            int col = nn & 4095;
            float bs0 = __ldg(bias + nn);
            float bs1 = __ldg(bias + nn + 1);
            __half2* outp = (__half2*)(pre + (size_t)dir * 4096 * 4096
                                       + (size_t)m * 4096 + col);
            *outp = __floats2half2_rn(d[mt][nt][0] + bs0, d[mt][nt][1] + bs1);
            *(outp + (size_t)8 * 2048) =
                __floats2half2_rn(d[mt][nt][2] + bs0, d[mt][nt][3] + bs1);
        }
    }
}

// ---------------------------------------------------------------------------
// Persistent HMMA BiLSTM layer. 128 CTAs x 512 threads. fp16 pre.
// Split arrive/wait barrier; coalesced h-frag publish; shadow work after arrive.
// ---------------------------------------------------------------------------
__global__ void __launch_bounds__(512, 1)
lstm_mma(const uint4* __restrict__ Ahi, const __half* __restrict__ pre,
         float* __restrict__ Xout, __half* __restrict__ Xfout) {
    extern __shared__ __align__(16) uint32_t smd[];
    uint32_t* Bsm = smd;                           // u32[16384] = 64 KB
    float* psum = (float*)(smd + 16384);           // [ksplit][64 rows][33]
    __half* hstage = (__half*)(smd + 16384 + 2 * 64 * 33);  // 512 halves

    const int tid = threadIdx.x;
    const int wid = tid >> 5;
    const int lid = tid & 31;
    const int cta = blockIdx.x;
    const int dir = cta >> 6;
    const int my_kstep = cta & 63;
    const int j0 = my_kstep * 16;

    const int ksplit = wid >> 3;
    const int mtile  = (wid >> 1) & 3;
    const int ntbase = (wid & 1) * 2;
    const int kbase  = ksplit * 32;

    const uint4* Aph = Ahi + (size_t)cta * 8192 + (size_t)kbase * 128 + mtile * 32 + lid;
    const __half* preD = pre + (size_t)dir * 4096 * 4096;

    const int cb = tid >> 4;
    const int cj = tid & 15;
    float creg = 0.f;

    const int kx = dir * HH + j0 + cj;
    const int xkstep = kx >> 4, xkin = kx & 15;

    const int hloc = (((cb >> 3) * 32 + (cb & 7) * 4 + ((cj & 7) >> 1)) * 2
                      + (cj >> 3)) * 2 + (cj & 1);

    volatile unsigned* vgen = &g_bar_gen[dir];
    const unsigned base = *vgen;

    float pg0, pg1, pg2, pg3;
    {
        const int sd0 = dir ? (SS - 1) : 0;
        const __half* pp = preD + (size_t)sd0 * BB * G4 + (size_t)cb * G4 + j0 + cj;
        pg0 = __half2float(__ldcg(pp));
        pg1 = __half2float(__ldcg(pp + 1024));
        pg2 = __half2float(__ldcg(pp + 2048));
        pg3 = __half2float(__ldcg(pp + 3072));
    }

    for (int t = 0; t < SS; t++) {
        const int sdir = dir ? (SS - 1 - t) : t;

        if (t > 0) {
            if (tid == 0) {
                while (*vgen < base + (unsigned)t) { __nanosleep(32); }
                __threadfence();
            }
            __syncthreads();

            const uint4* src = (const uint4*)g_hfrag[(t - 1) & 1][dir];
            uint4* dst = (uint4*)Bsm;
#pragma unroll
            for (int i = 0; i < 8; i++)
                dst[tid + i * 512] = __ldcg(src + tid + i * 512);
            __syncthreads();

            float d0a[4] = {0.f,0.f,0.f,0.f}, d0b[4] = {0.f,0.f,0.f,0.f};
            float d1a[4] = {0.f,0.f,0.f,0.f}, d1b[4] = {0.f,0.f,0.f,0.f};
            uint4 rah[4];
#pragma unroll
            for (int i = 0; i < 4; i++)
                rah[i] = __ldg(Aph + i * 128);

            const uint32_t* Bw = Bsm + (((kbase * 4 + ntbase) * 32 + lid) << 1);
#pragma unroll 4
            for (int ks = 0; ks < 32; ks++) {
                int s = ks & 3;
                uint4 ah = rah[s];
                if (ks < 28) rah[s] = __ldg(Aph + (ks + 4) * 128);
                const uint32_t* bp = Bw + ks * 256;
                uint2 b0 = *(const uint2*)bp;
                uint2 b1 = *(const uint2*)(bp + 64);
                if (ks & 1) {
                    MMA_F16(d0b, ah, b0);
                    MMA_F16(d1b, ah, b1);
                } else {
                    MMA_F16(d0a, ah, b0);
                    MMA_F16(d1a, ah, b1);
                }
            }
            float d0[4], d1[4];
#pragma unroll
            for (int i = 0; i < 4; i++) {
                d0[i] = d0a[i] + d0b[i];
                d1[i] = d1a[i] + d1b[i];
            }
            float* ps = psum + ksplit * (64 * 33);
            int row0 = mtile * 16 + (lid >> 2);
            int n0 = ntbase * 8 + (lid & 3) * 2;
            ps[row0 * 33 + n0]           = d0[0];
            ps[row0 * 33 + n0 + 1]       = d0[1];
            ps[(row0 + 8) * 33 + n0]     = d0[2];
            ps[(row0 + 8) * 33 + n0 + 1] = d0[3];
            ps[row0 * 33 + n0 + 8]           = d1[0];
            ps[row0 * 33 + n0 + 9]           = d1[1];
            ps[(row0 + 8) * 33 + n0 + 8]     = d1[2];
            ps[(row0 + 8) * 33 + n0 + 9]     = d1[3];
            __syncthreads();
        }

        float gi = pg0, gf = pg1, gg = pg2, go = pg3;
        if (t > 0) {
            gi += psum[(0 * 16 + cj) * 33 + cb] + psum[64 * 33 + (0 * 16 + cj) * 33 + cb];
            gf += psum[(1 * 16 + cj) * 33 + cb] + psum[64 * 33 + (1 * 16 + cj) * 33 + cb];
            gg += psum[(2 * 16 + cj) * 33 + cb] + psum[64 * 33 + (2 * 16 + cj) * 33 + cb];
            go += psum[(3 * 16 + cj) * 33 + cb] + psum[64 * 33 + (3 * 16 + cj) * 33 + cb];
        }
        float i_ = 1.f / (1.f + expf(-gi));
        float f_ = 1.f / (1.f + expf(-gf));
        creg = f_ * creg + i_ * tanhf(gg);
        float hv = (1.f / (1.f + expf(-go))) * tanhf(creg);
        __half hvh = __float2half_rn(hv);

        hstage[hloc] = hvh;
        __syncthreads();
        if (tid < 64) {
            uint4 v = ((const uint4*)hstage)[tid];
            *(((uint4*)(g_hfrag[t & 1][dir] + my_kstep * 256)) + tid) = v;
        }
        __threadfence();
        __syncthreads();

        if (tid == 0) {
            unsigned rank = atomicAdd(&g_bar_cnt[dir], 1);
            if (rank == DBAR - 1) {
                atomicExch(&g_bar_cnt[dir], 0);
                __threadfence();
                atomicExch(&g_bar_gen[dir], base + (unsigned)t + 1);
            }
        }

        if (Xfout) {
            int m = sdir * BB + cb;
            int rowblk = m >> 6, r = m & 63;
            int mt = r >> 4, mrow = r & 15;
            int lane2 = (mrow & 7) * 4 + ((xkin >> 1) & 3);
            int reg = ((mrow >> 3) & 1) + ((xkin >> 3) << 1);
            size_t e = (((((size_t)rowblk * 128 + xkstep) * 4 + mt) * 32 + lane2) * 4
                        + reg) * 2 + (xkin & 1);
            Xfout[e] = hvh;
        } else {
            Xout[(size_t)(sdir * BB + cb) * 2048 + dir * HH + j0 + cj] = hv;
        }
        if (t + 1 < SS) {
            const int sdn = dir ? (SS - 2 - t) : (t + 1);
            const __half* pp = preD + (size_t)sdn * BB * G4 + (size_t)cb * G4 + j0 + cj;
            pg0 = __half2float(__ldcg(pp));
            pg1 = __half2float(__ldcg(pp + 1024));
            pg2 = __half2float(__ldcg(pp + 2048));
            pg3 = __half2float(__ldcg(pp + 3072));
        }
    }
}

// ---------------------------------------------------------------------------
// BN + ReLU + lin2 -> emissions
// ---------------------------------------------------------------------------
__global__ void bn_lin2(const float* __restrict__ X, const float* __restrict__ gamma,
                        const float* __restrict__ beta, const float* __restrict__ w2,
                        const float* __restrict__ b2, float* __restrict__ emis) {
    int m = blockIdx.x;
    int s = m / BB, b = m % BB;
    int tid = threadIdx.x;
    const float inv = rsqrtf(1.f + 1e-5f);
    float acc[NT];
#pragma unroll
    for (int j = 0; j < NT; j++) acc[j] = 0.f;
    for (int k = tid; k < 2048; k += 128) {
        float hv = X[(size_t)m * 2048 + k];
        hv = fmaxf(gamma[k] * inv * hv + beta[k], 0.f);
#pragma unroll
        for (int j = 0; j < NT; j++) acc[j] += hv * w2[j * 2048 + k];
    }
    __shared__ float red[NT][128];
#pragma unroll
    for (int j = 0; j < NT; j++) red[j][tid] = acc[j];
    __syncthreads();
    for (int off = 64; off > 0; off >>= 1) {
        if (tid < off) {
#pragma unroll
            for (int j = 0; j < NT; j++) red[j][tid] += red[j][tid + off];
        }
        __syncthreads();
    }
    if (tid < NT) emis[(size_t)(b * SS + s) * NT + tid] = red[tid][0] + b2[tid];
}

// ---------------------------------------------------------------------------
// CRF log-likelihood -> scalar
// ---------------------------------------------------------------------------
__global__ void crf_kernel(const float* __restrict__ emis, const int* __restrict__ y,
                           const unsigned char* __restrict__ maskb,
                           const float* __restrict__ start, const float* __restrict__ end_,
                           const float* __restrict__ trans, float* __restrict__ out) {
    __shared__ float alpha[BB][12];
    __shared__ float tmp[BB][12];
    __shared__ float tr[NT * NT];
    __shared__ float numv[BB];
    __shared__ float denv[BB];
    __shared__ int mask_mode;

    int tid = threadIdx.x;
    if (tid == 0) {
        int mm = 1;
        for (int i = 0; i < 16; i++) {
            if (maskb[4 * i + 1] | maskb[4 * i + 2] | maskb[4 * i + 3]) { mm = 0; break; }
        }
        mask_mode = mm;
    }
    if (tid < NT * NT) tr[tid] = trans[tid];
    __syncthreads();

    int b = tid / NT;
    int j = tid % NT;
    const int mm = mask_mode;
    const int* mi = (const int*)maskb;

    alpha[b][j] = start[j] + emis[(size_t)(b * SS) * NT + j];
    __syncthreads();

    for (int t = 1; t < SS; t++) {
        float mx = -1e30f;
#pragma unroll
        for (int i = 0; i < NT; i++) {
            float v = alpha[b][i] + tr[i * NT + j];
            mx = fmaxf(mx, v);
        }
        float ssum = 0.f;
#pragma unroll
        for (int i = 0; i < NT; i++)
            ssum += expf(alpha[b][i] + tr[i * NT + j] - mx);
        float nxt = mx + logf(ssum) + emis[(size_t)(b * SS + t) * NT + j];
        bool mk = mm ? (mi[b * SS + t] != 0) : (maskb[b * SS + t] != 0);
        __syncthreads();
        if (mk) alpha[b][j] = nxt;
        __syncthreads();
    }

    tmp[b][j] = alpha[b][j] + end_[j];
    __syncthreads();
    if (j == 0) {
        float mx = tmp[b][0];
#pragma unroll
        for (int i = 1; i < NT; i++) mx = fmaxf(mx, tmp[b][i]);
        float ssum = 0.f;
#pragma unroll
        for (int i = 0; i < NT; i++) ssum += expf(tmp[b][i] - mx);
        denv[b] = mx + logf(ssum);

        const int* yb = y + b * SS;
        float num = start[yb[0]] + emis[(size_t)(b * SS) * NT + yb[0]];
        int len = (mm ? (mi[b * SS] != 0) : (maskb[b * SS] != 0)) ? 1 : 0;
        for (int t = 1; t < SS; t++) {
            bool mk = mm ? (mi[b * SS + t] != 0) : (maskb[b * SS + t] != 0);
            if (mk) {
                num += tr[yb[t - 1] * NT + yb[t]] + emis[(size_t)(b * SS + t) * NT + yb[t]];
                len++;
            }
        }
        int last = yb[(len > 0 ? len : 1) - 1];
        num += end_[last];
        numv[b] = num;
    }
    __syncthreads();
    if (tid == 0) {
        float acc = 0.f;
        for (int bb2 = 0; bb2 < BB; bb2++) acc += numv[bb2] - denv[bb2];
        out[0] = acc;
    }
}

// ---------------------------------------------------------------------------
// Host launcher
// ---------------------------------------------------------------------------
extern "C" void kernel_launch(void* const* d_in, const int* in_sizes, int n_in,
                              void* d_out, int out_size) {
    const int*   x       = (const int*)d_in[0];
    const int*   y       = (const int*)d_in[1];
    const unsigned char* mask = (const unsigned char*)d_in[2];
    const float* emb     = (const float*)d_in[3];
    const float* lin1_w  = (const float*)d_in[4];
    const float* lin1_b  = (const float*)d_in[5];
    const float* wih[4]  = {(const float*)d_in[6],  (const float*)d_in[9],
                            (const float*)d_in[12], (const float*)d_in[15]};
    const float* whh[4]  = {(const float*)d_in[7],  (const float*)d_in[10],
                            (const float*)d_in[13], (const float*)d_in[16]};
    const float* bias[4] = {(const float*)d_in[8],  (const float*)d_in[11],
                            (const float*)d_in[14], (const float*)d_in[17]};
    const float* bn_gamma = (const float*)d_in[18];
    const float* bn_beta  = (const float*)d_in[19];
    const float* lin2_w   = (const float*)d_in[20];
    const float* lin2_b   = (const float*)d_in[21];
    const float* crf_start = (const float*)d_in[22];
    const float* crf_end   = (const float*)d_in[23];
    const float* crf_trans = (const float*)d_in[24];

    float *X1, *emis;
    __half *pre;
    uint4 *Ahi, *Xf;
    uint2 *Wf, *WfL1;
    cudaGetSymbolAddress((void**)&X1, g_X1);
    cudaGetSymbolAddress((void**)&pre, g_pre);
    cudaGetSymbolAddress((void**)&emis, g_emis);
    cudaGetSymbolAddress((void**)&Ahi, g_Ahi);
    cudaGetSymbolAddress((void**)&Xf, g_Xf);
    cudaGetSymbolAddress((void**)&Wf, g_Wf);
    cudaGetSymbolAddress((void**)&WfL1, g_WfL1);

    static bool attr_set = false;
    if (!attr_set) {
        cudaFuncSetAttribute(lstm_mma, cudaFuncAttributeMaxDynamicSharedMemorySize,
                             LSTM_SMEM);
        attr_set = true;
    }

    const size_t XF_STRIDE = (size_t)64 * 128 * 4 * 32;   // uint4 per buffer

    // lin1 path: gather+convert E into Xf[1] (scratch), W1 frags, HMMA -> Xf[0]
    convE_kernel<<<(4096 * 304 + 255) / 256, 256>>>(x, emb,
                                                    (__half*)(Xf + XF_STRIDE));
    convW1_kernel<<<(512 * 304 + 255) / 256, 256>>>(lin1_w, (__half*)WfL1);
    hgemm_lin1<<<dim3(2, 32), 512>>>(Xf + XF_STRIDE, WfL1, lin1_b, (__half*)Xf);

    const int Kin[4] = {512, 2048, 2048, 2048};

    for (int l = 0; l < 4; l++) {
        const int K = Kin[l];
        const int KS = K / 16;
        uint4* XfIn  = Xf + (size_t)(l & 1) * XF_STRIDE;
        __half* XfOut = (l < 3) ? (__half*)(Xf + (size_t)((l + 1) & 1) * XF_STRIDE)
                                : (__half*)0;
        convw_kernel<<<(128 * 64 * 512) / 256, 256>>>(whh[l], (uint32_t*)Ahi);
        convwih_kernel<<<(8192 * (K / 2) + 255) / 256, 256>>>(
            wih[l], (uint32_t*)Wf, K, KS);
        hgemm_pre<<<dim3(32, 32), 512>>>(XfIn, Wf, bias[l], pre, KS);
        lstm_mma<<<LBLK, 512, LSTM_SMEM>>>(Ahi, pre, X1, XfOut);
    }

    bn_lin2<<<4096, 128>>>(X1, bn_gamma, bn_beta, lin2_w, lin2_b, emis);
    crf_kernel<<<1, BB * NT>>>(emis, y, mask, crf_start, crf_end, crf_trans,
                               (float*)d_out);
}